// round 1
// baseline (speedup 1.0000x reference)
#include <cuda_runtime.h>
#include <math.h>

// ---------------- problem constants ----------------
#define Bb   4
#define Tt   6
#define Nn   1024
#define CSc  48
#define GSg  32
#define Hh   270
#define ATa  32
#define DAd  64
#define Ee   32
#define Ll   32
#define EDd  400
#define OUTo 4000
#define BT   (Bb*Tt)        // 24
#define BT2  (Bb*(Tt-1))    // 20 (attention batches, t>=1)
#define H3   (3*Hh)         // 810
#define H4   (4*Hh)         // 1080
#define XCOLS (BT*CSc)      // 1152

// ---------------- device scratch (static, no allocs) ----------------
__device__ float g_X   [Nn*XCOLS];
__device__ float g_S   [Nn*XCOLS];
__device__ float g_co  [BT*Nn*GSg];
__device__ float g_no  [BT*Nn*GSg];
__device__ float g_qin [BT*Nn*GSg];
__device__ float g_q   [BT*Nn*ATa];
__device__ float g_k   [BT*Nn*ATa];
__device__ float g_v   [BT*Nn*Hh];
__device__ float g_gi  [BT*Nn*H3];
__device__ float g_G   [BT2*Nn*Nn];       // attention logits -> probs (84MB)
__device__ float g_hm23[BT2*Nn*Hh];
__device__ float g_h   [Bb*Nn*Hh];
__device__ float g_gh  [Bb*Nn*H3];
__device__ signed char g_m1 [BT*Nn];
__device__ signed char g_m23[BT*Nn];
__device__ float g_xe  [Bb*Ee*Ll*EDd];
__device__ float g_giL [Bb*Ee*Ll*H4];
__device__ float g_stack[Bb*(Ee+1)*Hh];
__device__ float g_wdc [Hh+1];            // Wd@ctx, plus bd.ctx at [Hh]
__device__ float g_vu  [Bb*(Ee+1)];
__device__ float g_o1  [Bb*Hh];

__device__ __forceinline__ float sigf(float x){ return 1.f/(1.f+expf(-x)); }

// ---------------- generic tiled SGEMM ----------------
// C[M,N] = epi( A[M,K] @ B[K,N] (+bias) )  row-major, batched via blockIdx.z
// epi: 0 none, 1 +bias, 2 tanh, 3 +bias then sigmoid
// mapB: 0 -> B batch z; 1 -> B batch (z + z/(Tt-1) + 1) (attn t>=1 -> full bt index)
__global__ void k_sgemm(const float* __restrict__ A, const float* __restrict__ B,
                        const float* __restrict__ bias, float* __restrict__ C,
                        int M, int N, int K,
                        long long sA, long long sB, long long sC,
                        int epi, int mapB)
{
    int z = blockIdx.z;
    const float* Ab = A + (long long)z * sA;
    int zb = mapB ? (z + z/(Tt-1) + 1) : z;
    const float* Bp = B + (long long)zb * sB;
    float* Cb = C + (long long)z * sC;

    __shared__ float As[64][17];
    __shared__ float Bs[16][64];

    int tid = threadIdx.x;
    int tx = tid & 15, ty = tid >> 4;
    int row0 = blockIdx.y * 64, col0 = blockIdx.x * 64;
    float acc[4][4] = {};

    for (int k0 = 0; k0 < K; k0 += 16) {
        #pragma unroll
        for (int i = 0; i < 4; i++) {
            int ml = (tid >> 4) + i * 16;
            int r  = row0 + ml;
            int kk = k0 + (tid & 15);
            As[ml][tid & 15] = (r < M && kk < K) ? Ab[(long long)r * K + kk] : 0.f;
        }
        #pragma unroll
        for (int i = 0; i < 4; i++) {
            int kl = (tid >> 6) + i * 4;
            int kk = k0 + kl;
            int c  = col0 + (tid & 63);
            Bs[kl][tid & 63] = (kk < K && c < N) ? Bp[(long long)kk * N + c] : 0.f;
        }
        __syncthreads();
        #pragma unroll
        for (int kt = 0; kt < 16; kt++) {
            float a0 = As[ty*4+0][kt], a1 = As[ty*4+1][kt];
            float a2 = As[ty*4+2][kt], a3 = As[ty*4+3][kt];
            float b0 = Bs[kt][tx*4+0], b1 = Bs[kt][tx*4+1];
            float b2 = Bs[kt][tx*4+2], b3 = Bs[kt][tx*4+3];
            acc[0][0]+=a0*b0; acc[0][1]+=a0*b1; acc[0][2]+=a0*b2; acc[0][3]+=a0*b3;
            acc[1][0]+=a1*b0; acc[1][1]+=a1*b1; acc[1][2]+=a1*b2; acc[1][3]+=a1*b3;
            acc[2][0]+=a2*b0; acc[2][1]+=a2*b1; acc[2][2]+=a2*b2; acc[2][3]+=a2*b3;
            acc[3][0]+=a3*b0; acc[3][1]+=a3*b1; acc[3][2]+=a3*b2; acc[3][3]+=a3*b3;
        }
        __syncthreads();
    }
    #pragma unroll
    for (int i = 0; i < 4; i++) {
        int r = row0 + ty*4 + i;
        if (r >= M) continue;
        #pragma unroll
        for (int j = 0; j < 4; j++) {
            int c = col0 + tx*4 + j;
            if (c >= N) continue;
            float v = acc[i][j];
            if (epi == 1 || epi == 3) v += bias[c];
            if (epi == 2) v = tanhf(v);
            if (epi == 3) v = sigf(v);
            Cb[(long long)r * N + c] = v;
        }
    }
}

// ---------------- graph-conv input build ----------------
// X[n, bt*48+c] = code_x[bt,n]*c_emb[n,c] + neighbors[bt,n]*n_emb[n,c]
__global__ void k_build_X(const int* __restrict__ code_x, const int* __restrict__ neigh,
                          const float* __restrict__ c_emb, const float* __restrict__ n_emb)
{
    int idx = blockIdx.x * blockDim.x + threadIdx.x;
    if (idx >= Nn * XCOLS) return;
    int n  = idx / XCOLS;
    int r  = idx % XCOLS;
    int bt = r / CSc;
    int c  = r % CSc;
    float cx = (float)code_x[bt*Nn + n];
    float nx = (float)neigh [bt*Nn + n];
    g_X[idx] = cx * c_emb[n*CSc + c] + nx * n_emb[n*CSc + c];
}

__global__ void k_masks(const int* __restrict__ divided)
{
    int i = blockIdx.x * blockDim.x + threadIdx.x;
    if (i >= BT*Nn) return;
    g_m1 [i] = (divided[3*i]     > 0) ? 1 : 0;
    g_m23[i] = (divided[3*i + 1] > 0 || divided[3*i + 2] > 0) ? 1 : 0;
}

// co/no: co = lrelu(cx*( (c_emb+S)@Wg ) + bg), no = lrelu(nx*( (n_emb+S)@Wg ) + bg)
__global__ void k_co_no(const int* __restrict__ code_x, const int* __restrict__ neigh,
                        const float* __restrict__ c_emb, const float* __restrict__ n_emb,
                        const float* __restrict__ Wg, const float* __restrict__ bg)
{
    int bt = blockIdx.x;
    int n  = blockIdx.y * 8 + threadIdx.y;
    int g  = threadIdx.x;
    __shared__ float Wgs[CSc][GSg];
    int tid = threadIdx.y * 32 + threadIdx.x;
    for (int i = tid; i < CSc*GSg; i += 256) Wgs[i / GSg][i % GSg] = Wg[i];
    __syncthreads();
    const float* Srow = g_S + (long long)n * XCOLS + bt * CSc;
    float a1 = 0.f, a2 = 0.f;
    #pragma unroll
    for (int c = 0; c < CSc; c++) {
        float s = Srow[c];
        float w = Wgs[c][g];
        a1 += (c_emb[n*CSc + c] + s) * w;
        a2 += (n_emb[n*CSc + c] + s) * w;
    }
    float cx = (float)code_x[bt*Nn + n];
    float nx = (float)neigh [bt*Nn + n];
    float co = cx * a1 + bg[g];
    float no = nx * a2 + bg[g];
    co = (co >= 0.f) ? co : 0.01f * co;
    no = (no >= 0.f) ? no : 0.01f * no;
    long long o = ((long long)bt*Nn + n) * GSg + g;
    g_co[o] = co;
    g_no[o] = no;
}

__global__ void k_qin(const int* __restrict__ divided, const float* __restrict__ u_emb)
{
    int idx = blockIdx.x * blockDim.x + threadIdx.x;
    if (idx >= BT*Nn*GSg) return;
    int g  = idx % GSg;
    int bn = idx / GSg;
    int n  = bn % Nn;
    int bt = bn / Nn;
    int t  = bt % Tt;
    float v;
    if (divided[bn*3 + 2] > 0)       v = u_emb[n*GSg + g];
    else if (t > 0)                  v = g_no[((long long)(bt-1)*Nn + n)*GSg + g];
    else                             v = 0.f;
    g_qin[idx] = v;
}

// ---------------- attention: logits with key mask ----------------
__global__ void k_attn_score()
{
    int z = blockIdx.z;
    int b = z / (Tt-1);
    int t = 1 + z % (Tt-1);
    int bt = b*Tt + t;
    const float* qp = g_q + (long long)bt*Nn*ATa;
    const float* kp = g_k + (long long)bt*Nn*ATa;
    const signed char* m = g_m23 + bt*Nn;
    float* G = g_G + (long long)z * Nn * Nn;
    int i0 = blockIdx.y * 64, j0 = blockIdx.x * 64;
    __shared__ float qs[64][33];
    __shared__ float ks[64][33];
    int tid = threadIdx.x;
    for (int idx = tid; idx < 64*32; idx += 256) {
        int rr = idx >> 5, a = idx & 31;
        qs[rr][a] = qp[(i0 + rr)*ATa + a];
        ks[rr][a] = kp[(j0 + rr)*ATa + a];
    }
    __syncthreads();
    int tx = tid & 15, ty = tid >> 4;
    float acc[4][4] = {};
    #pragma unroll
    for (int a = 0; a < 32; a++) {
        float av[4], bv[4];
        #pragma unroll
        for (int i = 0; i < 4; i++) av[i] = qs[ty*4+i][a];
        #pragma unroll
        for (int j = 0; j < 4; j++) bv[j] = ks[tx*4+j][a];
        #pragma unroll
        for (int i = 0; i < 4; i++)
            #pragma unroll
            for (int j = 0; j < 4; j++) acc[i][j] += av[i]*bv[j];
    }
    const float scale = 0.17677669529663687f; // 1/sqrt(32)
    #pragma unroll
    for (int i = 0; i < 4; i++) {
        int ii = i0 + ty*4 + i;
        #pragma unroll
        for (int j = 0; j < 4; j++) {
            int jj = j0 + tx*4 + j;
            G[(long long)ii*Nn + jj] = m[jj] ? acc[i][j]*scale : -1e30f;
        }
    }
}

__global__ void k_softmax()
{
    long long row = blockIdx.x;
    float* p = g_G + row * Nn;
    int tid = threadIdx.x;
    __shared__ float red[256];
    float v[4];
    float mx = -1e38f;
    #pragma unroll
    for (int i = 0; i < 4; i++) { v[i] = p[tid + i*256]; mx = fmaxf(mx, v[i]); }
    red[tid] = mx; __syncthreads();
    for (int s = 128; s > 0; s >>= 1) { if (tid < s) red[tid] = fmaxf(red[tid], red[tid+s]); __syncthreads(); }
    mx = red[0]; __syncthreads();
    float sum = 0.f;
    #pragma unroll
    for (int i = 0; i < 4; i++) { v[i] = expf(v[i] - mx); sum += v[i]; }
    red[tid] = sum; __syncthreads();
    for (int s = 128; s > 0; s >>= 1) { if (tid < s) red[tid] += red[tid+s]; __syncthreads(); }
    float inv = 1.f / red[0];
    #pragma unroll
    for (int i = 0; i < 4; i++) p[tid + i*256] = v[i] * inv;
}

// ---------------- GRU combine (per step) ----------------
__global__ void k_gru_combine(int t)
{
    int idx = blockIdx.x * blockDim.x + threadIdx.x;
    if (idx >= Bb*Nn*Hh) return;
    int j  = idx % Hh;
    int bn = idx / Hh;
    int n  = bn % Nn;
    int b  = bn / Nn;
    int bt = b*Tt + t;
    const float* gir = g_gi + ((long long)bt*Nn + n) * H3;
    const float* ghr = g_gh + (long long)bn * H3;
    float r  = sigf(gir[j]        + ghr[j]);
    float zz = sigf(gir[Hh + j]   + ghr[Hh + j]);
    float nn = tanhf(gir[2*Hh + j] + r * ghr[2*Hh + j]);
    float hp = g_h[idx];
    float hm1 = (1.f - zz) * nn + zz * hp;
    int mi = bt*Nn + n;
    float hv = 0.f;
    if (t > 0 && g_m23[mi])
        hv = g_hm23[((long long)(b*(Tt-1) + (t-1))*Nn + n) * Hh + j];
    else if (g_m1[mi])
        hv = hm1;
    g_h[idx] = hv;
}

__global__ void k_outlast()
{
    int b = blockIdx.x, j = threadIdx.x;
    if (j >= Hh) return;
    float mx1 = -1e38f, mx23 = -1e38f;
    int h1 = 0, h23 = 0;
    int mbase = (b*Tt + (Tt-1)) * Nn;
    for (int n = 0; n < Nn; n++) {
        float hv = g_h[((long long)b*Nn + n)*Hh + j];
        if (g_m1 [mbase + n]) { h1 = 1;  mx1  = fmaxf(mx1,  hv); }
        if (g_m23[mbase + n]) { h23 = 1; mx23 = fmaxf(mx23, hv); }
    }
    g_stack[(long long)b*(Ee+1)*Hh + j] = (h1 ? mx1 : 0.f) + (h23 ? mx23 : 0.f);
}

// ---------------- event LSTM ----------------
__global__ void k_evgather(const int* __restrict__ events, const float* __restrict__ Eemb)
{
    int idx = blockIdx.x * blockDim.x + threadIdx.x;
    if (idx >= Bb*Ee*Ll*EDd) return;
    int d   = idx % EDd;
    int rem = idx / EDd;
    int l   = rem % Ll;
    int be  = rem / Ll;
    int b   = be / Ee, e = be % Ee;
    int ev  = events[((b*Tt + (Tt-1))*Ee + e)*Ll + l];
    g_xe[idx] = Eemb[(long long)ev*EDd + d];
}

// persistent LSTM: 4 independent (b,e) rows per block, l-loop inside.
__global__ void k_lstm(const float* __restrict__ Whh)
{
    __shared__ float sh[4][Hh];
    int j = threadIdx.x;
    int row0 = blockIdx.x * 4;
    float cs[4] = {0.f, 0.f, 0.f, 0.f};
    if (j < Hh) { sh[0][j] = 0.f; sh[1][j] = 0.f; sh[2][j] = 0.f; sh[3][j] = 0.f; }
    __syncthreads();
    for (int l = 0; l < Ll; l++) {
        float hn[4];
        if (j < Hh) {
            float a[4][4] = {};
            for (int k2 = 0; k2 < Hh; k2++) {
                float w0 = __ldg(&Whh[k2*H4 + j]);
                float w1 = __ldg(&Whh[k2*H4 + Hh + j]);
                float w2 = __ldg(&Whh[k2*H4 + 2*Hh + j]);
                float w3 = __ldg(&Whh[k2*H4 + 3*Hh + j]);
                #pragma unroll
                for (int r = 0; r < 4; r++) {
                    float hv = sh[r][k2];
                    a[r][0] += hv*w0; a[r][1] += hv*w1;
                    a[r][2] += hv*w2; a[r][3] += hv*w3;
                }
            }
            #pragma unroll
            for (int r = 0; r < 4; r++) {
                const float* gl = g_giL + ((long long)(row0 + r)*Ll + l) * H4;
                float gi_ = gl[j]        + a[r][0];
                float gf  = gl[Hh + j]   + a[r][1];
                float gg  = gl[2*Hh + j] + a[r][2];
                float go  = gl[3*Hh + j] + a[r][3];
                cs[r] = sigf(gf)*cs[r] + sigf(gi_)*tanhf(gg);
                hn[r] = sigf(go)*tanhf(cs[r]);
            }
        }
        __syncthreads();
        if (j < Hh) { sh[0][j] = hn[0]; sh[1][j] = hn[1]; sh[2][j] = hn[2]; sh[3][j] = hn[3]; }
        __syncthreads();
    }
    if (j < Hh) {
        #pragma unroll
        for (int r = 0; r < 4; r++) {
            int be = row0 + r;
            int b = be / Ee, e = be % Ee;
            g_stack[((long long)b*(Ee+1) + 1 + e)*Hh + j] = sh[r][j];
        }
    }
}

// ---------------- final dp attention + head ----------------
__global__ void k_wdctx(const float* __restrict__ Wd, const float* __restrict__ bd,
                        const float* __restrict__ ctx)
{
    int j = threadIdx.x;
    if (j < Hh) {
        float s = 0.f;
        for (int d = 0; d < DAd; d++) s += Wd[j*DAd + d] * ctx[d];
        g_wdc[j] = s;
    } else if (j == Hh) {
        float s = 0.f;
        for (int d = 0; d < DAd; d++) s += bd[d] * ctx[d];
        g_wdc[Hh] = s;
    }
}

__global__ void k_dp1()
{
    int b = blockIdx.x, s = blockIdx.y;
    const float* x = g_stack + ((long long)b*(Ee+1) + s) * Hh;
    __shared__ float red[256];
    int tid = threadIdx.x;
    float acc = 0.f;
    for (int h = tid; h < Hh; h += 256) acc += x[h] * g_wdc[h];
    red[tid] = acc; __syncthreads();
    for (int st = 128; st > 0; st >>= 1) { if (tid < st) red[tid] += red[tid + st]; __syncthreads(); }
    if (tid == 0) g_vu[b*(Ee+1) + s] = red[0] + g_wdc[Hh];
}

__global__ void k_dp2()
{
    int b = blockIdx.x, j = threadIdx.x;
    __shared__ float sm[Ee+1];
    if (j == 0) {
        float mx = -1e38f;
        for (int s = 0; s < Ee+1; s++) mx = fmaxf(mx, g_vu[b*(Ee+1) + s]);
        float sum = 0.f;
        for (int s = 0; s < Ee+1; s++) { float e = expf(g_vu[b*(Ee+1) + s] - mx); sm[s] = e; sum += e; }
        float inv = 1.f / sum;
        for (int s = 0; s < Ee+1; s++) sm[s] *= inv;
    }
    __syncthreads();
    if (j < Hh) {
        float acc = 0.f;
        for (int s = 0; s < Ee+1; s++) acc += sm[s] * g_stack[((long long)b*(Ee+1) + s)*Hh + j];
        g_o1[b*Hh + j] = acc;
    }
}

// ---------------- host driver ----------------
extern "C" void kernel_launch(void* const* d_in, const int* in_sizes, int n_in,
                              void* d_out, int out_size)
{
    const int*   code_x = (const int*)  d_in[0];
    const int*   divided= (const int*)  d_in[1];
    const int*   neigh  = (const int*)  d_in[2];
    const int*   events = (const int*)  d_in[4];
    const float* c_emb  = (const float*)d_in[5];
    const float* n_emb  = (const float*)d_in[6];
    const float* u_emb  = (const float*)d_in[7];
    const float* adj    = (const float*)d_in[8];
    const float* Wg     = (const float*)d_in[9];
    const float* bg     = (const float*)d_in[10];
    const float* gWih   = (const float*)d_in[11];
    const float* gWhh   = (const float*)d_in[12];
    const float* gbih   = (const float*)d_in[13];
    const float* gbhh   = (const float*)d_in[14];
    const float* Wq     = (const float*)d_in[15];
    const float* bq     = (const float*)d_in[16];
    const float* Wk     = (const float*)d_in[17];
    const float* bk     = (const float*)d_in[18];
    const float* Wv     = (const float*)d_in[19];
    const float* bv     = (const float*)d_in[20];
    const float* Wd     = (const float*)d_in[21];
    const float* bd     = (const float*)d_in[22];
    const float* ctx    = (const float*)d_in[23];
    const float* Eemb   = (const float*)d_in[24];
    const float* lWih   = (const float*)d_in[25];
    const float* lWhh   = (const float*)d_in[26];
    const float* lb     = (const float*)d_in[27];
    const float* Wc     = (const float*)d_in[28];
    const float* bc     = (const float*)d_in[29];
    float* out = (float*)d_out;

    float *pX, *pS, *pco, *pqin, *pq, *pk, *pv, *pgi, *pG, *phm, *ph, *pgh, *pxe, *pgiL, *po1;
    cudaGetSymbolAddress((void**)&pX,   g_X);
    cudaGetSymbolAddress((void**)&pS,   g_S);
    cudaGetSymbolAddress((void**)&pco,  g_co);
    cudaGetSymbolAddress((void**)&pqin, g_qin);
    cudaGetSymbolAddress((void**)&pq,   g_q);
    cudaGetSymbolAddress((void**)&pk,   g_k);
    cudaGetSymbolAddress((void**)&pv,   g_v);
    cudaGetSymbolAddress((void**)&pgi,  g_gi);
    cudaGetSymbolAddress((void**)&pG,   g_G);
    cudaGetSymbolAddress((void**)&phm,  g_hm23);
    cudaGetSymbolAddress((void**)&ph,   g_h);
    cudaGetSymbolAddress((void**)&pgh,  g_gh);
    cudaGetSymbolAddress((void**)&pxe,  g_xe);
    cudaGetSymbolAddress((void**)&pgiL, g_giL);
    cudaGetSymbolAddress((void**)&po1,  g_o1);

    // Phase A: input-only graph work (all t in parallel)
    k_build_X<<<(Nn*XCOLS + 255)/256, 256>>>(code_x, neigh, c_emb, n_emb);
    k_masks  <<<(BT*Nn + 255)/256, 256>>>(divided);
    k_wdctx  <<<1, 288>>>(Wd, bd, ctx);

    // S = adj @ X   (1024 x 1152 x 1024)
    k_sgemm<<<dim3(18,16,1), 256>>>(adj, pX, nullptr, pS, Nn, XCOLS, Nn, 0,0,0, 0, 0);

    k_co_no<<<dim3(BT, Nn/8), dim3(32,8)>>>(code_x, neigh, c_emb, n_emb, Wg, bg);
    k_qin  <<<(BT*Nn*GSg + 255)/256, 256>>>(divided, u_emb);

    // q/k/v/gi projections (M = 24576, K = 32)
    k_sgemm<<<dim3(1, 384,1), 256>>>(pco,  Wk,   bk,   pk,  BT*Nn, ATa, GSg, 0,0,0, 1, 0);
    k_sgemm<<<dim3(1, 384,1), 256>>>(pqin, Wq,   bq,   pq,  BT*Nn, ATa, GSg, 0,0,0, 1, 0);
    k_sgemm<<<dim3(5, 384,1), 256>>>(pco,  Wv,   bv,   pv,  BT*Nn, Hh,  GSg, 0,0,0, 1, 0);
    k_sgemm<<<dim3(13,384,1), 256>>>(pco,  gWih, gbih, pgi, BT*Nn, H3,  GSg, 0,0,0, 1, 0);

    // attention (only t>=1): logits -> softmax -> tanh(P @ V)
    k_attn_score<<<dim3(16,16,BT2), 256>>>();
    k_softmax   <<<BT2*Nn, 256>>>();
    k_sgemm<<<dim3(5,16,BT2), 256>>>(pG, pv, nullptr, phm, Nn, Hh, Nn,
                                     (long long)Nn*Nn, (long long)Nn*Hh, (long long)Nn*Hh, 2, 1);

    // Phase B: GRU recurrence (6 sequential steps)
    cudaMemsetAsync(ph, 0, (size_t)Bb*Nn*Hh*sizeof(float));
    for (int t = 0; t < Tt; t++) {
        k_sgemm<<<dim3(13,64,1), 256>>>(ph, gWhh, gbhh, pgh, Bb*Nn, H3, Hh, 0,0,0, 1, 0);
        k_gru_combine<<<(Bb*Nn*Hh + 255)/256, 256>>>(t);
    }
    k_outlast<<<Bb, 288>>>();

    // Phase C: event LSTM
    k_evgather<<<(Bb*Ee*Ll*EDd + 255)/256, 256>>>(events, Eemb);
    k_sgemm<<<dim3(17,64,1), 256>>>(pxe, lWih, lb, pgiL, Bb*Ee*Ll, H4, EDd, 0,0,0, 1, 0);
    k_lstm<<<(Bb*Ee)/4, 288>>>(lWhh);

    // Phase D: dp attention (singleton second pass is identity) + classifier
    k_dp1<<<dim3(Bb, Ee+1), 256>>>();
    k_dp2<<<Bb, 288>>>();
    k_sgemm<<<dim3(63,1,1), 256>>>(po1, Wc, bc, out, Bb, OUTo, Hh, 0,0,0, 3, 0);
}

// round 2
// speedup vs baseline: 1.1963x; 1.1963x over previous
#include <cuda_runtime.h>
#include <math.h>

// ---------------- problem constants ----------------
#define Bb   4
#define Tt   6
#define Nn   1024
#define CSc  48
#define GSg  32
#define Hh   270
#define ATa  32
#define DAd  64
#define Ee   32
#define Ll   32
#define EDd  400
#define OUTo 4000
#define BT   (Bb*Tt)        // 24
#define BT2  (Bb*(Tt-1))    // 20 (attention batches, t>=1)
#define H3   (3*Hh)         // 810
#define H4   (4*Hh)         // 1080
#define XCOLS (BT*CSc)      // 1152

// ---------------- device scratch (static, no allocs) ----------------
__device__ float g_X   [Nn*XCOLS];
__device__ float g_S   [Nn*XCOLS];
__device__ float g_co  [BT*Nn*GSg];
__device__ float g_no  [BT*Nn*GSg];
__device__ float g_qin [BT*Nn*GSg];
__device__ float g_q   [BT*Nn*ATa];
__device__ float g_k   [BT*Nn*ATa];
__device__ float g_v   [BT*Nn*Hh];
__device__ float g_gi  [BT*Nn*H3];
__device__ float g_G   [BT2*Nn*Nn];       // compacted logits/probs
__device__ float g_hm23[BT2*Nn*Hh];
__device__ float g_h   [Bb*Nn*Hh];
__device__ float g_gh  [Bb*Nn*H3];
__device__ signed char g_m1 [BT*Nn];
__device__ signed char g_m23[BT*Nn];
__device__ int   g_idx [BT2*Nn];
__device__ int   g_cnt [BT2];
__device__ float g_xe  [Bb*Ee*Ll*EDd];
__device__ float g_giL [Bb*Ee*Ll*H4];
__device__ float g_stack[Bb*(Ee+1)*Hh];
__device__ float g_wdc [Hh+1];
__device__ float g_vu  [Bb*(Ee+1)];
__device__ float g_o1  [Bb*Hh];

__device__ __forceinline__ float sigf(float x){ return 1.f/(1.f+expf(-x)); }

// ---------------- high-throughput tiled SGEMM ----------------
// C[M,N] = epi( A[M,K] @ B[K,N] (+bias) ), row-major, batched on blockIdx.z.
// 128x64 tile, TK=16, double-buffered smem, 8x4 micro per thread (256 thr).
// Optional: gatherB (B row indices), scatterC (C row indices), cnt (M=K=cnt[z]).
// mapBz: B batch index = z + z/(Tt-1) + 1 (attention t>=1 -> bt).
#define TKk 16
__global__ __launch_bounds__(256) void k_gemm(
    const float* __restrict__ A, const float* __restrict__ B,
    const float* __restrict__ bias, float* __restrict__ C,
    int M, int N, int K, int lda, int ldb, int ldc,
    long long sA, long long sB, long long sC,
    int epi, int mapBz,
    const int* __restrict__ gatherB,
    const int* __restrict__ scatterC,
    const int* __restrict__ cnt)
{
    int z = blockIdx.z;
    if (cnt) { M = cnt[z]; K = cnt[z]; }
    int row0 = blockIdx.y * 128;
    if (row0 >= M) return;
    int col0 = blockIdx.x * 64;

    const float* Ab = A + (long long)z * sA;
    int zb = mapBz ? (z + z/(Tt-1) + 1) : z;
    const float* Bbp = B + (long long)zb * sB;
    float* Cb = C + (long long)z * sC;
    const int* gB  = gatherB  ? gatherB  + z*Nn : (const int*)0;
    const int* sCr = scatterC ? scatterC + z*Nn : (const int*)0;

    __shared__ __align__(16) float As[2][TKk][132];
    __shared__ __align__(16) float Bs[2][TKk][64];

    int tid = threadIdx.x;
    int ka = tid & 15, ra = tid >> 4;   // A tile load: k, row-base
    int cb = tid & 63, kb = tid >> 6;   // B tile load: col, k-base
    int tx = tid & 15, ty = tid >> 4;   // micro tile

    float acc[8][4] = {};

    int nk = (K + TKk - 1) / TKk;

    // prologue load tile 0
    {
        int k0 = 0;
        #pragma unroll
        for (int i = 0; i < 8; i++) {
            int r = ra + i*16;
            int gr = row0 + r, kk = k0 + ka;
            float v = 0.f;
            if (gr < M && kk < K) v = Ab[(long long)gr*lda + kk];
            As[0][ka][r] = v;
        }
        #pragma unroll
        for (int i = 0; i < 4; i++) {
            int kk = k0 + kb + i*4;
            int c = col0 + cb;
            float v = 0.f;
            if (kk < K && c < N) {
                int br = gB ? gB[kk] : kk;
                v = Bbp[(long long)br*ldb + c];
            }
            Bs[0][kb + i*4][cb] = v;
        }
    }
    __syncthreads();

    for (int kt = 0; kt < nk; kt++) {
        int buf = kt & 1;
        if (kt + 1 < nk) {
            int k0 = (kt + 1) * TKk;
            #pragma unroll
            for (int i = 0; i < 8; i++) {
                int r = ra + i*16;
                int gr = row0 + r, kk = k0 + ka;
                float v = 0.f;
                if (gr < M && kk < K) v = Ab[(long long)gr*lda + kk];
                As[buf^1][ka][r] = v;
            }
            #pragma unroll
            for (int i = 0; i < 4; i++) {
                int kk = k0 + kb + i*4;
                int c = col0 + cb;
                float v = 0.f;
                if (kk < K && c < N) {
                    int br = gB ? gB[kk] : kk;
                    v = Bbp[(long long)br*ldb + c];
                }
                Bs[buf^1][kb + i*4][cb] = v;
            }
        }
        #pragma unroll
        for (int kk = 0; kk < TKk; kk++) {
            float4 a0 = *(const float4*)&As[buf][kk][ty*8];
            float4 a1 = *(const float4*)&As[buf][kk][ty*8 + 4];
            float4 b0 = *(const float4*)&Bs[buf][kk][tx*4];
            float av[8] = {a0.x,a0.y,a0.z,a0.w,a1.x,a1.y,a1.z,a1.w};
            float bv[4] = {b0.x,b0.y,b0.z,b0.w};
            #pragma unroll
            for (int i = 0; i < 8; i++)
                #pragma unroll
                for (int j = 0; j < 4; j++)
                    acc[i][j] += av[i]*bv[j];
        }
        __syncthreads();
    }

    #pragma unroll
    for (int i = 0; i < 8; i++) {
        int r = row0 + ty*8 + i;
        if (r >= M) continue;
        long long crow = sCr ? (long long)sCr[r]*ldc : (long long)r*ldc;
        #pragma unroll
        for (int j = 0; j < 4; j++) {
            int c = col0 + tx*4 + j;
            if (c >= N) continue;
            float v = acc[i][j];
            if (epi == 1 || epi == 3) v += bias[c];
            if (epi == 2) v = tanhf(v);
            if (epi == 3) v = sigf(v);
            Cb[crow + c] = v;
        }
    }
}

// ---------------- graph-conv input build ----------------
__global__ void k_build_X(const int* __restrict__ code_x, const int* __restrict__ neigh,
                          const float* __restrict__ c_emb, const float* __restrict__ n_emb)
{
    int idx = blockIdx.x * blockDim.x + threadIdx.x;
    if (idx >= Nn * XCOLS) return;
    int n  = idx / XCOLS;
    int r  = idx % XCOLS;
    int bt = r / CSc;
    int c  = r % CSc;
    float cx = (float)code_x[bt*Nn + n];
    float nx = (float)neigh [bt*Nn + n];
    g_X[idx] = cx * c_emb[n*CSc + c] + nx * n_emb[n*CSc + c];
}

// sparse S = adj @ X (adj ~2% dense). 1 block per output row m, 288 threads x 4 cols.
__global__ __launch_bounds__(288) void k_spmm(const float* __restrict__ adj)
{
    int m = blockIdx.x;
    int tid = threadIdx.x;
    __shared__ float arow[Nn];
    for (int i = tid; i < Nn; i += 288) arow[i] = adj[(long long)m*Nn + i];
    __syncthreads();
    float acc0 = 0.f, acc1 = 0.f, acc2 = 0.f, acc3 = 0.f;
    for (int n = 0; n < Nn; n++) {
        float a = arow[n];
        if (a != 0.f) {
            const float* xr = g_X + (long long)n * XCOLS;
            acc0 += a * xr[tid];
            acc1 += a * xr[tid + 288];
            acc2 += a * xr[tid + 576];
            acc3 += a * xr[tid + 864];
        }
    }
    float* sr = g_S + (long long)m * XCOLS;
    sr[tid] = acc0; sr[tid+288] = acc1; sr[tid+576] = acc2; sr[tid+864] = acc3;
}

__global__ void k_masks(const int* __restrict__ divided)
{
    int i = blockIdx.x * blockDim.x + threadIdx.x;
    if (i >= BT*Nn) return;
    g_m1 [i] = (divided[3*i]     > 0) ? 1 : 0;
    g_m23[i] = (divided[3*i + 1] > 0 || divided[3*i + 2] > 0) ? 1 : 0;
}

// ordered compaction of m23 rows per attention batch z (t>=1)
__global__ __launch_bounds__(1024) void k_compact()
{
    int z = blockIdx.x;
    int b = z / (Tt-1), t = 1 + z % (Tt-1);
    int bt = b*Tt + t;
    int n = threadIdx.x;
    __shared__ int warpCnt[32];
    int m = g_m23[bt*Nn + n];
    unsigned bal = __ballot_sync(0xffffffffu, m != 0);
    int lane = n & 31, w = n >> 5;
    int pre = __popc(bal & ((1u << lane) - 1u));
    if (lane == 0) warpCnt[w] = __popc(bal);
    __syncthreads();
    if (w == 0) {
        int v = warpCnt[lane];
        #pragma unroll
        for (int o = 1; o < 32; o <<= 1) {
            int u = __shfl_up_sync(0xffffffffu, v, o);
            if (lane >= o) v += u;
        }
        warpCnt[lane] = v;
    }
    __syncthreads();
    int base = (w == 0) ? 0 : warpCnt[w - 1];
    if (m) g_idx[z*Nn + base + pre] = n;
    if (n == 1023) g_cnt[z] = warpCnt[31];
}

// co/no fused graph conv epilogue
__global__ void k_co_no(const int* __restrict__ code_x, const int* __restrict__ neigh,
                        const float* __restrict__ c_emb, const float* __restrict__ n_emb,
                        const float* __restrict__ Wg, const float* __restrict__ bg)
{
    int bt = blockIdx.x;
    int n  = blockIdx.y * 8 + threadIdx.y;
    int g  = threadIdx.x;
    __shared__ float Wgs[CSc][GSg];
    int tid = threadIdx.y * 32 + threadIdx.x;
    for (int i = tid; i < CSc*GSg; i += 256) Wgs[i / GSg][i % GSg] = Wg[i];
    __syncthreads();
    const float* Srow = g_S + (long long)n * XCOLS + bt * CSc;
    float a1 = 0.f, a2 = 0.f;
    #pragma unroll
    for (int c = 0; c < CSc; c++) {
        float s = Srow[c];
        float w = Wgs[c][g];
        a1 += (c_emb[n*CSc + c] + s) * w;
        a2 += (n_emb[n*CSc + c] + s) * w;
    }
    float cx = (float)code_x[bt*Nn + n];
    float nx = (float)neigh [bt*Nn + n];
    float co = cx * a1 + bg[g];
    float no = nx * a2 + bg[g];
    co = (co >= 0.f) ? co : 0.01f * co;
    no = (no >= 0.f) ? no : 0.01f * no;
    long long o = ((long long)bt*Nn + n) * GSg + g;
    g_co[o] = co;
    g_no[o] = no;
}

__global__ void k_qin(const int* __restrict__ divided, const float* __restrict__ u_emb)
{
    int idx = blockIdx.x * blockDim.x + threadIdx.x;
    if (idx >= BT*Nn*GSg) return;
    int g  = idx % GSg;
    int bn = idx / GSg;
    int n  = bn % Nn;
    int bt = bn / Nn;
    int t  = bt % Tt;
    float v;
    if (divided[bn*3 + 2] > 0)       v = u_emb[n*GSg + g];
    else if (t > 0)                  v = g_no[((long long)(bt-1)*Nn + n)*GSg + g];
    else                             v = 0.f;
    g_qin[idx] = v;
}

// ---------------- fused compacted score + softmax ----------------
// block = (qtile of 64 compacted rows, z). two passes over the G row (L2).
__global__ __launch_bounds__(256) void k_score_softmax()
{
    int z = blockIdx.y;
    int cq = g_cnt[z];
    int qr0 = blockIdx.x * 64;
    if (qr0 >= cq) return;
    int b = z / (Tt-1), t = 1 + z % (Tt-1), bt = b*Tt + t;
    const int* idx = g_idx + z*Nn;
    const float* qp = g_q + (long long)bt*Nn*ATa;
    const float* kp = g_k + (long long)bt*Nn*ATa;
    float* G = g_G + (long long)z * Nn * Nn;

    __shared__ float qs[64][33];
    __shared__ float ks[64][33];
    __shared__ float pmax[16][64];
    __shared__ float rowmax[64];

    int tid = threadIdx.x;
    int tx = tid & 15, ty = tid >> 4;

    for (int i = tid; i < 64*32; i += 256) {
        int r = i >> 5, a = i & 31;
        int gq = qr0 + r;
        qs[r][a] = (gq < cq) ? qp[(long long)idx[gq]*ATa + a] : 0.f;
    }

    float tmax[4] = {-1e30f, -1e30f, -1e30f, -1e30f};
    const float scale = 0.17677669529663687f;

    for (int j0 = 0; j0 < cq; j0 += 64) {
        __syncthreads();
        for (int i = tid; i < 64*32; i += 256) {
            int r = i >> 5, a = i & 31;
            int gk = j0 + r;
            ks[r][a] = (gk < cq) ? kp[(long long)idx[gk]*ATa + a] : 0.f;
        }
        __syncthreads();
        float acc[4][4] = {};
        #pragma unroll
        for (int a = 0; a < 32; a++) {
            float av[4], bv[4];
            #pragma unroll
            for (int i = 0; i < 4; i++) av[i] = qs[ty*4+i][a];
            #pragma unroll
            for (int j = 0; j < 4; j++) bv[j] = ks[tx*4+j][a];
            #pragma unroll
            for (int i = 0; i < 4; i++)
                #pragma unroll
                for (int j = 0; j < 4; j++) acc[i][j] += av[i]*bv[j];
        }
        #pragma unroll
        for (int i = 0; i < 4; i++) {
            int gr = qr0 + ty*4 + i;
            if (gr >= cq) continue;
            #pragma unroll
            for (int j = 0; j < 4; j++) {
                int gc = j0 + tx*4 + j;
                if (gc >= cq) continue;
                float v = acc[i][j] * scale;
                G[(long long)gr*Nn + gc] = v;
                tmax[i] = fmaxf(tmax[i], v);
            }
        }
    }
    #pragma unroll
    for (int i = 0; i < 4; i++) pmax[tx][ty*4 + i] = tmax[i];
    __syncthreads();
    if (tid < 64) {
        float m = -1e30f;
        #pragma unroll
        for (int x = 0; x < 16; x++) m = fmaxf(m, pmax[x][tid]);
        rowmax[tid] = m;
    }
    __syncthreads();

    int row = tid >> 2, l4 = tid & 3;
    int gr = qr0 + row;
    float s = 0.f;
    if (gr < cq) {
        float m = rowmax[row];
        for (int c = l4; c < cq; c += 4) {
            float e = expf(G[(long long)gr*Nn + c] - m);
            G[(long long)gr*Nn + c] = e;
            s += e;
        }
    }
    s += __shfl_xor_sync(0xffffffffu, s, 1);
    s += __shfl_xor_sync(0xffffffffu, s, 2);
    if (gr < cq) {
        float inv = 1.f / s;
        for (int c = l4; c < cq; c += 4)
            G[(long long)gr*Nn + c] *= inv;
    }
}

// ---------------- GRU combine ----------------
__global__ void k_gru_combine(int t, int biasOnly, const float* __restrict__ gbhh)
{
    int idx = blockIdx.x * blockDim.x + threadIdx.x;
    if (idx >= Bb*Nn*Hh) return;
    int j  = idx % Hh;
    int bn = idx / Hh;
    int n  = bn % Nn;
    int b  = bn / Nn;
    int bt = b*Tt + t;
    const float* gir = g_gi + ((long long)bt*Nn + n) * H3;
    float g0, g1, g2;
    if (biasOnly) { g0 = gbhh[j]; g1 = gbhh[Hh + j]; g2 = gbhh[2*Hh + j]; }
    else {
        const float* ghr = g_gh + (long long)bn * H3;
        g0 = ghr[j]; g1 = ghr[Hh + j]; g2 = ghr[2*Hh + j];
    }
    float r  = sigf(gir[j]          + g0);
    float zz = sigf(gir[Hh + j]     + g1);
    float nn = tanhf(gir[2*Hh + j]  + r * g2);
    float hp = g_h[idx];
    float hm1 = (1.f - zz) * nn + zz * hp;
    int mi = bt*Nn + n;
    float hv = 0.f;
    if (t > 0 && g_m23[mi])
        hv = g_hm23[((long long)(b*(Tt-1) + (t-1))*Nn + n) * Hh + j];
    else if (g_m1[mi])
        hv = hm1;
    g_h[idx] = hv;
}

__global__ void k_outlast()
{
    int b = blockIdx.x, j = threadIdx.x;
    if (j >= Hh) return;
    float mx1 = -1e38f, mx23 = -1e38f;
    int h1 = 0, h23 = 0;
    int mbase = (b*Tt + (Tt-1)) * Nn;
    for (int n = 0; n < Nn; n++) {
        float hv = g_h[((long long)b*Nn + n)*Hh + j];
        if (g_m1 [mbase + n]) { h1 = 1;  mx1  = fmaxf(mx1,  hv); }
        if (g_m23[mbase + n]) { h23 = 1; mx23 = fmaxf(mx23, hv); }
    }
    g_stack[(long long)b*(Ee+1)*Hh + j] = (h1 ? mx1 : 0.f) + (h23 ? mx23 : 0.f);
}

// ---------------- event LSTM ----------------
__global__ void k_evgather(const int* __restrict__ events, const float* __restrict__ Eemb)
{
    int idx = blockIdx.x * blockDim.x + threadIdx.x;
    if (idx >= Bb*Ee*Ll*EDd) return;
    int d   = idx % EDd;
    int rem = idx / EDd;
    int l   = rem % Ll;
    int be  = rem / Ll;
    int b   = be / Ee, e = be % Ee;
    int ev  = events[((b*Tt + (Tt-1))*Ee + e)*Ll + l];
    g_xe[idx] = Eemb[(long long)ev*EDd + d];
}

__global__ void k_lstm(const float* __restrict__ Whh)
{
    __shared__ float sh[4][Hh];
    int j = threadIdx.x;
    int row0 = blockIdx.x * 4;
    float cs[4] = {0.f, 0.f, 0.f, 0.f};
    if (j < Hh) { sh[0][j] = 0.f; sh[1][j] = 0.f; sh[2][j] = 0.f; sh[3][j] = 0.f; }
    __syncthreads();
    for (int l = 0; l < Ll; l++) {
        float hn[4];
        if (j < Hh) {
            float a[4][4] = {};
            for (int k2 = 0; k2 < Hh; k2++) {
                float w0 = __ldg(&Whh[k2*H4 + j]);
                float w1 = __ldg(&Whh[k2*H4 + Hh + j]);
                float w2 = __ldg(&Whh[k2*H4 + 2*Hh + j]);
                float w3 = __ldg(&Whh[k2*H4 + 3*Hh + j]);
                #pragma unroll
                for (int r = 0; r < 4; r++) {
                    float hv = sh[r][k2];
                    a[r][0] += hv*w0; a[r][1] += hv*w1;
                    a[r][2] += hv*w2; a[r][3] += hv*w3;
                }
            }
            #pragma unroll
            for (int r = 0; r < 4; r++) {
                const float* gl = g_giL + ((long long)(row0 + r)*Ll + l) * H4;
                float gi_ = gl[j]        + a[r][0];
                float gf  = gl[Hh + j]   + a[r][1];
                float gg  = gl[2*Hh + j] + a[r][2];
                float go  = gl[3*Hh + j] + a[r][3];
                cs[r] = sigf(gf)*cs[r] + sigf(gi_)*tanhf(gg);
                hn[r] = sigf(go)*tanhf(cs[r]);
            }
        }
        __syncthreads();
        if (j < Hh) { sh[0][j] = hn[0]; sh[1][j] = hn[1]; sh[2][j] = hn[2]; sh[3][j] = hn[3]; }
        __syncthreads();
    }
    if (j < Hh) {
        #pragma unroll
        for (int r = 0; r < 4; r++) {
            int be = row0 + r;
            int b = be / Ee, e = be % Ee;
            g_stack[((long long)b*(Ee+1) + 1 + e)*Hh + j] = sh[r][j];
        }
    }
}

// ---------------- final dp attention + head ----------------
__global__ void k_wdctx(const float* __restrict__ Wd, const float* __restrict__ bd,
                        const float* __restrict__ ctx)
{
    int j = threadIdx.x;
    if (j < Hh) {
        float s = 0.f;
        for (int d = 0; d < DAd; d++) s += Wd[j*DAd + d] * ctx[d];
        g_wdc[j] = s;
    } else if (j == Hh) {
        float s = 0.f;
        for (int d = 0; d < DAd; d++) s += bd[d] * ctx[d];
        g_wdc[Hh] = s;
    }
}

__global__ void k_dp1()
{
    int b = blockIdx.x, s = blockIdx.y;
    const float* x = g_stack + ((long long)b*(Ee+1) + s) * Hh;
    __shared__ float red[256];
    int tid = threadIdx.x;
    float acc = 0.f;
    for (int h = tid; h < Hh; h += 256) acc += x[h] * g_wdc[h];
    red[tid] = acc; __syncthreads();
    for (int st = 128; st > 0; st >>= 1) { if (tid < st) red[tid] += red[tid + st]; __syncthreads(); }
    if (tid == 0) g_vu[b*(Ee+1) + s] = red[0] + g_wdc[Hh];
}

__global__ void k_dp2()
{
    int b = blockIdx.x, j = threadIdx.x;
    __shared__ float sm[Ee+1];
    if (j == 0) {
        float mx = -1e38f;
        for (int s = 0; s < Ee+1; s++) mx = fmaxf(mx, g_vu[b*(Ee+1) + s]);
        float sum = 0.f;
        for (int s = 0; s < Ee+1; s++) { float e = expf(g_vu[b*(Ee+1) + s] - mx); sm[s] = e; sum += e; }
        float inv = 1.f / sum;
        for (int s = 0; s < Ee+1; s++) sm[s] *= inv;
    }
    __syncthreads();
    if (j < Hh) {
        float acc = 0.f;
        for (int s = 0; s < Ee+1; s++) acc += sm[s] * g_stack[((long long)b*(Ee+1) + s)*Hh + j];
        g_o1[b*Hh + j] = acc;
    }
}

// ---------------- host driver ----------------
extern "C" void kernel_launch(void* const* d_in, const int* in_sizes, int n_in,
                              void* d_out, int out_size)
{
    const int*   code_x = (const int*)  d_in[0];
    const int*   divided= (const int*)  d_in[1];
    const int*   neigh  = (const int*)  d_in[2];
    const int*   events = (const int*)  d_in[4];
    const float* c_emb  = (const float*)d_in[5];
    const float* n_emb  = (const float*)d_in[6];
    const float* u_emb  = (const float*)d_in[7];
    const float* adj    = (const float*)d_in[8];
    const float* Wg     = (const float*)d_in[9];
    const float* bg     = (const float*)d_in[10];
    const float* gWih   = (const float*)d_in[11];
    const float* gWhh   = (const float*)d_in[12];
    const float* gbih   = (const float*)d_in[13];
    const float* gbhh   = (const float*)d_in[14];
    const float* Wq     = (const float*)d_in[15];
    const float* bq     = (const float*)d_in[16];
    const float* Wk     = (const float*)d_in[17];
    const float* bk     = (const float*)d_in[18];
    const float* Wv     = (const float*)d_in[19];
    const float* bv     = (const float*)d_in[20];
    const float* Wd     = (const float*)d_in[21];
    const float* bd     = (const float*)d_in[22];
    const float* ctx    = (const float*)d_in[23];
    const float* Eemb   = (const float*)d_in[24];
    const float* lWih   = (const float*)d_in[25];
    const float* lWhh   = (const float*)d_in[26];
    const float* lb     = (const float*)d_in[27];
    const float* Wc     = (const float*)d_in[28];
    const float* bc     = (const float*)d_in[29];
    float* out = (float*)d_out;

    float *pco, *pqin, *pq, *pk, *pv, *pgi, *pG, *phm, *ph, *pgh, *pxe, *pgiL, *po1;
    int *pidx, *pcnt;
    cudaGetSymbolAddress((void**)&pco,  g_co);
    cudaGetSymbolAddress((void**)&pqin, g_qin);
    cudaGetSymbolAddress((void**)&pq,   g_q);
    cudaGetSymbolAddress((void**)&pk,   g_k);
    cudaGetSymbolAddress((void**)&pv,   g_v);
    cudaGetSymbolAddress((void**)&pgi,  g_gi);
    cudaGetSymbolAddress((void**)&pG,   g_G);
    cudaGetSymbolAddress((void**)&phm,  g_hm23);
    cudaGetSymbolAddress((void**)&ph,   g_h);
    cudaGetSymbolAddress((void**)&pgh,  g_gh);
    cudaGetSymbolAddress((void**)&pxe,  g_xe);
    cudaGetSymbolAddress((void**)&pgiL, g_giL);
    cudaGetSymbolAddress((void**)&po1,  g_o1);
    cudaGetSymbolAddress((void**)&pidx, g_idx);
    cudaGetSymbolAddress((void**)&pcnt, g_cnt);

    // Phase A: input-only graph work (all t in parallel)
    k_build_X<<<(Nn*XCOLS + 255)/256, 256>>>(code_x, neigh, c_emb, n_emb);
    k_masks  <<<(BT*Nn + 255)/256, 256>>>(divided);
    k_wdctx  <<<1, 288>>>(Wd, bd, ctx);
    k_compact<<<BT2, 1024>>>();

    // S = adj @ X   (adj is ~2% dense -> spmm)
    k_spmm<<<Nn, 288>>>(adj);

    k_co_no<<<dim3(BT, Nn/8), dim3(32,8)>>>(code_x, neigh, c_emb, n_emb, Wg, bg);
    k_qin  <<<(BT*Nn*GSg + 255)/256, 256>>>(divided, u_emb);

    // q/k/v/gi projections (M = 24576, K = 32)
    k_gemm<<<dim3(1, 192,1), 256>>>(pco,  Wk,   bk,   pk,  BT*Nn, ATa, GSg, GSg, ATa, ATa, 0,0,0, 1, 0, 0,0,0);
    k_gemm<<<dim3(1, 192,1), 256>>>(pqin, Wq,   bq,   pq,  BT*Nn, ATa, GSg, GSg, ATa, ATa, 0,0,0, 1, 0, 0,0,0);
    k_gemm<<<dim3(5, 192,1), 256>>>(pco,  Wv,   bv,   pv,  BT*Nn, Hh,  GSg, GSg, Hh,  Hh,  0,0,0, 1, 0, 0,0,0);
    k_gemm<<<dim3(13,192,1), 256>>>(pco,  gWih, gbih, pgi, BT*Nn, H3,  GSg, GSg, H3,  H3,  0,0,0, 1, 0, 0,0,0);

    // attention (compacted m23 rows only): fused score+softmax, then tanh(P @ V)
    k_score_softmax<<<dim3(16, BT2), 256>>>();
    k_gemm<<<dim3(5, 8, BT2), 256>>>(pG, pv, 0, phm, Nn, Hh, Nn, Nn, Hh, Hh,
                                     (long long)Nn*Nn, (long long)Nn*Hh, (long long)Nn*Hh,
                                     2, 1, pidx, pidx, pcnt);

    // Phase B: GRU recurrence. t=0 has h=0 -> gh = bias (skip GEMM).
    cudaMemsetAsync(ph, 0, (size_t)Bb*Nn*Hh*sizeof(float));
    k_gru_combine<<<(Bb*Nn*Hh + 255)/256, 256>>>(0, 1, gbhh);
    for (int t = 1; t < Tt; t++) {
        k_gemm<<<dim3(13, 32, 1), 256>>>(ph, gWhh, gbhh, pgh, Bb*Nn, H3, Hh, Hh, H3, H3,
                                         0,0,0, 1, 0, 0,0,0);
        k_gru_combine<<<(Bb*Nn*Hh + 255)/256, 256>>>(t, 0, gbhh);
    }
    k_outlast<<<Bb, 288>>>();

    // Phase C: event LSTM
    k_evgather<<<(Bb*Ee*Ll*EDd + 255)/256, 256>>>(events, Eemb);
    k_gemm<<<dim3(17, 32, 1), 256>>>(pxe, lWih, lb, pgiL, Bb*Ee*Ll, H4, EDd, EDd, H4, H4,
                                     0,0,0, 1, 0, 0,0,0);
    k_lstm<<<(Bb*Ee)/4, 288>>>(lWhh);

    // Phase D: dp attention + classifier
    k_dp1<<<dim3(Bb, Ee+1), 256>>>();
    k_dp2<<<Bb, 288>>>();
    k_gemm<<<dim3(63, 1, 1), 256>>>(po1, Wc, bc, out, Bb, OUTo, Hh, Hh, OUTo, OUTo,
                                    0,0,0, 3, 0, 0,0,0);
}

// round 3
// speedup vs baseline: 1.6025x; 1.3396x over previous
#include <cuda_runtime.h>
#include <math.h>

// ---------------- problem constants ----------------
#define Bb   4
#define Tt   6
#define Nn   1024
#define CSc  48
#define GSg  32
#define Hh   270
#define ATa  32
#define DAd  64
#define Ee   32
#define Ll   32
#define EDd  400
#define OUTo 4000
#define BT   (Bb*Tt)        // 24
#define BT2  (Bb*(Tt-1))    // 20
#define H3   (3*Hh)         // 810
#define H4   (4*Hh)         // 1080
#define XCOLS (BT*CSc)      // 1152
#define KVG  1112           // packed cols: k(32) | v(270) | gi(810)
#define OFF_K 0
#define OFF_V 32
#define OFF_GI 302

// ---------------- device scratch ----------------
__device__ float g_X   [Nn*XCOLS];
__device__ float g_S   [Nn*XCOLS];
__device__ float g_co  [BT*Nn*GSg];
__device__ float g_no  [BT*Nn*GSg];
__device__ float g_qin [BT*Nn*GSg];
__device__ float g_q   [BT2*Nn*ATa];     // compact q per attention batch
__device__ float g_kvg [BT*Nn*KVG];      // packed k|v|gi (rows m1|m23 valid)
__device__ float g_packB[33*KVG];        // 32 rows of W + 1 bias row
__device__ float g_G   [BT2*Nn*Nn];
__device__ float g_hm23[BT2*Nn*Hh];
__device__ float g_h   [Bb*Nn*Hh];
__device__ float g_gh  [Bb*Nn*H3];
__device__ signed char g_m1 [BT*Nn];
__device__ signed char g_m23[BT*Nn];
__device__ int   g_idx [BT2*Nn];         // m23 compact per attn batch
__device__ int   g_cnt [BT2];
__device__ int   g_idxU[BT*Nn];          // m1|m23 compact per bt
__device__ int   g_cntU[BT];
__device__ int   g_idx1t[Tt*Bb*Nn];      // m1 compact per t over 4096 rows
__device__ int   g_c1t [Tt];
__device__ float g_xe  [Bb*Ee*Ll*EDd];
__device__ float g_giL [Bb*Ee*Ll*H4];
__device__ float g_stack[Bb*(Ee+1)*Hh];
__device__ float g_wdc [Hh+1];
__device__ float g_vu  [Bb*(Ee+1)];
__device__ float g_o1  [Bb*Hh];

__device__ __forceinline__ float sigf(float x){ return 1.f/(1.f+expf(-x)); }

// ---------------- generic tiled SGEMM with gather/scatter ----------------
// C[M,N] = epi( A[M,K] @ B[K,N] (+bias) ), 128x64 tile, TK=16, dbl-buffered.
// epi: 0 none, 1 +bias, 2 tanh, 3 +bias,sigmoid
#define TKk 16
__global__ __launch_bounds__(256) void k_gemm(
    const float* __restrict__ A, const float* __restrict__ B,
    const float* __restrict__ bias, float* __restrict__ C,
    int M, int N, int K,
    int lda, int ldb, int ldc,
    long long sA, long long sB, long long sC,
    int epi, int mapAz, int mapBz,
    const int* __restrict__ gAidx, int gAs,
    const int* __restrict__ gBidx, int gBs,
    const int* __restrict__ sCidx, int sCs,
    const int* __restrict__ cntM, const int* __restrict__ cntK)
{
    int z = blockIdx.z;
    if (cntM) M = cntM[z];
    if (cntK) K = cntK[z];
    int row0 = blockIdx.y * 128;
    if (row0 >= M) return;
    int col0 = blockIdx.x * 64;

    int za = mapAz ? (z + z/(Tt-1) + 1) : z;
    int zb = mapBz ? (z + z/(Tt-1) + 1) : z;
    const float* Ab = A + (long long)za * sA;
    const float* Bbp = B + (long long)zb * sB;
    float* Cb = C + (long long)z * sC;
    const int* gA = gAidx ? gAidx + (long long)z * gAs : (const int*)0;
    const int* gB = gBidx ? gBidx + (long long)z * gBs : (const int*)0;
    const int* sCr = sCidx ? sCidx + (long long)z * sCs : (const int*)0;

    __shared__ __align__(16) float As[2][TKk][132];
    __shared__ __align__(16) float Bs[2][TKk][64];

    int tid = threadIdx.x;
    int ka = tid & 15, ra = tid >> 4;
    int cb = tid & 63, kb = tid >> 6;
    int tx = tid & 15, ty = tid >> 4;

    float acc[8][4] = {};
    int nk = (K + TKk - 1) / TKk;

    {
        #pragma unroll
        for (int i = 0; i < 8; i++) {
            int r = ra + i*16;
            int gr = row0 + r, kk = ka;
            float v = 0.f;
            if (gr < M && kk < K) {
                int ar = gA ? gA[gr] : gr;
                v = Ab[(long long)ar*lda + kk];
            }
            As[0][ka][r] = v;
        }
        #pragma unroll
        for (int i = 0; i < 4; i++) {
            int kk = kb + i*4;
            int c = col0 + cb;
            float v = 0.f;
            if (kk < K && c < N) {
                int br = gB ? gB[kk] : kk;
                v = Bbp[(long long)br*ldb + c];
            }
            Bs[0][kb + i*4][cb] = v;
        }
    }
    __syncthreads();

    for (int kt = 0; kt < nk; kt++) {
        int buf = kt & 1;
        if (kt + 1 < nk) {
            int k0 = (kt + 1) * TKk;
            #pragma unroll
            for (int i = 0; i < 8; i++) {
                int r = ra + i*16;
                int gr = row0 + r, kk = k0 + ka;
                float v = 0.f;
                if (gr < M && kk < K) {
                    int ar = gA ? gA[gr] : gr;
                    v = Ab[(long long)ar*lda + kk];
                }
                As[buf^1][ka][r] = v;
            }
            #pragma unroll
            for (int i = 0; i < 4; i++) {
                int kk = k0 + kb + i*4;
                int c = col0 + cb;
                float v = 0.f;
                if (kk < K && c < N) {
                    int br = gB ? gB[kk] : kk;
                    v = Bbp[(long long)br*ldb + c];
                }
                Bs[buf^1][kb + i*4][cb] = v;
            }
        }
        #pragma unroll
        for (int kk = 0; kk < TKk; kk++) {
            float4 a0 = *(const float4*)&As[buf][kk][ty*8];
            float4 a1 = *(const float4*)&As[buf][kk][ty*8 + 4];
            float4 b0 = *(const float4*)&Bs[buf][kk][tx*4];
            float av[8] = {a0.x,a0.y,a0.z,a0.w,a1.x,a1.y,a1.z,a1.w};
            float bv[4] = {b0.x,b0.y,b0.z,b0.w};
            #pragma unroll
            for (int i = 0; i < 8; i++)
                #pragma unroll
                for (int j = 0; j < 4; j++)
                    acc[i][j] += av[i]*bv[j];
        }
        __syncthreads();
    }

    #pragma unroll
    for (int i = 0; i < 8; i++) {
        int r = row0 + ty*8 + i;
        if (r >= M) continue;
        long long crow = sCr ? (long long)sCr[r]*ldc : (long long)r*ldc;
        #pragma unroll
        for (int j = 0; j < 4; j++) {
            int c = col0 + tx*4 + j;
            if (c >= N) continue;
            float v = acc[i][j];
            if (epi == 1 || epi == 3) v += bias[c];
            if (epi == 2) v = tanhf(v);
            if (epi == 3) v = sigf(v);
            Cb[crow + c] = v;
        }
    }
}

// ---------------- input build ----------------
__global__ void k_build_X(const int* __restrict__ code_x, const int* __restrict__ neigh,
                          const float* __restrict__ c_emb, const float* __restrict__ n_emb)
{
    int idx = blockIdx.x * blockDim.x + threadIdx.x;
    if (idx >= Nn * XCOLS) return;
    int n  = idx / XCOLS;
    int r  = idx % XCOLS;
    int bt = r / CSc;
    int c  = r % CSc;
    float cx = (float)code_x[bt*Nn + n];
    float nx = (float)neigh [bt*Nn + n];
    g_X[idx] = cx * c_emb[n*CSc + c] + nx * n_emb[n*CSc + c];
}

__global__ __launch_bounds__(288) void k_spmm(const float* __restrict__ adj)
{
    int m = blockIdx.x;
    int tid = threadIdx.x;
    __shared__ float arow[Nn];
    for (int i = tid; i < Nn; i += 288) arow[i] = adj[(long long)m*Nn + i];
    __syncthreads();
    float acc0 = 0.f, acc1 = 0.f, acc2 = 0.f, acc3 = 0.f;
    for (int n = 0; n < Nn; n++) {
        float a = arow[n];
        if (a != 0.f) {
            const float* xr = g_X + (long long)n * XCOLS;
            acc0 += a * xr[tid];
            acc1 += a * xr[tid + 288];
            acc2 += a * xr[tid + 576];
            acc3 += a * xr[tid + 864];
        }
    }
    float* sr = g_S + (long long)m * XCOLS;
    sr[tid] = acc0; sr[tid+288] = acc1; sr[tid+576] = acc2; sr[tid+864] = acc3;
}

__global__ void k_masks(const int* __restrict__ divided)
{
    int i = blockIdx.x * blockDim.x + threadIdx.x;
    if (i >= BT*Nn) return;
    g_m1 [i] = (divided[3*i]     > 0) ? 1 : 0;
    g_m23[i] = (divided[3*i + 1] > 0 || divided[3*i + 2] > 0) ? 1 : 0;
}

// m23 compaction per attention batch z (t>=1)
__global__ __launch_bounds__(1024) void k_compact()
{
    int z = blockIdx.x;
    int b = z / (Tt-1), t = 1 + z % (Tt-1);
    int bt = b*Tt + t;
    int n = threadIdx.x;
    __shared__ int warpCnt[32];
    int m = g_m23[bt*Nn + n];
    unsigned bal = __ballot_sync(0xffffffffu, m != 0);
    int lane = n & 31, w = n >> 5;
    int pre = __popc(bal & ((1u << lane) - 1u));
    if (lane == 0) warpCnt[w] = __popc(bal);
    __syncthreads();
    if (w == 0) {
        int v = warpCnt[lane];
        #pragma unroll
        for (int o = 1; o < 32; o <<= 1) {
            int u = __shfl_up_sync(0xffffffffu, v, o);
            if (lane >= o) v += u;
        }
        warpCnt[lane] = v;
    }
    __syncthreads();
    int base = (w == 0) ? 0 : warpCnt[w - 1];
    if (m) g_idx[z*Nn + base + pre] = n;
    if (n == 1023) g_cnt[z] = warpCnt[31];
}

// m1|m23 compaction per bt
__global__ __launch_bounds__(1024) void k_compactU()
{
    int bt = blockIdx.x;
    int n = threadIdx.x;
    __shared__ int warpCnt[32];
    int m = (g_m1[bt*Nn + n] | g_m23[bt*Nn + n]);
    unsigned bal = __ballot_sync(0xffffffffu, m != 0);
    int lane = n & 31, w = n >> 5;
    int pre = __popc(bal & ((1u << lane) - 1u));
    if (lane == 0) warpCnt[w] = __popc(bal);
    __syncthreads();
    if (w == 0) {
        int v = warpCnt[lane];
        #pragma unroll
        for (int o = 1; o < 32; o <<= 1) {
            int u = __shfl_up_sync(0xffffffffu, v, o);
            if (lane >= o) v += u;
        }
        warpCnt[lane] = v;
    }
    __syncthreads();
    int base = (w == 0) ? 0 : warpCnt[w - 1];
    if (m) g_idxU[bt*Nn + base + pre] = n;
    if (n == 1023) g_cntU[bt] = warpCnt[31];
}

// m1 compaction per t over flattened 4096 rows (b-major)
__global__ __launch_bounds__(1024) void k_compact1t()
{
    int t = blockIdx.x;
    int n = threadIdx.x;
    int lane = n & 31, w = n >> 5;
    __shared__ int warpCnt[32];
    __shared__ int baseAcc;
    if (n == 0) baseAcc = 0;
    __syncthreads();
    for (int b = 0; b < Bb; b++) {
        int bt = b*Tt + t;
        int m = g_m1[bt*Nn + n];
        unsigned bal = __ballot_sync(0xffffffffu, m != 0);
        int pre = __popc(bal & ((1u << lane) - 1u));
        if (lane == 0) warpCnt[w] = __popc(bal);
        __syncthreads();
        if (w == 0) {
            int v = warpCnt[lane];
            #pragma unroll
            for (int o = 1; o < 32; o <<= 1) {
                int u = __shfl_up_sync(0xffffffffu, v, o);
                if (lane >= o) v += u;
            }
            warpCnt[lane] = v;
        }
        __syncthreads();
        int base = baseAcc + ((w == 0) ? 0 : warpCnt[w - 1]);
        if (m) g_idx1t[t*(Bb*Nn) + base + pre] = b*Nn + n;
        __syncthreads();
        if (n == 0) baseAcc += warpCnt[31];
        __syncthreads();
    }
    if (n == 0) g_c1t[t] = baseAcc;
}

__global__ void k_co_no(const int* __restrict__ code_x, const int* __restrict__ neigh,
                        const float* __restrict__ c_emb, const float* __restrict__ n_emb,
                        const float* __restrict__ Wg, const float* __restrict__ bg)
{
    int bt = blockIdx.x;
    int n  = blockIdx.y * 8 + threadIdx.y;
    int g  = threadIdx.x;
    __shared__ float Wgs[CSc][GSg];
    int tid = threadIdx.y * 32 + threadIdx.x;
    for (int i = tid; i < CSc*GSg; i += 256) Wgs[i / GSg][i % GSg] = Wg[i];
    __syncthreads();
    const float* Srow = g_S + (long long)n * XCOLS + bt * CSc;
    float a1 = 0.f, a2 = 0.f;
    #pragma unroll
    for (int c = 0; c < CSc; c++) {
        float s = Srow[c];
        float w = Wgs[c][g];
        a1 += (c_emb[n*CSc + c] + s) * w;
        a2 += (n_emb[n*CSc + c] + s) * w;
    }
    float cx = (float)code_x[bt*Nn + n];
    float nx = (float)neigh [bt*Nn + n];
    float co = cx * a1 + bg[g];
    float no = nx * a2 + bg[g];
    co = (co >= 0.f) ? co : 0.01f * co;
    no = (no >= 0.f) ? no : 0.01f * no;
    long long o = ((long long)bt*Nn + n) * GSg + g;
    g_co[o] = co;
    g_no[o] = no;
}

__global__ void k_qin(const int* __restrict__ divided, const float* __restrict__ u_emb)
{
    int idx = blockIdx.x * blockDim.x + threadIdx.x;
    if (idx >= BT*Nn*GSg) return;
    int g  = idx % GSg;
    int bn = idx / GSg;
    int n  = bn % Nn;
    int bt = bn / Nn;
    int t  = bt % Tt;
    float v;
    if (divided[bn*3 + 2] > 0)       v = u_emb[n*GSg + g];
    else if (t > 0)                  v = g_no[((long long)(bt-1)*Nn + n)*GSg + g];
    else                             v = 0.f;
    g_qin[idx] = v;
}

// pack [Wk | Wv | gWih] rows (32) + bias row at row 32
__global__ void k_packB(const float* __restrict__ Wk, const float* __restrict__ bk,
                        const float* __restrict__ Wv, const float* __restrict__ bv,
                        const float* __restrict__ Wih, const float* __restrict__ bih)
{
    int idx = blockIdx.x * blockDim.x + threadIdx.x;
    if (idx >= 33*KVG) return;
    int r = idx / KVG, c = idx % KVG;
    float v;
    if (r < 32) {
        if (c < OFF_V)       v = Wk [r*ATa + c];
        else if (c < OFF_GI) v = Wv [r*Hh  + (c - OFF_V)];
        else                 v = Wih[r*H3  + (c - OFF_GI)];
    } else {
        if (c < OFF_V)       v = bk [c];
        else if (c < OFF_GI) v = bv [c - OFF_V];
        else                 v = bih[c - OFF_GI];
    }
    g_packB[idx] = v;
}

// ---------------- fused compacted score + softmax ----------------
__global__ __launch_bounds__(256) void k_score_softmax()
{
    int z = blockIdx.y;
    int cq = g_cnt[z];
    int qr0 = blockIdx.x * 64;
    if (qr0 >= cq) return;
    int b = z / (Tt-1), t = 1 + z % (Tt-1), bt = b*Tt + t;
    const int* idx = g_idx + z*Nn;
    const float* qp = g_q + (long long)z*Nn*ATa;        // compact
    const float* kb = g_kvg + (long long)bt*Nn*KVG;     // gather
    float* G = g_G + (long long)z * Nn * Nn;

    __shared__ float qs[64][33];
    __shared__ float ks[64][33];
    __shared__ float pmax[16][64];
    __shared__ float rowmax[64];

    int tid = threadIdx.x;
    int tx = tid & 15, ty = tid >> 4;

    for (int i = tid; i < 64*32; i += 256) {
        int r = i >> 5, a = i & 31;
        int gq = qr0 + r;
        qs[r][a] = (gq < cq) ? qp[(long long)gq*ATa + a] : 0.f;
    }

    float tmax[4] = {-1e30f, -1e30f, -1e30f, -1e30f};
    const float scale = 0.17677669529663687f;

    for (int j0 = 0; j0 < cq; j0 += 64) {
        __syncthreads();
        for (int i = tid; i < 64*32; i += 256) {
            int r = i >> 5, a = i & 31;
            int gk = j0 + r;
            ks[r][a] = (gk < cq) ? kb[(long long)idx[gk]*KVG + a] : 0.f;
        }
        __syncthreads();
        float acc[4][4] = {};
        #pragma unroll
        for (int a = 0; a < 32; a++) {
            float av[4], bv[4];
            #pragma unroll
            for (int i = 0; i < 4; i++) av[i] = qs[ty*4+i][a];
            #pragma unroll
            for (int j = 0; j < 4; j++) bv[j] = ks[tx*4+j][a];
            #pragma unroll
            for (int i = 0; i < 4; i++)
                #pragma unroll
                for (int j = 0; j < 4; j++) acc[i][j] += av[i]*bv[j];
        }
        #pragma unroll
        for (int i = 0; i < 4; i++) {
            int gr = qr0 + ty*4 + i;
            if (gr >= cq) continue;
            #pragma unroll
            for (int j = 0; j < 4; j++) {
                int gc = j0 + tx*4 + j;
                if (gc >= cq) continue;
                float v = acc[i][j] * scale;
                G[(long long)gr*Nn + gc] = v;
                tmax[i] = fmaxf(tmax[i], v);
            }
        }
    }
    #pragma unroll
    for (int i = 0; i < 4; i++) pmax[tx][ty*4 + i] = tmax[i];
    __syncthreads();
    if (tid < 64) {
        float m = -1e30f;
        #pragma unroll
        for (int x = 0; x < 16; x++) m = fmaxf(m, pmax[x][tid]);
        rowmax[tid] = m;
    }
    __syncthreads();

    int row = tid >> 2, l4 = tid & 3;
    int gr = qr0 + row;
    float s = 0.f;
    if (gr < cq) {
        float m = rowmax[row];
        for (int c = l4; c < cq; c += 4) {
            float e = expf(G[(long long)gr*Nn + c] - m);
            G[(long long)gr*Nn + c] = e;
            s += e;
        }
    }
    s += __shfl_xor_sync(0xffffffffu, s, 1);
    s += __shfl_xor_sync(0xffffffffu, s, 2);
    if (gr < cq) {
        float inv = 1.f / s;
        for (int c = l4; c < cq; c += 4)
            G[(long long)gr*Nn + c] *= inv;
    }
}

// ---------------- GRU combine ----------------
__global__ void k_gru_combine(int t, const float* __restrict__ gbhh)
{
    int idx = blockIdx.x * blockDim.x + threadIdx.x;
    if (idx >= Bb*Nn*Hh) return;
    int j  = idx % Hh;
    int bn = idx / Hh;
    int n  = bn % Nn;
    int b  = bn / Nn;
    int bt = b*Tt + t;
    int mi = bt*Nn + n;
    float hv = 0.f;
    if (t > 0 && g_m23[mi]) {
        hv = g_hm23[((long long)(b*(Tt-1) + (t-1))*Nn + n) * Hh + j];
    } else if (g_m1[mi]) {
        const float* gir = g_kvg + ((long long)bt*Nn + n)*KVG + OFF_GI;
        float g0, g1, g2;
        if (t == 0) { g0 = gbhh[j]; g1 = gbhh[Hh + j]; g2 = gbhh[2*Hh + j]; }
        else {
            const float* ghr = g_gh + (long long)bn * H3;
            g0 = ghr[j]; g1 = ghr[Hh + j]; g2 = ghr[2*Hh + j];
        }
        float r  = sigf(gir[j]        + g0);
        float zz = sigf(gir[Hh + j]   + g1);
        float nn = tanhf(gir[2*Hh + j] + r * g2);
        float hp = (t == 0) ? 0.f : g_h[idx];
        hv = (1.f - zz) * nn + zz * hp;
    }
    g_h[idx] = hv;
}

__global__ void k_outlast()
{
    int b = blockIdx.x, j = threadIdx.x;
    if (j >= Hh) return;
    float mx1 = -1e38f, mx23 = -1e38f;
    int h1 = 0, h23 = 0;
    int mbase = (b*Tt + (Tt-1)) * Nn;
    for (int n = 0; n < Nn; n++) {
        float hv = g_h[((long long)b*Nn + n)*Hh + j];
        if (g_m1 [mbase + n]) { h1 = 1;  mx1  = fmaxf(mx1,  hv); }
        if (g_m23[mbase + n]) { h23 = 1; mx23 = fmaxf(mx23, hv); }
    }
    g_stack[(long long)b*(Ee+1)*Hh + j] = (h1 ? mx1 : 0.f) + (h23 ? mx23 : 0.f);
}

// ---------------- event LSTM ----------------
__global__ void k_evgather(const int* __restrict__ events, const float* __restrict__ Eemb)
{
    int idx = blockIdx.x * blockDim.x + threadIdx.x;
    if (idx >= Bb*Ee*Ll*EDd) return;
    int d   = idx % EDd;
    int rem = idx / EDd;
    int l   = rem % Ll;
    int be  = rem / Ll;
    int b   = be / Ee, e = be % Ee;
    int ev  = events[((b*Tt + (Tt-1))*Ee + e)*Ll + l];
    g_xe[idx] = Eemb[(long long)ev*EDd + d];
}

// persistent LSTM: 2 rows per block (64 blocks)
__global__ __launch_bounds__(288) void k_lstm(const float* __restrict__ Whh)
{
    __shared__ float sh[2][Hh];
    int j = threadIdx.x;
    int row0 = blockIdx.x * 2;
    float cs[2] = {0.f, 0.f};
    if (j < Hh) { sh[0][j] = 0.f; sh[1][j] = 0.f; }
    __syncthreads();
    for (int l = 0; l < Ll; l++) {
        float hn[2];
        if (j < Hh) {
            float a[2][4] = {};
            for (int k2 = 0; k2 < Hh; k2++) {
                float w0 = __ldg(&Whh[k2*H4 + j]);
                float w1 = __ldg(&Whh[k2*H4 + Hh + j]);
                float w2 = __ldg(&Whh[k2*H4 + 2*Hh + j]);
                float w3 = __ldg(&Whh[k2*H4 + 3*Hh + j]);
                #pragma unroll
                for (int r = 0; r < 2; r++) {
                    float hv = sh[r][k2];
                    a[r][0] += hv*w0; a[r][1] += hv*w1;
                    a[r][2] += hv*w2; a[r][3] += hv*w3;
                }
            }
            #pragma unroll
            for (int r = 0; r < 2; r++) {
                const float* gl = g_giL + ((long long)(row0 + r)*Ll + l) * H4;
                float gi_ = gl[j]        + a[r][0];
                float gf  = gl[Hh + j]   + a[r][1];
                float gg  = gl[2*Hh + j] + a[r][2];
                float go  = gl[3*Hh + j] + a[r][3];
                cs[r] = sigf(gf)*cs[r] + sigf(gi_)*tanhf(gg);
                hn[r] = sigf(go)*tanhf(cs[r]);
            }
        }
        __syncthreads();
        if (j < Hh) { sh[0][j] = hn[0]; sh[1][j] = hn[1]; }
        __syncthreads();
    }
    if (j < Hh) {
        #pragma unroll
        for (int r = 0; r < 2; r++) {
            int be = row0 + r;
            int b = be / Ee, e = be % Ee;
            g_stack[((long long)b*(Ee+1) + 1 + e)*Hh + j] = sh[r][j];
        }
    }
}

// ---------------- final dp attention + head ----------------
__global__ void k_wdctx(const float* __restrict__ Wd, const float* __restrict__ bd,
                        const float* __restrict__ ctx)
{
    int j = threadIdx.x;
    if (j < Hh) {
        float s = 0.f;
        for (int d = 0; d < DAd; d++) s += Wd[j*DAd + d] * ctx[d];
        g_wdc[j] = s;
    } else if (j == Hh) {
        float s = 0.f;
        for (int d = 0; d < DAd; d++) s += bd[d] * ctx[d];
        g_wdc[Hh] = s;
    }
}

__global__ void k_dp1()
{
    int b = blockIdx.x, s = blockIdx.y;
    const float* x = g_stack + ((long long)b*(Ee+1) + s) * Hh;
    __shared__ float red[256];
    int tid = threadIdx.x;
    float acc = 0.f;
    for (int h = tid; h < Hh; h += 256) acc += x[h] * g_wdc[h];
    red[tid] = acc; __syncthreads();
    for (int st = 128; st > 0; st >>= 1) { if (tid < st) red[tid] += red[tid + st]; __syncthreads(); }
    if (tid == 0) g_vu[b*(Ee+1) + s] = red[0] + g_wdc[Hh];
}

__global__ void k_dp2()
{
    int b = blockIdx.x, j = threadIdx.x;
    __shared__ float sm[Ee+1];
    if (j == 0) {
        float mx = -1e38f;
        for (int s = 0; s < Ee+1; s++) mx = fmaxf(mx, g_vu[b*(Ee+1) + s]);
        float sum = 0.f;
        for (int s = 0; s < Ee+1; s++) { float e = expf(g_vu[b*(Ee+1) + s] - mx); sm[s] = e; sum += e; }
        float inv = 1.f / sum;
        for (int s = 0; s < Ee+1; s++) sm[s] *= inv;
    }
    __syncthreads();
    if (j < Hh) {
        float acc = 0.f;
        for (int s = 0; s < Ee+1; s++) acc += sm[s] * g_stack[((long long)b*(Ee+1) + s)*Hh + j];
        g_o1[b*Hh + j] = acc;
    }
}

// ---------------- host driver ----------------
extern "C" void kernel_launch(void* const* d_in, const int* in_sizes, int n_in,
                              void* d_out, int out_size)
{
    const int*   code_x = (const int*)  d_in[0];
    const int*   divided= (const int*)  d_in[1];
    const int*   neigh  = (const int*)  d_in[2];
    const int*   events = (const int*)  d_in[4];
    const float* c_emb  = (const float*)d_in[5];
    const float* n_emb  = (const float*)d_in[6];
    const float* u_emb  = (const float*)d_in[7];
    const float* adj    = (const float*)d_in[8];
    const float* Wg     = (const float*)d_in[9];
    const float* bg     = (const float*)d_in[10];
    const float* gWih   = (const float*)d_in[11];
    const float* gWhh   = (const float*)d_in[12];
    const float* gbih   = (const float*)d_in[13];
    const float* gbhh   = (const float*)d_in[14];
    const float* Wq     = (const float*)d_in[15];
    const float* bq     = (const float*)d_in[16];
    const float* Wk     = (const float*)d_in[17];
    const float* bk     = (const float*)d_in[18];
    const float* Wv     = (const float*)d_in[19];
    const float* bv     = (const float*)d_in[20];
    const float* Wd     = (const float*)d_in[21];
    const float* bd     = (const float*)d_in[22];
    const float* ctx    = (const float*)d_in[23];
    const float* Eemb   = (const float*)d_in[24];
    const float* lWih   = (const float*)d_in[25];
    const float* lWhh   = (const float*)d_in[26];
    const float* lb     = (const float*)d_in[27];
    const float* Wc     = (const float*)d_in[28];
    const float* bc     = (const float*)d_in[29];
    float* out = (float*)d_out;

    float *pco, *pqin, *pq, *pkvg, *ppB, *pG, *phm, *ph, *pgh, *pxe, *pgiL, *po1;
    int *pidx, *pcnt, *pidxU, *pcntU, *pidx1t, *pc1t;
    cudaGetSymbolAddress((void**)&pco,   g_co);
    cudaGetSymbolAddress((void**)&pqin,  g_qin);
    cudaGetSymbolAddress((void**)&pq,    g_q);
    cudaGetSymbolAddress((void**)&pkvg,  g_kvg);
    cudaGetSymbolAddress((void**)&ppB,   g_packB);
    cudaGetSymbolAddress((void**)&pG,    g_G);
    cudaGetSymbolAddress((void**)&phm,   g_hm23);
    cudaGetSymbolAddress((void**)&ph,    g_h);
    cudaGetSymbolAddress((void**)&pgh,   g_gh);
    cudaGetSymbolAddress((void**)&pxe,   g_xe);
    cudaGetSymbolAddress((void**)&pgiL,  g_giL);
    cudaGetSymbolAddress((void**)&po1,   g_o1);
    cudaGetSymbolAddress((void**)&pidx,  g_idx);
    cudaGetSymbolAddress((void**)&pcnt,  g_cnt);
    cudaGetSymbolAddress((void**)&pidxU, g_idxU);
    cudaGetSymbolAddress((void**)&pcntU, g_cntU);
    cudaGetSymbolAddress((void**)&pidx1t,g_idx1t);
    cudaGetSymbolAddress((void**)&pc1t,  g_c1t);

    static cudaStream_t s2 = 0;
    static cudaEvent_t evF = 0, evJ = 0;
    if (!s2) {
        cudaStreamCreateWithFlags(&s2, cudaStreamNonBlocking);
        cudaEventCreateWithFlags(&evF, cudaEventDisableTiming);
        cudaEventCreateWithFlags(&evJ, cudaEventDisableTiming);
    }

    // fork: event-LSTM chain on s2 (independent until dp1)
    cudaEventRecord(evF, 0);
    cudaStreamWaitEvent(s2, evF, 0);
    k_evgather<<<(Bb*Ee*Ll*EDd + 255)/256, 256, 0, s2>>>(events, Eemb);
    k_gemm<<<dim3(17, 32, 1), 256, 0, s2>>>(pxe, lWih, lb, pgiL,
        Bb*Ee*Ll, H4, EDd, EDd, H4, H4, 0,0,0, 1, 0,0, 0,0, 0,0, 0,0, 0,0);
    k_lstm<<<(Bb*Ee)/2, 288, 0, s2>>>(lWhh);
    cudaEventRecord(evJ, s2);

    // main stream: graph conv + attention + GRU
    k_build_X<<<(Nn*XCOLS + 255)/256, 256>>>(code_x, neigh, c_emb, n_emb);
    k_masks  <<<(BT*Nn + 255)/256, 256>>>(divided);
    k_wdctx  <<<1, 288>>>(Wd, bd, ctx);
    k_compact  <<<BT2, 1024>>>();
    k_compactU <<<BT,  1024>>>();
    k_compact1t<<<Tt,  1024>>>();
    k_packB<<<(33*KVG + 255)/256, 256>>>(Wk, bk, Wv, bv, gWih, gbih);

    k_spmm<<<Nn, 288>>>(adj);
    k_co_no<<<dim3(BT, Nn/8), dim3(32,8)>>>(code_x, neigh, c_emb, n_emb, Wg, bg);
    k_qin  <<<(BT*Nn*GSg + 255)/256, 256>>>(divided, u_emb);

    // packed k|v|gi projection, only m1|m23 rows
    k_gemm<<<dim3(18, 8, BT), 256>>>(pco, ppB, ppB + 32*KVG, pkvg,
        Nn, KVG, GSg, GSg, KVG, KVG,
        (long long)Nn*GSg, 0, (long long)Nn*KVG,
        1, 0,0, pidxU, Nn, 0,0, pidxU, Nn, pcntU, 0);

    // q projection, compact m23 rows, t>=1 batches
    k_gemm<<<dim3(1, 8, BT2), 256>>>(pqin, Wq, bq, pq,
        Nn, ATa, GSg, GSg, ATa, ATa,
        (long long)Nn*GSg, 0, (long long)Nn*ATa,
        1, 1,0, pidx, Nn, 0,0, 0,0, pcnt, 0);

    // attention: fused score+softmax, then tanh(P @ V) scattered
    k_score_softmax<<<dim3(16, BT2), 256>>>();
    k_gemm<<<dim3(5, 8, BT2), 256>>>(pG, pkvg + OFF_V, 0, phm,
        Nn, Hh, Nn, Nn, KVG, Hh,
        (long long)Nn*Nn, (long long)Nn*KVG, (long long)Nn*Hh,
        2, 0,1, 0,0, pidx, Nn, pidx, Nn, pcnt, pcnt);

    // GRU: t=0 bias-only; t>=1 gh GEMM compacted to m1 rows
    k_gru_combine<<<(Bb*Nn*Hh + 255)/256, 256>>>(0, gbhh);
    for (int t = 1; t < Tt; t++) {
        k_gemm<<<dim3(13, 32, 1), 256>>>(ph, gWhh, gbhh, pgh,
            Bb*Nn, H3, Hh, Hh, H3, H3, 0,0,0,
            1, 0,0, pidx1t + t*(Bb*Nn), 0, 0,0, pidx1t + t*(Bb*Nn), 0, pc1t + t, 0);
        k_gru_combine<<<(Bb*Nn*Hh + 255)/256, 256>>>(t, gbhh);
    }
    k_outlast<<<Bb, 288>>>();

    // join LSTM chain, then dp attention + classifier
    cudaStreamWaitEvent(0, evJ, 0);
    k_dp1<<<dim3(Bb, Ee+1), 256>>>();
    k_dp2<<<Bb, 288>>>();
    k_gemm<<<dim3(63, 1, 1), 256>>>(po1, Wc, bc, out,
        Bb, OUTo, Hh, Hh, OUTo, OUTo, 0,0,0, 3, 0,0, 0,0, 0,0, 0,0, 0,0);
}

// round 4
// speedup vs baseline: 1.8149x; 1.1325x over previous
#include <cuda_runtime.h>
#include <math.h>

// ---------------- problem constants ----------------
#define Bb   4
#define Tt   6
#define Nn   1024
#define CSc  48
#define GSg  32
#define Hh   270
#define ATa  32
#define DAd  64
#define Ee   32
#define Ll   32
#define EDd  400
#define OUTo 4000
#define BT   (Bb*Tt)        // 24
#define BT2  (Bb*(Tt-1))    // 20
#define H3   (3*Hh)         // 810
#define H4   (4*Hh)         // 1080
#define XCOLS (BT*CSc)      // 1152
#define KVG  1112           // packed cols: k(32) | v(270) | gi(810)
#define OFF_K 0
#define OFF_V 32
#define OFF_GI 302

// ---------------- device scratch ----------------
__device__ float g_X   [Nn*XCOLS];
__device__ float g_S   [Nn*XCOLS];
__device__ float g_co  [BT*Nn*GSg];
__device__ float g_no  [BT*Nn*GSg];
__device__ float g_qin [BT*Nn*GSg];
__device__ float g_q   [BT2*Nn*ATa];
__device__ float g_kvg [BT*Nn*KVG];
__device__ float g_packB[33*KVG];
__device__ float g_G   [BT2*Nn*Nn];
__device__ float g_hm23[BT2*Nn*Hh];
__device__ float g_h   [Bb*Nn*Hh];
__device__ float g_gh  [Bb*Nn*H3];
__device__ signed char g_m1 [BT*Nn];
__device__ signed char g_m23[BT*Nn];
__device__ int   g_idx [BT2*Nn];
__device__ int   g_cnt [BT2];
__device__ int   g_idxU[BT*Nn];
__device__ int   g_cntU[BT];
__device__ int   g_idx1t[Tt*Bb*Nn];
__device__ int   g_c1t [Tt];
__device__ float g_xe  [Bb*Ee*Ll*EDd];
__device__ float g_giL [Bb*Ee*Ll*H4];
__device__ float g_W4  [Hh*Hh*4];        // repacked lstm Whh: [k][j][gate]
__device__ float g_stack[Bb*(Ee+1)*Hh];
__device__ float g_wdc [Hh+1];
__device__ float g_vu  [Bb*(Ee+1)];
__device__ float g_o1  [Bb*Hh];
__device__ float g_opart[Bb*16*2*Hh];

__device__ __forceinline__ float sigf(float x){ return 1.f/(1.f+expf(-x)); }

// ---------------- 128x64 tiled SGEMM with gather/scatter ----------------
#define TKk 16
__global__ __launch_bounds__(256) void k_gemm(
    const float* __restrict__ A, const float* __restrict__ B,
    const float* __restrict__ bias, float* __restrict__ C,
    int M, int N, int K,
    int lda, int ldb, int ldc,
    long long sA, long long sB, long long sC,
    int epi, int mapAz, int mapBz,
    const int* __restrict__ gAidx, int gAs,
    const int* __restrict__ gBidx, int gBs,
    const int* __restrict__ sCidx, int sCs,
    const int* __restrict__ cntM, const int* __restrict__ cntK)
{
    int z = blockIdx.z;
    if (cntM) M = cntM[z];
    if (cntK) K = cntK[z];
    int row0 = blockIdx.y * 128;
    if (row0 >= M) return;
    int col0 = blockIdx.x * 64;

    int za = mapAz ? (z + z/(Tt-1) + 1) : z;
    int zb = mapBz ? (z + z/(Tt-1) + 1) : z;
    const float* Ab = A + (long long)za * sA;
    const float* Bbp = B + (long long)zb * sB;
    float* Cb = C + (long long)z * sC;
    const int* gA = gAidx ? gAidx + (long long)z * gAs : (const int*)0;
    const int* gB = gBidx ? gBidx + (long long)z * gBs : (const int*)0;
    const int* sCr = sCidx ? sCidx + (long long)z * sCs : (const int*)0;

    __shared__ __align__(16) float As[2][TKk][132];
    __shared__ __align__(16) float Bs[2][TKk][64];

    int tid = threadIdx.x;
    int ka = tid & 15, ra = tid >> 4;
    int cb = tid & 63, kb = tid >> 6;
    int tx = tid & 15, ty = tid >> 4;

    float acc[8][4] = {};
    int nk = (K + TKk - 1) / TKk;

    {
        #pragma unroll
        for (int i = 0; i < 8; i++) {
            int r = ra + i*16;
            int gr = row0 + r, kk = ka;
            float v = 0.f;
            if (gr < M && kk < K) {
                int ar = gA ? gA[gr] : gr;
                v = Ab[(long long)ar*lda + kk];
            }
            As[0][ka][r] = v;
        }
        #pragma unroll
        for (int i = 0; i < 4; i++) {
            int kk = kb + i*4;
            int c = col0 + cb;
            float v = 0.f;
            if (kk < K && c < N) {
                int br = gB ? gB[kk] : kk;
                v = Bbp[(long long)br*ldb + c];
            }
            Bs[0][kb + i*4][cb] = v;
        }
    }
    __syncthreads();

    for (int kt = 0; kt < nk; kt++) {
        int buf = kt & 1;
        if (kt + 1 < nk) {
            int k0 = (kt + 1) * TKk;
            #pragma unroll
            for (int i = 0; i < 8; i++) {
                int r = ra + i*16;
                int gr = row0 + r, kk = k0 + ka;
                float v = 0.f;
                if (gr < M && kk < K) {
                    int ar = gA ? gA[gr] : gr;
                    v = Ab[(long long)ar*lda + kk];
                }
                As[buf^1][ka][r] = v;
            }
            #pragma unroll
            for (int i = 0; i < 4; i++) {
                int kk = k0 + kb + i*4;
                int c = col0 + cb;
                float v = 0.f;
                if (kk < K && c < N) {
                    int br = gB ? gB[kk] : kk;
                    v = Bbp[(long long)br*ldb + c];
                }
                Bs[buf^1][kb + i*4][cb] = v;
            }
        }
        #pragma unroll
        for (int kk = 0; kk < TKk; kk++) {
            float4 a0 = *(const float4*)&As[buf][kk][ty*8];
            float4 a1 = *(const float4*)&As[buf][kk][ty*8 + 4];
            float4 b0 = *(const float4*)&Bs[buf][kk][tx*4];
            float av[8] = {a0.x,a0.y,a0.z,a0.w,a1.x,a1.y,a1.z,a1.w};
            float bv[4] = {b0.x,b0.y,b0.z,b0.w};
            #pragma unroll
            for (int i = 0; i < 8; i++)
                #pragma unroll
                for (int j = 0; j < 4; j++)
                    acc[i][j] += av[i]*bv[j];
        }
        __syncthreads();
    }

    #pragma unroll
    for (int i = 0; i < 8; i++) {
        int r = row0 + ty*8 + i;
        if (r >= M) continue;
        long long crow = sCr ? (long long)sCr[r]*ldc : (long long)r*ldc;
        #pragma unroll
        for (int j = 0; j < 4; j++) {
            int c = col0 + tx*4 + j;
            if (c >= N) continue;
            float v = acc[i][j];
            if (epi == 1 || epi == 3) v += bias[c];
            if (epi == 2) v = tanhf(v);
            if (epi == 3) v = sigf(v);
            Cb[crow + c] = v;
        }
    }
}

// ---------------- 64x64 tiled SGEMM (for occupancy-limited shapes) ----------------
__global__ __launch_bounds__(256) void k_gemm64(
    const float* __restrict__ A, const float* __restrict__ B,
    const float* __restrict__ bias, float* __restrict__ C,
    int M, int N, int K,
    int lda, int ldb, int ldc,
    long long sA, long long sB, long long sC,
    int epi, int mapAz, int mapBz,
    const int* __restrict__ gAidx, int gAs,
    const int* __restrict__ gBidx, int gBs,
    const int* __restrict__ sCidx, int sCs,
    const int* __restrict__ cntM, const int* __restrict__ cntK)
{
    int z = blockIdx.z;
    if (cntM) M = cntM[z];
    if (cntK) K = cntK[z];
    int row0 = blockIdx.y * 64;
    if (row0 >= M) return;
    int col0 = blockIdx.x * 64;

    int za = mapAz ? (z + z/(Tt-1) + 1) : z;
    int zb = mapBz ? (z + z/(Tt-1) + 1) : z;
    const float* Ab = A + (long long)za * sA;
    const float* Bbp = B + (long long)zb * sB;
    float* Cb = C + (long long)z * sC;
    const int* gA = gAidx ? gAidx + (long long)z * gAs : (const int*)0;
    const int* gB = gBidx ? gBidx + (long long)z * gBs : (const int*)0;
    const int* sCr = sCidx ? sCidx + (long long)z * sCs : (const int*)0;

    __shared__ __align__(16) float As[2][TKk][68];
    __shared__ __align__(16) float Bs[2][TKk][64];

    int tid = threadIdx.x;
    int ka = tid & 15, ra = tid >> 4;
    int cb = tid & 63, kb = tid >> 6;
    int tx = tid & 15, ty = tid >> 4;

    float acc[4][4] = {};
    int nk = (K + TKk - 1) / TKk;

    {
        #pragma unroll
        for (int i = 0; i < 4; i++) {
            int r = ra + i*16;
            int gr = row0 + r, kk = ka;
            float v = 0.f;
            if (gr < M && kk < K) {
                int ar = gA ? gA[gr] : gr;
                v = Ab[(long long)ar*lda + kk];
            }
            As[0][ka][r] = v;
        }
        #pragma unroll
        for (int i = 0; i < 4; i++) {
            int kk = kb + i*4;
            int c = col0 + cb;
            float v = 0.f;
            if (kk < K && c < N) {
                int br = gB ? gB[kk] : kk;
                v = Bbp[(long long)br*ldb + c];
            }
            Bs[0][kb + i*4][cb] = v;
        }
    }
    __syncthreads();

    for (int kt = 0; kt < nk; kt++) {
        int buf = kt & 1;
        if (kt + 1 < nk) {
            int k0 = (kt + 1) * TKk;
            #pragma unroll
            for (int i = 0; i < 4; i++) {
                int r = ra + i*16;
                int gr = row0 + r, kk = k0 + ka;
                float v = 0.f;
                if (gr < M && kk < K) {
                    int ar = gA ? gA[gr] : gr;
                    v = Ab[(long long)ar*lda + kk];
                }
                As[buf^1][ka][r] = v;
            }
            #pragma unroll
            for (int i = 0; i < 4; i++) {
                int kk = k0 + kb + i*4;
                int c = col0 + cb;
                float v = 0.f;
                if (kk < K && c < N) {
                    int br = gB ? gB[kk] : kk;
                    v = Bbp[(long long)br*ldb + c];
                }
                Bs[buf^1][kb + i*4][cb] = v;
            }
        }
        #pragma unroll
        for (int kk = 0; kk < TKk; kk++) {
            float4 a0 = *(const float4*)&As[buf][kk][ty*4];
            float4 b0 = *(const float4*)&Bs[buf][kk][tx*4];
            float av[4] = {a0.x,a0.y,a0.z,a0.w};
            float bv[4] = {b0.x,b0.y,b0.z,b0.w};
            #pragma unroll
            for (int i = 0; i < 4; i++)
                #pragma unroll
                for (int j = 0; j < 4; j++)
                    acc[i][j] += av[i]*bv[j];
        }
        __syncthreads();
    }

    #pragma unroll
    for (int i = 0; i < 4; i++) {
        int r = row0 + ty*4 + i;
        if (r >= M) continue;
        long long crow = sCr ? (long long)sCr[r]*ldc : (long long)r*ldc;
        #pragma unroll
        for (int j = 0; j < 4; j++) {
            int c = col0 + tx*4 + j;
            if (c >= N) continue;
            float v = acc[i][j];
            if (epi == 1 || epi == 3) v += bias[c];
            if (epi == 2) v = tanhf(v);
            if (epi == 3) v = sigf(v);
            Cb[crow + c] = v;
        }
    }
}

// ---------------- input build ----------------
__global__ void k_build_X(const int* __restrict__ code_x, const int* __restrict__ neigh,
                          const float* __restrict__ c_emb, const float* __restrict__ n_emb)
{
    int idx = blockIdx.x * blockDim.x + threadIdx.x;
    if (idx >= Nn * XCOLS) return;
    int n  = idx / XCOLS;
    int r  = idx % XCOLS;
    int bt = r / CSc;
    int c  = r % CSc;
    float cx = (float)code_x[bt*Nn + n];
    float nx = (float)neigh [bt*Nn + n];
    g_X[idx] = cx * c_emb[n*CSc + c] + nx * n_emb[n*CSc + c];
}

__global__ __launch_bounds__(288) void k_spmm(const float* __restrict__ adj)
{
    int m = blockIdx.x;
    int tid = threadIdx.x;
    __shared__ float arow[Nn];
    for (int i = tid; i < Nn; i += 288) arow[i] = adj[(long long)m*Nn + i];
    __syncthreads();
    float acc0 = 0.f, acc1 = 0.f, acc2 = 0.f, acc3 = 0.f;
    for (int n = 0; n < Nn; n++) {
        float a = arow[n];
        if (a != 0.f) {
            const float* xr = g_X + (long long)n * XCOLS;
            acc0 += a * xr[tid];
            acc1 += a * xr[tid + 288];
            acc2 += a * xr[tid + 576];
            acc3 += a * xr[tid + 864];
        }
    }
    float* sr = g_S + (long long)m * XCOLS;
    sr[tid] = acc0; sr[tid+288] = acc1; sr[tid+576] = acc2; sr[tid+864] = acc3;
}

__global__ void k_masks(const int* __restrict__ divided)
{
    int i = blockIdx.x * blockDim.x + threadIdx.x;
    if (i >= BT*Nn) return;
    g_m1 [i] = (divided[3*i]     > 0) ? 1 : 0;
    g_m23[i] = (divided[3*i + 1] > 0 || divided[3*i + 2] > 0) ? 1 : 0;
}

__global__ __launch_bounds__(1024) void k_compact()
{
    int z = blockIdx.x;
    int b = z / (Tt-1), t = 1 + z % (Tt-1);
    int bt = b*Tt + t;
    int n = threadIdx.x;
    __shared__ int warpCnt[32];
    int m = g_m23[bt*Nn + n];
    unsigned bal = __ballot_sync(0xffffffffu, m != 0);
    int lane = n & 31, w = n >> 5;
    int pre = __popc(bal & ((1u << lane) - 1u));
    if (lane == 0) warpCnt[w] = __popc(bal);
    __syncthreads();
    if (w == 0) {
        int v = warpCnt[lane];
        #pragma unroll
        for (int o = 1; o < 32; o <<= 1) {
            int u = __shfl_up_sync(0xffffffffu, v, o);
            if (lane >= o) v += u;
        }
        warpCnt[lane] = v;
    }
    __syncthreads();
    int base = (w == 0) ? 0 : warpCnt[w - 1];
    if (m) g_idx[z*Nn + base + pre] = n;
    if (n == 1023) g_cnt[z] = warpCnt[31];
}

__global__ __launch_bounds__(1024) void k_compactU()
{
    int bt = blockIdx.x;
    int n = threadIdx.x;
    __shared__ int warpCnt[32];
    int m = (g_m1[bt*Nn + n] | g_m23[bt*Nn + n]);
    unsigned bal = __ballot_sync(0xffffffffu, m != 0);
    int lane = n & 31, w = n >> 5;
    int pre = __popc(bal & ((1u << lane) - 1u));
    if (lane == 0) warpCnt[w] = __popc(bal);
    __syncthreads();
    if (w == 0) {
        int v = warpCnt[lane];
        #pragma unroll
        for (int o = 1; o < 32; o <<= 1) {
            int u = __shfl_up_sync(0xffffffffu, v, o);
            if (lane >= o) v += u;
        }
        warpCnt[lane] = v;
    }
    __syncthreads();
    int base = (w == 0) ? 0 : warpCnt[w - 1];
    if (m) g_idxU[bt*Nn + base + pre] = n;
    if (n == 1023) g_cntU[bt] = warpCnt[31];
}

__global__ __launch_bounds__(1024) void k_compact1t()
{
    int t = blockIdx.x;
    int n = threadIdx.x;
    int lane = n & 31, w = n >> 5;
    __shared__ int warpCnt[32];
    __shared__ int baseAcc;
    if (n == 0) baseAcc = 0;
    __syncthreads();
    for (int b = 0; b < Bb; b++) {
        int bt = b*Tt + t;
        int m = g_m1[bt*Nn + n];
        unsigned bal = __ballot_sync(0xffffffffu, m != 0);
        int pre = __popc(bal & ((1u << lane) - 1u));
        if (lane == 0) warpCnt[w] = __popc(bal);
        __syncthreads();
        if (w == 0) {
            int v = warpCnt[lane];
            #pragma unroll
            for (int o = 1; o < 32; o <<= 1) {
                int u = __shfl_up_sync(0xffffffffu, v, o);
                if (lane >= o) v += u;
            }
            warpCnt[lane] = v;
        }
        __syncthreads();
        int base = baseAcc + ((w == 0) ? 0 : warpCnt[w - 1]);
        if (m) g_idx1t[t*(Bb*Nn) + base + pre] = b*Nn + n;
        __syncthreads();
        if (n == 0) baseAcc += warpCnt[31];
        __syncthreads();
    }
    if (n == 0) g_c1t[t] = baseAcc;
}

__global__ void k_co_no(const int* __restrict__ code_x, const int* __restrict__ neigh,
                        const float* __restrict__ c_emb, const float* __restrict__ n_emb,
                        const float* __restrict__ Wg, const float* __restrict__ bg)
{
    int bt = blockIdx.x;
    int n  = blockIdx.y * 8 + threadIdx.y;
    int g  = threadIdx.x;
    __shared__ float Wgs[CSc][GSg];
    int tid = threadIdx.y * 32 + threadIdx.x;
    for (int i = tid; i < CSc*GSg; i += 256) Wgs[i / GSg][i % GSg] = Wg[i];
    __syncthreads();
    const float* Srow = g_S + (long long)n * XCOLS + bt * CSc;
    float a1 = 0.f, a2 = 0.f;
    #pragma unroll
    for (int c = 0; c < CSc; c++) {
        float s = Srow[c];
        float w = Wgs[c][g];
        a1 += (c_emb[n*CSc + c] + s) * w;
        a2 += (n_emb[n*CSc + c] + s) * w;
    }
    float cx = (float)code_x[bt*Nn + n];
    float nx = (float)neigh [bt*Nn + n];
    float co = cx * a1 + bg[g];
    float no = nx * a2 + bg[g];
    co = (co >= 0.f) ? co : 0.01f * co;
    no = (no >= 0.f) ? no : 0.01f * no;
    long long o = ((long long)bt*Nn + n) * GSg + g;
    g_co[o] = co;
    g_no[o] = no;
}

__global__ void k_qin(const int* __restrict__ divided, const float* __restrict__ u_emb)
{
    int idx = blockIdx.x * blockDim.x + threadIdx.x;
    if (idx >= BT*Nn*GSg) return;
    int g  = idx % GSg;
    int bn = idx / GSg;
    int n  = bn % Nn;
    int bt = bn / Nn;
    int t  = bt % Tt;
    float v;
    if (divided[bn*3 + 2] > 0)       v = u_emb[n*GSg + g];
    else if (t > 0)                  v = g_no[((long long)(bt-1)*Nn + n)*GSg + g];
    else                             v = 0.f;
    g_qin[idx] = v;
}

__global__ void k_packB(const float* __restrict__ Wk, const float* __restrict__ bk,
                        const float* __restrict__ Wv, const float* __restrict__ bv,
                        const float* __restrict__ Wih, const float* __restrict__ bih)
{
    int idx = blockIdx.x * blockDim.x + threadIdx.x;
    if (idx >= 33*KVG) return;
    int r = idx / KVG, c = idx % KVG;
    float v;
    if (r < 32) {
        if (c < OFF_V)       v = Wk [r*ATa + c];
        else if (c < OFF_GI) v = Wv [r*Hh  + (c - OFF_V)];
        else                 v = Wih[r*H3  + (c - OFF_GI)];
    } else {
        if (c < OFF_V)       v = bk [c];
        else if (c < OFF_GI) v = bv [c - OFF_V];
        else                 v = bih[c - OFF_GI];
    }
    g_packB[idx] = v;
}

// repack lstm Whh to [k][j][gate] for float4 loads
__global__ void k_packWhh(const float* __restrict__ Whh)
{
    int idx = blockIdx.x * blockDim.x + threadIdx.x;
    if (idx >= Hh*Hh*4) return;
    int g = idx & 3;
    int rem = idx >> 2;
    int j = rem % Hh;
    int k2 = rem / Hh;
    g_W4[idx] = Whh[k2*H4 + g*Hh + j];
}

// ---------------- fused compacted score + softmax ----------------
__global__ __launch_bounds__(256) void k_score_softmax()
{
    int z = blockIdx.y;
    int cq = g_cnt[z];
    int qr0 = blockIdx.x * 64;
    if (qr0 >= cq) return;
    int b = z / (Tt-1), t = 1 + z % (Tt-1), bt = b*Tt + t;
    const int* idx = g_idx + z*Nn;
    const float* qp = g_q + (long long)z*Nn*ATa;
    const float* kb = g_kvg + (long long)bt*Nn*KVG;
    float* G = g_G + (long long)z * Nn * Nn;

    __shared__ float qs[64][33];
    __shared__ float ks[64][33];
    __shared__ float pmax[16][64];
    __shared__ float rowmax[64];

    int tid = threadIdx.x;
    int tx = tid & 15, ty = tid >> 4;

    for (int i = tid; i < 64*32; i += 256) {
        int r = i >> 5, a = i & 31;
        int gq = qr0 + r;
        qs[r][a] = (gq < cq) ? qp[(long long)gq*ATa + a] : 0.f;
    }

    float tmax[4] = {-1e30f, -1e30f, -1e30f, -1e30f};
    const float scale = 0.17677669529663687f;

    for (int j0 = 0; j0 < cq; j0 += 64) {
        __syncthreads();
        for (int i = tid; i < 64*32; i += 256) {
            int r = i >> 5, a = i & 31;
            int gk = j0 + r;
            ks[r][a] = (gk < cq) ? kb[(long long)idx[gk]*KVG + a] : 0.f;
        }
        __syncthreads();
        float acc[4][4] = {};
        #pragma unroll
        for (int a = 0; a < 32; a++) {
            float av[4], bv[4];
            #pragma unroll
            for (int i = 0; i < 4; i++) av[i] = qs[ty*4+i][a];
            #pragma unroll
            for (int j = 0; j < 4; j++) bv[j] = ks[tx*4+j][a];
            #pragma unroll
            for (int i = 0; i < 4; i++)
                #pragma unroll
                for (int j = 0; j < 4; j++) acc[i][j] += av[i]*bv[j];
        }
        #pragma unroll
        for (int i = 0; i < 4; i++) {
            int gr = qr0 + ty*4 + i;
            if (gr >= cq) continue;
            #pragma unroll
            for (int j = 0; j < 4; j++) {
                int gc = j0 + tx*4 + j;
                if (gc >= cq) continue;
                float v = acc[i][j] * scale;
                G[(long long)gr*Nn + gc] = v;
                tmax[i] = fmaxf(tmax[i], v);
            }
        }
    }
    #pragma unroll
    for (int i = 0; i < 4; i++) pmax[tx][ty*4 + i] = tmax[i];
    __syncthreads();
    if (tid < 64) {
        float m = -1e30f;
        #pragma unroll
        for (int x = 0; x < 16; x++) m = fmaxf(m, pmax[x][tid]);
        rowmax[tid] = m;
    }
    __syncthreads();

    int row = tid >> 2, l4 = tid & 3;
    int gr = qr0 + row;
    float s = 0.f;
    if (gr < cq) {
        float m = rowmax[row];
        for (int c = l4; c < cq; c += 4) {
            float e = expf(G[(long long)gr*Nn + c] - m);
            G[(long long)gr*Nn + c] = e;
            s += e;
        }
    }
    s += __shfl_xor_sync(0xffffffffu, s, 1);
    s += __shfl_xor_sync(0xffffffffu, s, 2);
    if (gr < cq) {
        float inv = 1.f / s;
        for (int c = l4; c < cq; c += 4)
            G[(long long)gr*Nn + c] *= inv;
    }
}

// ---------------- GRU combine ----------------
__global__ void k_gru_combine(int t, const float* __restrict__ gbhh)
{
    int idx = blockIdx.x * blockDim.x + threadIdx.x;
    if (idx >= Bb*Nn*Hh) return;
    int j  = idx % Hh;
    int bn = idx / Hh;
    int n  = bn % Nn;
    int b  = bn / Nn;
    int bt = b*Tt + t;
    int mi = bt*Nn + n;
    float hv = 0.f;
    if (t > 0 && g_m23[mi]) {
        hv = g_hm23[((long long)(b*(Tt-1) + (t-1))*Nn + n) * Hh + j];
    } else if (g_m1[mi]) {
        const float* gir = g_kvg + ((long long)bt*Nn + n)*KVG + OFF_GI;
        float g0, g1, g2;
        if (t == 0) { g0 = gbhh[j]; g1 = gbhh[Hh + j]; g2 = gbhh[2*Hh + j]; }
        else {
            const float* ghr = g_gh + (long long)bn * H3;
            g0 = ghr[j]; g1 = ghr[Hh + j]; g2 = ghr[2*Hh + j];
        }
        float r  = sigf(gir[j]        + g0);
        float zz = sigf(gir[Hh + j]   + g1);
        float nn = tanhf(gir[2*Hh + j] + r * g2);
        float hp = (t == 0) ? 0.f : g_h[idx];
        hv = (1.f - zz) * nn + zz * hp;
    }
    g_h[idx] = hv;
}

// parallel outlast: stage 1 partial maxima over 64-n slices
__global__ __launch_bounds__(288) void k_outlast1()
{
    int b = blockIdx.x, p = blockIdx.y, j = threadIdx.x;
    if (j >= Hh) return;
    float mx1 = -1e38f, mx23 = -1e38f;
    int mbase = (b*Tt + (Tt-1)) * Nn;
    int n0 = p * 64;
    for (int n = n0; n < n0 + 64; n++) {
        float hv = g_h[((long long)b*Nn + n)*Hh + j];
        if (g_m1 [mbase + n]) mx1  = fmaxf(mx1,  hv);
        if (g_m23[mbase + n]) mx23 = fmaxf(mx23, hv);
    }
    g_opart[((b*16 + p)*2    )*Hh + j] = mx1;
    g_opart[((b*16 + p)*2 + 1)*Hh + j] = mx23;
}

__global__ __launch_bounds__(288) void k_outlast2()
{
    int b = blockIdx.x, j = threadIdx.x;
    if (j >= Hh) return;
    float mx1 = -1e38f, mx23 = -1e38f;
    #pragma unroll
    for (int p = 0; p < 16; p++) {
        mx1  = fmaxf(mx1,  g_opart[((b*16 + p)*2    )*Hh + j]);
        mx23 = fmaxf(mx23, g_opart[((b*16 + p)*2 + 1)*Hh + j]);
    }
    float o = 0.f;
    if (mx1  > -1e37f) o += mx1;
    if (mx23 > -1e37f) o += mx23;
    g_stack[(long long)b*(Ee+1)*Hh + j] = o;
}

// ---------------- event LSTM ----------------
__global__ void k_evgather(const int* __restrict__ events, const float* __restrict__ Eemb)
{
    int idx = blockIdx.x * blockDim.x + threadIdx.x;
    if (idx >= Bb*Ee*Ll*EDd) return;
    int d   = idx % EDd;
    int rem = idx / EDd;
    int l   = rem % Ll;
    int be  = rem / Ll;
    int b   = be / Ee, e = be % Ee;
    int ev  = events[((b*Tt + (Tt-1))*Ee + e)*Ll + l];
    g_xe[idx] = Eemb[(long long)ev*EDd + d];
}

// persistent LSTM: 2 rows per block (64 blocks), float4-packed Whh
__global__ __launch_bounds__(288) void k_lstm()
{
    __shared__ float sh[2][Hh];
    const float4* W4 = (const float4*)g_W4;
    int j = threadIdx.x;
    int row0 = blockIdx.x * 2;
    float cs[2] = {0.f, 0.f};
    if (j < Hh) { sh[0][j] = 0.f; sh[1][j] = 0.f; }
    __syncthreads();
    for (int l = 0; l < Ll; l++) {
        float hn[2];
        if (j < Hh) {
            float a[2][4] = {};
            for (int k2 = 0; k2 < Hh; k2++) {
                float4 w = __ldg(&W4[k2*Hh + j]);
                #pragma unroll
                for (int r = 0; r < 2; r++) {
                    float hv = sh[r][k2];
                    a[r][0] += hv*w.x; a[r][1] += hv*w.y;
                    a[r][2] += hv*w.z; a[r][3] += hv*w.w;
                }
            }
            #pragma unroll
            for (int r = 0; r < 2; r++) {
                const float* gl = g_giL + ((long long)(row0 + r)*Ll + l) * H4;
                float gi_ = gl[j]        + a[r][0];
                float gf  = gl[Hh + j]   + a[r][1];
                float gg  = gl[2*Hh + j] + a[r][2];
                float go  = gl[3*Hh + j] + a[r][3];
                cs[r] = sigf(gf)*cs[r] + sigf(gi_)*tanhf(gg);
                hn[r] = sigf(go)*tanhf(cs[r]);
            }
        }
        __syncthreads();
        if (j < Hh) { sh[0][j] = hn[0]; sh[1][j] = hn[1]; }
        __syncthreads();
    }
    if (j < Hh) {
        #pragma unroll
        for (int r = 0; r < 2; r++) {
            int be = row0 + r;
            int b = be / Ee, e = be % Ee;
            g_stack[((long long)b*(Ee+1) + 1 + e)*Hh + j] = sh[r][j];
        }
    }
}

// ---------------- final dp attention + head ----------------
__global__ void k_wdctx(const float* __restrict__ Wd, const float* __restrict__ bd,
                        const float* __restrict__ ctx)
{
    int j = threadIdx.x;
    if (j < Hh) {
        float s = 0.f;
        for (int d = 0; d < DAd; d++) s += Wd[j*DAd + d] * ctx[d];
        g_wdc[j] = s;
    } else if (j == Hh) {
        float s = 0.f;
        for (int d = 0; d < DAd; d++) s += bd[d] * ctx[d];
        g_wdc[Hh] = s;
    }
}

__global__ void k_dp1()
{
    int b = blockIdx.x, s = blockIdx.y;
    const float* x = g_stack + ((long long)b*(Ee+1) + s) * Hh;
    __shared__ float red[256];
    int tid = threadIdx.x;
    float acc = 0.f;
    for (int h = tid; h < Hh; h += 256) acc += x[h] * g_wdc[h];
    red[tid] = acc; __syncthreads();
    for (int st = 128; st > 0; st >>= 1) { if (tid < st) red[tid] += red[tid + st]; __syncthreads(); }
    if (tid == 0) g_vu[b*(Ee+1) + s] = red[0] + g_wdc[Hh];
}

__global__ void k_dp2()
{
    int b = blockIdx.x, j = threadIdx.x;
    __shared__ float sm[Ee+1];
    if (j == 0) {
        float mx = -1e38f;
        for (int s = 0; s < Ee+1; s++) mx = fmaxf(mx, g_vu[b*(Ee+1) + s]);
        float sum = 0.f;
        for (int s = 0; s < Ee+1; s++) { float e = expf(g_vu[b*(Ee+1) + s] - mx); sm[s] = e; sum += e; }
        float inv = 1.f / sum;
        for (int s = 0; s < Ee+1; s++) sm[s] *= inv;
    }
    __syncthreads();
    if (j < Hh) {
        float acc = 0.f;
        for (int s = 0; s < Ee+1; s++) acc += sm[s] * g_stack[((long long)b*(Ee+1) + s)*Hh + j];
        g_o1[b*Hh + j] = acc;
    }
}

// ---------------- host driver ----------------
extern "C" void kernel_launch(void* const* d_in, const int* in_sizes, int n_in,
                              void* d_out, int out_size)
{
    const int*   code_x = (const int*)  d_in[0];
    const int*   divided= (const int*)  d_in[1];
    const int*   neigh  = (const int*)  d_in[2];
    const int*   events = (const int*)  d_in[4];
    const float* c_emb  = (const float*)d_in[5];
    const float* n_emb  = (const float*)d_in[6];
    const float* u_emb  = (const float*)d_in[7];
    const float* adj    = (const float*)d_in[8];
    const float* Wg     = (const float*)d_in[9];
    const float* bg     = (const float*)d_in[10];
    const float* gWih   = (const float*)d_in[11];
    const float* gWhh   = (const float*)d_in[12];
    const float* gbih   = (const float*)d_in[13];
    const float* gbhh   = (const float*)d_in[14];
    const float* Wq     = (const float*)d_in[15];
    const float* bq     = (const float*)d_in[16];
    const float* Wk     = (const float*)d_in[17];
    const float* bk     = (const float*)d_in[18];
    const float* Wv     = (const float*)d_in[19];
    const float* bv     = (const float*)d_in[20];
    const float* Wd     = (const float*)d_in[21];
    const float* bd     = (const float*)d_in[22];
    const float* ctx    = (const float*)d_in[23];
    const float* Eemb   = (const float*)d_in[24];
    const float* lWih   = (const float*)d_in[25];
    const float* lWhh   = (const float*)d_in[26];
    const float* lb     = (const float*)d_in[27];
    const float* Wc     = (const float*)d_in[28];
    const float* bc     = (const float*)d_in[29];
    float* out = (float*)d_out;

    float *pco, *pqin, *pq, *pkvg, *ppB, *pG, *phm, *ph, *pgh, *pxe, *pgiL, *po1;
    int *pidx, *pcnt, *pidxU, *pcntU, *pidx1t, *pc1t;
    cudaGetSymbolAddress((void**)&pco,   g_co);
    cudaGetSymbolAddress((void**)&pqin,  g_qin);
    cudaGetSymbolAddress((void**)&pq,    g_q);
    cudaGetSymbolAddress((void**)&pkvg,  g_kvg);
    cudaGetSymbolAddress((void**)&ppB,   g_packB);
    cudaGetSymbolAddress((void**)&pG,    g_G);
    cudaGetSymbolAddress((void**)&phm,   g_hm23);
    cudaGetSymbolAddress((void**)&ph,    g_h);
    cudaGetSymbolAddress((void**)&pgh,   g_gh);
    cudaGetSymbolAddress((void**)&pxe,   g_xe);
    cudaGetSymbolAddress((void**)&pgiL,  g_giL);
    cudaGetSymbolAddress((void**)&po1,   g_o1);
    cudaGetSymbolAddress((void**)&pidx,  g_idx);
    cudaGetSymbolAddress((void**)&pcnt,  g_cnt);
    cudaGetSymbolAddress((void**)&pidxU, g_idxU);
    cudaGetSymbolAddress((void**)&pcntU, g_cntU);
    cudaGetSymbolAddress((void**)&pidx1t,g_idx1t);
    cudaGetSymbolAddress((void**)&pc1t,  g_c1t);

    static cudaStream_t s2 = 0;
    static cudaEvent_t evF = 0, evJ = 0;
    if (!s2) {
        cudaStreamCreateWithFlags(&s2, cudaStreamNonBlocking);
        cudaEventCreateWithFlags(&evF, cudaEventDisableTiming);
        cudaEventCreateWithFlags(&evJ, cudaEventDisableTiming);
    }

    // fork: event-LSTM chain on s2 (independent until dp1)
    cudaEventRecord(evF, 0);
    cudaStreamWaitEvent(s2, evF, 0);
    k_packWhh<<<(Hh*Hh*4 + 255)/256, 256, 0, s2>>>(lWhh);
    k_evgather<<<(Bb*Ee*Ll*EDd + 255)/256, 256, 0, s2>>>(events, Eemb);
    k_gemm<<<dim3(17, 32, 1), 256, 0, s2>>>(pxe, lWih, lb, pgiL,
        Bb*Ee*Ll, H4, EDd, EDd, H4, H4, 0,0,0, 1, 0,0, 0,0, 0,0, 0,0, 0,0);
    k_lstm<<<(Bb*Ee)/2, 288, 0, s2>>>();
    cudaEventRecord(evJ, s2);

    // main stream
    k_build_X<<<(Nn*XCOLS + 255)/256, 256>>>(code_x, neigh, c_emb, n_emb);
    k_masks  <<<(BT*Nn + 255)/256, 256>>>(divided);
    k_wdctx  <<<1, 288>>>(Wd, bd, ctx);
    k_compact  <<<BT2, 1024>>>();
    k_compactU <<<BT,  1024>>>();
    k_compact1t<<<Tt,  1024>>>();
    k_packB<<<(33*KVG + 255)/256, 256>>>(Wk, bk, Wv, bv, gWih, gbih);

    k_spmm<<<Nn, 288>>>(adj);
    k_co_no<<<dim3(BT, Nn/8), dim3(32,8)>>>(code_x, neigh, c_emb, n_emb, Wg, bg);
    k_qin  <<<(BT*Nn*GSg + 255)/256, 256>>>(divided, u_emb);

    // packed k|v|gi projection, only m1|m23 rows
    k_gemm<<<dim3(18, 8, BT), 256>>>(pco, ppB, ppB + 32*KVG, pkvg,
        Nn, KVG, GSg, GSg, KVG, KVG,
        (long long)Nn*GSg, 0, (long long)Nn*KVG,
        1, 0,0, pidxU, Nn, 0,0, pidxU, Nn, pcntU, 0);

    // q projection, compact m23 rows, t>=1 batches
    k_gemm64<<<dim3(1, 16, BT2), 256>>>(pqin, Wq, bq, pq,
        Nn, ATa, GSg, GSg, ATa, ATa,
        (long long)Nn*GSg, 0, (long long)Nn*ATa,
        1, 1,0, pidx, Nn, 0,0, 0,0, pcnt, 0);

    // attention: fused score+softmax, then tanh(P @ V) scattered
    k_score_softmax<<<dim3(16, BT2), 256>>>();
    k_gemm<<<dim3(5, 8, BT2), 256>>>(pG, pkvg + OFF_V, 0, phm,
        Nn, Hh, Nn, Nn, KVG, Hh,
        (long long)Nn*Nn, (long long)Nn*KVG, (long long)Nn*Hh,
        2, 0,1, 0,0, pidx, Nn, pidx, Nn, pcnt, pcnt);

    // GRU: t=0 bias-only; t>=1 gh GEMM compacted to m1 rows (64-tile, more blocks)
    k_gru_combine<<<(Bb*Nn*Hh + 255)/256, 256>>>(0, gbhh);
    for (int t = 1; t < Tt; t++) {
        k_gemm64<<<dim3(13, 64, 1), 256>>>(ph, gWhh, gbhh, pgh,
            Bb*Nn, H3, Hh, Hh, H3, H3, 0,0,0,
            1, 0,0, pidx1t + t*(Bb*Nn), 0, 0,0, pidx1t + t*(Bb*Nn), 0, pc1t + t, 0);
        k_gru_combine<<<(Bb*Nn*Hh + 255)/256, 256>>>(t, gbhh);
    }
    k_outlast1<<<dim3(Bb, 16), 288>>>();
    k_outlast2<<<Bb, 288>>>();

    // join LSTM chain, then dp attention + classifier
    cudaStreamWaitEvent(0, evJ, 0);
    k_dp1<<<dim3(Bb, Ee+1), 256>>>();
    k_dp2<<<Bb, 288>>>();
    k_gemm64<<<dim3(63, 1, 1), 256>>>(po1, Wc, bc, out,
        Bb, OUTo, Hh, Hh, OUTo, OUTo, 0,0,0, 3, 0,0, 0,0, 0,0, 0,0, 0,0);
}

// round 6
// speedup vs baseline: 2.2036x; 1.2142x over previous
#include <cuda_runtime.h>
#include <math.h>

// ---------------- problem constants ----------------
#define Bb   4
#define Tt   6
#define Nn   1024
#define CSc  48
#define GSg  32
#define Hh   270
#define ATa  32
#define DAd  64
#define Ee   32
#define Ll   32
#define EDd  400
#define OUTo 4000
#define BT   (Bb*Tt)        // 24
#define BT2  (Bb*(Tt-1))    // 20
#define H3   (3*Hh)         // 810
#define H4   (4*Hh)         // 1080
#define XCOLS (BT*CSc)      // 1152
#define KVG  1112           // packed cols: k(32) | v(270) | gi(810)
#define OFF_K 0
#define OFF_V 32
#define OFF_GI 302

// ---------------- device scratch ----------------
__device__ float g_X   [Nn*XCOLS];
__device__ float g_S   [Nn*XCOLS];
__device__ float g_co  [BT*Nn*GSg];
__device__ float g_no  [BT*Nn*GSg];
__device__ float g_qin [BT*Nn*GSg];
__device__ float g_q   [BT2*Nn*ATa];
__device__ float g_kvg [BT*Nn*KVG];
__device__ float g_packB[33*KVG];
__device__ float g_G   [BT2*Nn*Nn];
__device__ float g_hm23[BT2*Nn*Hh];
__device__ float g_h   [Bb*Nn*Hh];
__device__ float g_gh  [Bb*Nn*H3];
__device__ signed char g_m1 [BT*Nn];
__device__ signed char g_m23[BT*Nn];
__device__ int   g_idx [BT2*Nn];
__device__ int   g_cnt [BT2];
__device__ int   g_idxU[BT*Nn];
__device__ int   g_cntU[BT];
__device__ int   g_idx1t[Tt*Bb*Nn];
__device__ int   g_c1t [Tt];
__device__ float g_xe  [Bb*Ee*Ll*EDd];
__device__ float g_giL [Bb*Ee*Ll*H4];
__device__ float g_W4  [Hh*H4];          // repacked lstm Whh: [k][j*4+gate]
__device__ float g_stack[Bb*(Ee+1)*Hh];
__device__ float g_wdc [Hh+1];
__device__ float g_vu  [Bb*(Ee+1)];
__device__ float g_o1  [Bb*Hh];
__device__ float g_opart[Bb*16*2*Hh];

__device__ __forceinline__ float sigf(float x){ return 1.f/(1.f+expf(-x)); }

// ---------------- 128x64 tiled SGEMM with gather/scatter ----------------
#define TKk 16
__global__ __launch_bounds__(256) void k_gemm(
    const float* __restrict__ A, const float* __restrict__ B,
    const float* __restrict__ bias, float* __restrict__ C,
    int M, int N, int K,
    int lda, int ldb, int ldc,
    long long sA, long long sB, long long sC,
    int epi, int mapAz, int mapBz,
    const int* __restrict__ gAidx, int gAs,
    const int* __restrict__ gBidx, int gBs,
    const int* __restrict__ sCidx, int sCs,
    const int* __restrict__ cntM, const int* __restrict__ cntK)
{
    int z = blockIdx.z;
    if (cntM) M = cntM[z];
    if (cntK) K = cntK[z];
    int row0 = blockIdx.y * 128;
    if (row0 >= M) return;
    int col0 = blockIdx.x * 64;

    int za = mapAz ? (z + z/(Tt-1) + 1) : z;
    int zb = mapBz ? (z + z/(Tt-1) + 1) : z;
    const float* Ab = A + (long long)za * sA;
    const float* Bbp = B + (long long)zb * sB;
    float* Cb = C + (long long)z * sC;
    const int* gA = gAidx ? gAidx + (long long)z * gAs : (const int*)0;
    const int* gB = gBidx ? gBidx + (long long)z * gBs : (const int*)0;
    const int* sCr = sCidx ? sCidx + (long long)z * sCs : (const int*)0;

    __shared__ __align__(16) float As[2][TKk][132];
    __shared__ __align__(16) float Bs[2][TKk][64];

    int tid = threadIdx.x;
    int ka = tid & 15, ra = tid >> 4;
    int cb = tid & 63, kb = tid >> 6;
    int tx = tid & 15, ty = tid >> 4;

    float acc[8][4] = {};
    int nk = (K + TKk - 1) / TKk;

    {
        #pragma unroll
        for (int i = 0; i < 8; i++) {
            int r = ra + i*16;
            int gr = row0 + r, kk = ka;
            float v = 0.f;
            if (gr < M && kk < K) {
                int ar = gA ? gA[gr] : gr;
                v = Ab[(long long)ar*lda + kk];
            }
            As[0][ka][r] = v;
        }
        #pragma unroll
        for (int i = 0; i < 4; i++) {
            int kk = kb + i*4;
            int c = col0 + cb;
            float v = 0.f;
            if (kk < K && c < N) {
                int br = gB ? gB[kk] : kk;
                v = Bbp[(long long)br*ldb + c];
            }
            Bs[0][kb + i*4][cb] = v;
        }
    }
    __syncthreads();

    for (int kt = 0; kt < nk; kt++) {
        int buf = kt & 1;
        if (kt + 1 < nk) {
            int k0 = (kt + 1) * TKk;
            #pragma unroll
            for (int i = 0; i < 8; i++) {
                int r = ra + i*16;
                int gr = row0 + r, kk = k0 + ka;
                float v = 0.f;
                if (gr < M && kk < K) {
                    int ar = gA ? gA[gr] : gr;
                    v = Ab[(long long)ar*lda + kk];
                }
                As[buf^1][ka][r] = v;
            }
            #pragma unroll
            for (int i = 0; i < 4; i++) {
                int kk = k0 + kb + i*4;
                int c = col0 + cb;
                float v = 0.f;
                if (kk < K && c < N) {
                    int br = gB ? gB[kk] : kk;
                    v = Bbp[(long long)br*ldb + c];
                }
                Bs[buf^1][kb + i*4][cb] = v;
            }
        }
        #pragma unroll
        for (int kk = 0; kk < TKk; kk++) {
            float4 a0 = *(const float4*)&As[buf][kk][ty*8];
            float4 a1 = *(const float4*)&As[buf][kk][ty*8 + 4];
            float4 b0 = *(const float4*)&Bs[buf][kk][tx*4];
            float av[8] = {a0.x,a0.y,a0.z,a0.w,a1.x,a1.y,a1.z,a1.w};
            float bv[4] = {b0.x,b0.y,b0.z,b0.w};
            #pragma unroll
            for (int i = 0; i < 8; i++)
                #pragma unroll
                for (int j = 0; j < 4; j++)
                    acc[i][j] += av[i]*bv[j];
        }
        __syncthreads();
    }

    #pragma unroll
    for (int i = 0; i < 8; i++) {
        int r = row0 + ty*8 + i;
        if (r >= M) continue;
        long long crow = sCr ? (long long)sCr[r]*ldc : (long long)r*ldc;
        #pragma unroll
        for (int j = 0; j < 4; j++) {
            int c = col0 + tx*4 + j;
            if (c >= N) continue;
            float v = acc[i][j];
            if (epi == 1 || epi == 3) v += bias[c];
            if (epi == 2) v = tanhf(v);
            if (epi == 3) v = sigf(v);
            Cb[crow + c] = v;
        }
    }
}

// ---------------- 64x64 tiled SGEMM ----------------
__global__ __launch_bounds__(256) void k_gemm64(
    const float* __restrict__ A, const float* __restrict__ B,
    const float* __restrict__ bias, float* __restrict__ C,
    int M, int N, int K,
    int lda, int ldb, int ldc,
    long long sA, long long sB, long long sC,
    int epi, int mapAz, int mapBz,
    const int* __restrict__ gAidx, int gAs,
    const int* __restrict__ gBidx, int gBs,
    const int* __restrict__ sCidx, int sCs,
    const int* __restrict__ cntM, const int* __restrict__ cntK)
{
    int z = blockIdx.z;
    if (cntM) M = cntM[z];
    if (cntK) K = cntK[z];
    int row0 = blockIdx.y * 64;
    if (row0 >= M) return;
    int col0 = blockIdx.x * 64;

    int za = mapAz ? (z + z/(Tt-1) + 1) : z;
    int zb = mapBz ? (z + z/(Tt-1) + 1) : z;
    const float* Ab = A + (long long)za * sA;
    const float* Bbp = B + (long long)zb * sB;
    float* Cb = C + (long long)z * sC;
    const int* gA = gAidx ? gAidx + (long long)z * gAs : (const int*)0;
    const int* gB = gBidx ? gBidx + (long long)z * gBs : (const int*)0;
    const int* sCr = sCidx ? sCidx + (long long)z * sCs : (const int*)0;

    __shared__ __align__(16) float As[2][TKk][68];
    __shared__ __align__(16) float Bs[2][TKk][64];

    int tid = threadIdx.x;
    int ka = tid & 15, ra = tid >> 4;
    int cb = tid & 63, kb = tid >> 6;
    int tx = tid & 15, ty = tid >> 4;

    float acc[4][4] = {};
    int nk = (K + TKk - 1) / TKk;

    {
        #pragma unroll
        for (int i = 0; i < 4; i++) {
            int r = ra + i*16;
            int gr = row0 + r, kk = ka;
            float v = 0.f;
            if (gr < M && kk < K) {
                int ar = gA ? gA[gr] : gr;
                v = Ab[(long long)ar*lda + kk];
            }
            As[0][ka][r] = v;
        }
        #pragma unroll
        for (int i = 0; i < 4; i++) {
            int kk = kb + i*4;
            int c = col0 + cb;
            float v = 0.f;
            if (kk < K && c < N) {
                int br = gB ? gB[kk] : kk;
                v = Bbp[(long long)br*ldb + c];
            }
            Bs[0][kb + i*4][cb] = v;
        }
    }
    __syncthreads();

    for (int kt = 0; kt < nk; kt++) {
        int buf = kt & 1;
        if (kt + 1 < nk) {
            int k0 = (kt + 1) * TKk;
            #pragma unroll
            for (int i = 0; i < 4; i++) {
                int r = ra + i*16;
                int gr = row0 + r, kk = k0 + ka;
                float v = 0.f;
                if (gr < M && kk < K) {
                    int ar = gA ? gA[gr] : gr;
                    v = Ab[(long long)ar*lda + kk];
                }
                As[buf^1][ka][r] = v;
            }
            #pragma unroll
            for (int i = 0; i < 4; i++) {
                int kk = k0 + kb + i*4;
                int c = col0 + cb;
                float v = 0.f;
                if (kk < K && c < N) {
                    int br = gB ? gB[kk] : kk;
                    v = Bbp[(long long)br*ldb + c];
                }
                Bs[buf^1][kb + i*4][cb] = v;
            }
        }
        #pragma unroll
        for (int kk = 0; kk < TKk; kk++) {
            float4 a0 = *(const float4*)&As[buf][kk][ty*4];
            float4 b0 = *(const float4*)&Bs[buf][kk][tx*4];
            float av[4] = {a0.x,a0.y,a0.z,a0.w};
            float bv[4] = {b0.x,b0.y,b0.z,b0.w};
            #pragma unroll
            for (int i = 0; i < 4; i++)
                #pragma unroll
                for (int j = 0; j < 4; j++)
                    acc[i][j] += av[i]*bv[j];
        }
        __syncthreads();
    }

    #pragma unroll
    for (int i = 0; i < 4; i++) {
        int r = row0 + ty*4 + i;
        if (r >= M) continue;
        long long crow = sCr ? (long long)sCr[r]*ldc : (long long)r*ldc;
        #pragma unroll
        for (int j = 0; j < 4; j++) {
            int c = col0 + tx*4 + j;
            if (c >= N) continue;
            float v = acc[i][j];
            if (epi == 1 || epi == 3) v += bias[c];
            if (epi == 2) v = tanhf(v);
            if (epi == 3) v = sigf(v);
            Cb[crow + c] = v;
        }
    }
}

// ---------------- input build ----------------
__global__ void k_build_X(const int* __restrict__ code_x, const int* __restrict__ neigh,
                          const float* __restrict__ c_emb, const float* __restrict__ n_emb)
{
    int idx = blockIdx.x * blockDim.x + threadIdx.x;
    if (idx >= Nn * XCOLS) return;
    int n  = idx / XCOLS;
    int r  = idx % XCOLS;
    int bt = r / CSc;
    int c  = r % CSc;
    float cx = (float)code_x[bt*Nn + n];
    float nx = (float)neigh [bt*Nn + n];
    g_X[idx] = cx * c_emb[n*CSc + c] + nx * n_emb[n*CSc + c];
}

__global__ __launch_bounds__(288) void k_spmm(const float* __restrict__ adj)
{
    int m = blockIdx.x;
    int tid = threadIdx.x;
    __shared__ float arow[Nn];
    for (int i = tid; i < Nn; i += 288) arow[i] = adj[(long long)m*Nn + i];
    __syncthreads();
    float acc0 = 0.f, acc1 = 0.f, acc2 = 0.f, acc3 = 0.f;
    for (int n = 0; n < Nn; n++) {
        float a = arow[n];
        if (a != 0.f) {
            const float* xr = g_X + (long long)n * XCOLS;
            acc0 += a * xr[tid];
            acc1 += a * xr[tid + 288];
            acc2 += a * xr[tid + 576];
            acc3 += a * xr[tid + 864];
        }
    }
    float* sr = g_S + (long long)m * XCOLS;
    sr[tid] = acc0; sr[tid+288] = acc1; sr[tid+576] = acc2; sr[tid+864] = acc3;
}

__global__ void k_masks(const int* __restrict__ divided)
{
    int i = blockIdx.x * blockDim.x + threadIdx.x;
    if (i >= BT*Nn) return;
    g_m1 [i] = (divided[3*i]     > 0) ? 1 : 0;
    g_m23[i] = (divided[3*i + 1] > 0 || divided[3*i + 2] > 0) ? 1 : 0;
}

__global__ __launch_bounds__(1024) void k_compact()
{
    int z = blockIdx.x;
    int b = z / (Tt-1), t = 1 + z % (Tt-1);
    int bt = b*Tt + t;
    int n = threadIdx.x;
    __shared__ int warpCnt[32];
    int m = g_m23[bt*Nn + n];
    unsigned bal = __ballot_sync(0xffffffffu, m != 0);
    int lane = n & 31, w = n >> 5;
    int pre = __popc(bal & ((1u << lane) - 1u));
    if (lane == 0) warpCnt[w] = __popc(bal);
    __syncthreads();
    if (w == 0) {
        int v = warpCnt[lane];
        #pragma unroll
        for (int o = 1; o < 32; o <<= 1) {
            int u = __shfl_up_sync(0xffffffffu, v, o);
            if (lane >= o) v += u;
        }
        warpCnt[lane] = v;
    }
    __syncthreads();
    int base = (w == 0) ? 0 : warpCnt[w - 1];
    if (m) g_idx[z*Nn + base + pre] = n;
    if (n == 1023) g_cnt[z] = warpCnt[31];
}

__global__ __launch_bounds__(1024) void k_compactU()
{
    int bt = blockIdx.x;
    int n = threadIdx.x;
    __shared__ int warpCnt[32];
    int m = (g_m1[bt*Nn + n] | g_m23[bt*Nn + n]);
    unsigned bal = __ballot_sync(0xffffffffu, m != 0);
    int lane = n & 31, w = n >> 5;
    int pre = __popc(bal & ((1u << lane) - 1u));
    if (lane == 0) warpCnt[w] = __popc(bal);
    __syncthreads();
    if (w == 0) {
        int v = warpCnt[lane];
        #pragma unroll
        for (int o = 1; o < 32; o <<= 1) {
            int u = __shfl_up_sync(0xffffffffu, v, o);
            if (lane >= o) v += u;
        }
        warpCnt[lane] = v;
    }
    __syncthreads();
    int base = (w == 0) ? 0 : warpCnt[w - 1];
    if (m) g_idxU[bt*Nn + base + pre] = n;
    if (n == 1023) g_cntU[bt] = warpCnt[31];
}

__global__ __launch_bounds__(1024) void k_compact1t()
{
    int t = blockIdx.x;
    int n = threadIdx.x;
    int lane = n & 31, w = n >> 5;
    __shared__ int warpCnt[32];
    __shared__ int baseAcc;
    if (n == 0) baseAcc = 0;
    __syncthreads();
    for (int b = 0; b < Bb; b++) {
        int bt = b*Tt + t;
        int m = g_m1[bt*Nn + n];
        unsigned bal = __ballot_sync(0xffffffffu, m != 0);
        int pre = __popc(bal & ((1u << lane) - 1u));
        if (lane == 0) warpCnt[w] = __popc(bal);
        __syncthreads();
        if (w == 0) {
            int v = warpCnt[lane];
            #pragma unroll
            for (int o = 1; o < 32; o <<= 1) {
                int u = __shfl_up_sync(0xffffffffu, v, o);
                if (lane >= o) v += u;
            }
            warpCnt[lane] = v;
        }
        __syncthreads();
        int base = baseAcc + ((w == 0) ? 0 : warpCnt[w - 1]);
        if (m) g_idx1t[t*(Bb*Nn) + base + pre] = b*Nn + n;
        __syncthreads();
        if (n == 0) baseAcc += warpCnt[31];
        __syncthreads();
    }
    if (n == 0) g_c1t[t] = baseAcc;
}

__global__ void k_co_no(const int* __restrict__ code_x, const int* __restrict__ neigh,
                        const float* __restrict__ c_emb, const float* __restrict__ n_emb,
                        const float* __restrict__ Wg, const float* __restrict__ bg)
{
    int bt = blockIdx.x;
    int n  = blockIdx.y * 8 + threadIdx.y;
    int g  = threadIdx.x;
    __shared__ float Wgs[CSc][GSg];
    int tid = threadIdx.y * 32 + threadIdx.x;
    for (int i = tid; i < CSc*GSg; i += 256) Wgs[i / GSg][i % GSg] = Wg[i];
    __syncthreads();
    const float* Srow = g_S + (long long)n * XCOLS + bt * CSc;
    float a1 = 0.f, a2 = 0.f;
    #pragma unroll
    for (int c = 0; c < CSc; c++) {
        float s = Srow[c];
        float w = Wgs[c][g];
        a1 += (c_emb[n*CSc + c] + s) * w;
        a2 += (n_emb[n*CSc + c] + s) * w;
    }
    float cx = (float)code_x[bt*Nn + n];
    float nx = (float)neigh [bt*Nn + n];
    float co = cx * a1 + bg[g];
    float no = nx * a2 + bg[g];
    co = (co >= 0.f) ? co : 0.01f * co;
    no = (no >= 0.f) ? no : 0.01f * no;
    long long o = ((long long)bt*Nn + n) * GSg + g;
    g_co[o] = co;
    g_no[o] = no;
}

__global__ void k_qin(const int* __restrict__ divided, const float* __restrict__ u_emb)
{
    int idx = blockIdx.x * blockDim.x + threadIdx.x;
    if (idx >= BT*Nn*GSg) return;
    int g  = idx % GSg;
    int bn = idx / GSg;
    int n  = bn % Nn;
    int bt = bn / Nn;
    int t  = bt % Tt;
    float v;
    if (divided[bn*3 + 2] > 0)       v = u_emb[n*GSg + g];
    else if (t > 0)                  v = g_no[((long long)(bt-1)*Nn + n)*GSg + g];
    else                             v = 0.f;
    g_qin[idx] = v;
}

__global__ void k_packB(const float* __restrict__ Wk, const float* __restrict__ bk,
                        const float* __restrict__ Wv, const float* __restrict__ bv,
                        const float* __restrict__ Wih, const float* __restrict__ bih)
{
    int idx = blockIdx.x * blockDim.x + threadIdx.x;
    if (idx >= 33*KVG) return;
    int r = idx / KVG, c = idx % KVG;
    float v;
    if (r < 32) {
        if (c < OFF_V)       v = Wk [r*ATa + c];
        else if (c < OFF_GI) v = Wv [r*Hh  + (c - OFF_V)];
        else                 v = Wih[r*H3  + (c - OFF_GI)];
    } else {
        if (c < OFF_V)       v = bk [c];
        else if (c < OFF_GI) v = bv [c - OFF_V];
        else                 v = bih[c - OFF_GI];
    }
    g_packB[idx] = v;
}

// repack lstm Whh to [k][j*4+gate]
__global__ void k_packWhh(const float* __restrict__ Whh)
{
    int idx = blockIdx.x * blockDim.x + threadIdx.x;
    if (idx >= Hh*H4) return;
    int g = idx & 3;
    int rem = idx >> 2;
    int j = rem % Hh;
    int k2 = rem / Hh;
    g_W4[idx] = Whh[k2*H4 + g*Hh + j];
}

// ---------------- fused compacted score + softmax ----------------
__global__ __launch_bounds__(256) void k_score_softmax()
{
    int z = blockIdx.y;
    int cq = g_cnt[z];
    int qr0 = blockIdx.x * 64;
    if (qr0 >= cq) return;
    int b = z / (Tt-1), t = 1 + z % (Tt-1), bt = b*Tt + t;
    const int* idx = g_idx + z*Nn;
    const float* qp = g_q + (long long)z*Nn*ATa;
    const float* kb = g_kvg + (long long)bt*Nn*KVG;
    float* G = g_G + (long long)z * Nn * Nn;

    __shared__ float qs[64][33];
    __shared__ float ks[64][33];
    __shared__ float pmax[16][64];
    __shared__ float rowmax[64];

    int tid = threadIdx.x;
    int tx = tid & 15, ty = tid >> 4;

    for (int i = tid; i < 64*32; i += 256) {
        int r = i >> 5, a = i & 31;
        int gq = qr0 + r;
        qs[r][a] = (gq < cq) ? qp[(long long)gq*ATa + a] : 0.f;
    }

    float tmax[4] = {-1e30f, -1e30f, -1e30f, -1e30f};
    const float scale = 0.17677669529663687f;

    for (int j0 = 0; j0 < cq; j0 += 64) {
        __syncthreads();
        for (int i = tid; i < 64*32; i += 256) {
            int r = i >> 5, a = i & 31;
            int gk = j0 + r;
            ks[r][a] = (gk < cq) ? kb[(long long)idx[gk]*KVG + a] : 0.f;
        }
        __syncthreads();
        float acc[4][4] = {};
        #pragma unroll
        for (int a = 0; a < 32; a++) {
            float av[4], bv[4];
            #pragma unroll
            for (int i = 0; i < 4; i++) av[i] = qs[ty*4+i][a];
            #pragma unroll
            for (int j = 0; j < 4; j++) bv[j] = ks[tx*4+j][a];
            #pragma unroll
            for (int i = 0; i < 4; i++)
                #pragma unroll
                for (int j = 0; j < 4; j++) acc[i][j] += av[i]*bv[j];
        }
        #pragma unroll
        for (int i = 0; i < 4; i++) {
            int gr = qr0 + ty*4 + i;
            if (gr >= cq) continue;
            #pragma unroll
            for (int j = 0; j < 4; j++) {
                int gc = j0 + tx*4 + j;
                if (gc >= cq) continue;
                float v = acc[i][j] * scale;
                G[(long long)gr*Nn + gc] = v;
                tmax[i] = fmaxf(tmax[i], v);
            }
        }
    }
    #pragma unroll
    for (int i = 0; i < 4; i++) pmax[tx][ty*4 + i] = tmax[i];
    __syncthreads();
    if (tid < 64) {
        float m = -1e30f;
        #pragma unroll
        for (int x = 0; x < 16; x++) m = fmaxf(m, pmax[x][tid]);
        rowmax[tid] = m;
    }
    __syncthreads();

    int row = tid >> 2, l4 = tid & 3;
    int gr = qr0 + row;
    float s = 0.f;
    if (gr < cq) {
        float m = rowmax[row];
        for (int c = l4; c < cq; c += 4) {
            float e = expf(G[(long long)gr*Nn + c] - m);
            G[(long long)gr*Nn + c] = e;
            s += e;
        }
    }
    s += __shfl_xor_sync(0xffffffffu, s, 1);
    s += __shfl_xor_sync(0xffffffffu, s, 2);
    if (gr < cq) {
        float inv = 1.f / s;
        for (int c = l4; c < cq; c += 4)
            G[(long long)gr*Nn + c] *= inv;
    }
}

// ---------------- GRU combine ----------------
__global__ void k_gru_combine(int t, const float* __restrict__ gbhh)
{
    int idx = blockIdx.x * blockDim.x + threadIdx.x;
    if (idx >= Bb*Nn*Hh) return;
    int j  = idx % Hh;
    int bn = idx / Hh;
    int n  = bn % Nn;
    int b  = bn / Nn;
    int bt = b*Tt + t;
    int mi = bt*Nn + n;
    float hv = 0.f;
    if (t > 0 && g_m23[mi]) {
        hv = g_hm23[((long long)(b*(Tt-1) + (t-1))*Nn + n) * Hh + j];
    } else if (g_m1[mi]) {
        const float* gir = g_kvg + ((long long)bt*Nn + n)*KVG + OFF_GI;
        float g0, g1, g2;
        if (t == 0) { g0 = gbhh[j]; g1 = gbhh[Hh + j]; g2 = gbhh[2*Hh + j]; }
        else {
            const float* ghr = g_gh + (long long)bn * H3;
            g0 = ghr[j]; g1 = ghr[Hh + j]; g2 = ghr[2*Hh + j];
        }
        float r  = sigf(gir[j]        + g0);
        float zz = sigf(gir[Hh + j]   + g1);
        float nn = tanhf(gir[2*Hh + j] + r * g2);
        float hp = (t == 0) ? 0.f : g_h[idx];
        hv = (1.f - zz) * nn + zz * hp;
    }
    g_h[idx] = hv;
}

// parallel outlast
__global__ __launch_bounds__(288) void k_outlast1()
{
    int b = blockIdx.x, p = blockIdx.y, j = threadIdx.x;
    if (j >= Hh) return;
    float mx1 = -1e38f, mx23 = -1e38f;
    int mbase = (b*Tt + (Tt-1)) * Nn;
    int n0 = p * 64;
    for (int n = n0; n < n0 + 64; n++) {
        float hv = g_h[((long long)b*Nn + n)*Hh + j];
        if (g_m1 [mbase + n]) mx1  = fmaxf(mx1,  hv);
        if (g_m23[mbase + n]) mx23 = fmaxf(mx23, hv);
    }
    g_opart[((b*16 + p)*2    )*Hh + j] = mx1;
    g_opart[((b*16 + p)*2 + 1)*Hh + j] = mx23;
}

__global__ __launch_bounds__(288) void k_outlast2()
{
    int b = blockIdx.x, j = threadIdx.x;
    if (j >= Hh) return;
    float mx1 = -1e38f, mx23 = -1e38f;
    #pragma unroll
    for (int p = 0; p < 16; p++) {
        mx1  = fmaxf(mx1,  g_opart[((b*16 + p)*2    )*Hh + j]);
        mx23 = fmaxf(mx23, g_opart[((b*16 + p)*2 + 1)*Hh + j]);
    }
    float o = 0.f;
    if (mx1  > -1e37f) o += mx1;
    if (mx23 > -1e37f) o += mx23;
    g_stack[(long long)b*(Ee+1)*Hh + j] = o;
}

// ---------------- event LSTM ----------------
__global__ void k_evgather(const int* __restrict__ events, const float* __restrict__ Eemb)
{
    int idx = blockIdx.x * blockDim.x + threadIdx.x;
    if (idx >= Bb*Ee*Ll*EDd) return;
    int d   = idx % EDd;
    int rem = idx / EDd;
    int l   = rem % Ll;
    int be  = rem / Ll;
    int b   = be / Ee, e = be % Ee;
    int ev  = events[((b*Tt + (Tt-1))*Ee + e)*Ll + l];
    g_xe[idx] = Eemb[(long long)ev*EDd + d];
}

// column-parallel persistent LSTM: 2 rows per block, 64 blocks, 544 threads.
// Threads 0..539 each compute TWO gate columns (tid, tid+540) for both rows,
// streaming W4 ([k][j*4+g]) coalesced from L2. Epilogue: thread (er,ej) keeps
// cs register-resident (er = tid/270, ej = tid%270).
__global__ __launch_bounds__(544) void k_lstm3()
{
    __shared__ __align__(8)  float2 h2[Hh];       // h of 2 rows, per k
    __shared__ __align__(16) float a_sh[2][H4];   // gate pre-activations
    int tid = threadIdx.x;
    int row0 = blockIdx.x * 2;

    int er = tid / Hh;            // epilogue row (valid if tid < 540)
    int ej = tid - er * Hh;
    float cs = 0.f;

    if (tid < Hh) h2[tid] = make_float2(0.f, 0.f);
    __syncthreads();

    for (int l = 0; l < Ll; l++) {
        if (tid < 2*Hh) {
            const float* W0 = g_W4 + tid;
            const float* W1 = g_W4 + tid + 2*Hh;
            float a00 = 0.f, a01 = 0.f, a10 = 0.f, a11 = 0.f;
            #pragma unroll 5
            for (int k2 = 0; k2 < Hh; k2++) {
                float2 h = h2[k2];
                float w0 = __ldg(&W0[k2*H4]);
                float w1 = __ldg(&W1[k2*H4]);
                a00 += h.x * w0; a01 += h.y * w0;
                a10 += h.x * w1; a11 += h.y * w1;
            }
            a_sh[0][tid]        = a00;
            a_sh[1][tid]        = a01;
            a_sh[0][tid + 2*Hh] = a10;
            a_sh[1][tid + 2*Hh] = a11;
        }
        __syncthreads();
        float hn = 0.f;
        if (tid < 2*Hh) {
            float4 ga = *(const float4*)&a_sh[er][ej*4];
            const float* gl = g_giL + ((long long)(row0 + er)*Ll + l) * H4;
            float gi_ = ga.x + gl[ej];
            float gf  = ga.y + gl[Hh   + ej];
            float gg  = ga.z + gl[2*Hh + ej];
            float go  = ga.w + gl[3*Hh + ej];
            cs = sigf(gf)*cs + sigf(gi_)*tanhf(gg);
            hn = sigf(go)*tanhf(cs);
        }
        __syncthreads();
        if (tid < 2*Hh) {
            float* hp = (float*)&h2[ej];
            hp[er] = hn;
        }
        __syncthreads();
    }

    if (tid < 2*Hh) {
        int be = row0 + er;
        int b = be / Ee, e = be % Ee;
        float* hp = (float*)&h2[ej];
        g_stack[((long long)b*(Ee+1) + 1 + e)*Hh + ej] = hp[er];
    }
}

// ---------------- final dp attention + head ----------------
__global__ void k_wdctx(const float* __restrict__ Wd, const float* __restrict__ bd,
                        const float* __restrict__ ctx)
{
    int j = threadIdx.x;
    if (j < Hh) {
        float s = 0.f;
        for (int d = 0; d < DAd; d++) s += Wd[j*DAd + d] * ctx[d];
        g_wdc[j] = s;
    } else if (j == Hh) {
        float s = 0.f;
        for (int d = 0; d < DAd; d++) s += bd[d] * ctx[d];
        g_wdc[Hh] = s;
    }
}

__global__ void k_dp1()
{
    int b = blockIdx.x, s = blockIdx.y;
    const float* x = g_stack + ((long long)b*(Ee+1) + s) * Hh;
    __shared__ float red[256];
    int tid = threadIdx.x;
    float acc = 0.f;
    for (int h = tid; h < Hh; h += 256) acc += x[h] * g_wdc[h];
    red[tid] = acc; __syncthreads();
    for (int st = 128; st > 0; st >>= 1) { if (tid < st) red[tid] += red[tid + st]; __syncthreads(); }
    if (tid == 0) g_vu[b*(Ee+1) + s] = red[0] + g_wdc[Hh];
}

__global__ void k_dp2()
{
    int b = blockIdx.x, j = threadIdx.x;
    __shared__ float sm[Ee+1];
    if (j == 0) {
        float mx = -1e38f;
        for (int s = 0; s < Ee+1; s++) mx = fmaxf(mx, g_vu[b*(Ee+1) + s]);
        float sum = 0.f;
        for (int s = 0; s < Ee+1; s++) { float e = expf(g_vu[b*(Ee+1) + s] - mx); sm[s] = e; sum += e; }
        float inv = 1.f / sum;
        for (int s = 0; s < Ee+1; s++) sm[s] *= inv;
    }
    __syncthreads();
    if (j < Hh) {
        float acc = 0.f;
        for (int s = 0; s < Ee+1; s++) acc += sm[s] * g_stack[((long long)b*(Ee+1) + s)*Hh + j];
        g_o1[b*Hh + j] = acc;
    }
}

// ---------------- host driver ----------------
extern "C" void kernel_launch(void* const* d_in, const int* in_sizes, int n_in,
                              void* d_out, int out_size)
{
    const int*   code_x = (const int*)  d_in[0];
    const int*   divided= (const int*)  d_in[1];
    const int*   neigh  = (const int*)  d_in[2];
    const int*   events = (const int*)  d_in[4];
    const float* c_emb  = (const float*)d_in[5];
    const float* n_emb  = (const float*)d_in[6];
    const float* u_emb  = (const float*)d_in[7];
    const float* adj    = (const float*)d_in[8];
    const float* Wg     = (const float*)d_in[9];
    const float* bg     = (const float*)d_in[10];
    const float* gWih   = (const float*)d_in[11];
    const float* gWhh   = (const float*)d_in[12];
    const float* gbih   = (const float*)d_in[13];
    const float* gbhh   = (const float*)d_in[14];
    const float* Wq     = (const float*)d_in[15];
    const float* bq     = (const float*)d_in[16];
    const float* Wk     = (const float*)d_in[17];
    const float* bk     = (const float*)d_in[18];
    const float* Wv     = (const float*)d_in[19];
    const float* bv     = (const float*)d_in[20];
    const float* Wd     = (const float*)d_in[21];
    const float* bd     = (const float*)d_in[22];
    const float* ctx    = (const float*)d_in[23];
    const float* Eemb   = (const float*)d_in[24];
    const float* lWih   = (const float*)d_in[25];
    const float* lWhh   = (const float*)d_in[26];
    const float* lb     = (const float*)d_in[27];
    const float* Wc     = (const float*)d_in[28];
    const float* bc     = (const float*)d_in[29];
    float* out = (float*)d_out;

    float *pco, *pqin, *pq, *pkvg, *ppB, *pG, *phm, *ph, *pgh, *pxe, *pgiL, *po1;
    int *pidx, *pcnt, *pidxU, *pcntU, *pidx1t, *pc1t;
    cudaGetSymbolAddress((void**)&pco,   g_co);
    cudaGetSymbolAddress((void**)&pqin,  g_qin);
    cudaGetSymbolAddress((void**)&pq,    g_q);
    cudaGetSymbolAddress((void**)&pkvg,  g_kvg);
    cudaGetSymbolAddress((void**)&ppB,   g_packB);
    cudaGetSymbolAddress((void**)&pG,    g_G);
    cudaGetSymbolAddress((void**)&phm,   g_hm23);
    cudaGetSymbolAddress((void**)&ph,    g_h);
    cudaGetSymbolAddress((void**)&pgh,   g_gh);
    cudaGetSymbolAddress((void**)&pxe,   g_xe);
    cudaGetSymbolAddress((void**)&pgiL,  g_giL);
    cudaGetSymbolAddress((void**)&po1,   g_o1);
    cudaGetSymbolAddress((void**)&pidx,  g_idx);
    cudaGetSymbolAddress((void**)&pcnt,  g_cnt);
    cudaGetSymbolAddress((void**)&pidxU, g_idxU);
    cudaGetSymbolAddress((void**)&pcntU, g_cntU);
    cudaGetSymbolAddress((void**)&pidx1t,g_idx1t);
    cudaGetSymbolAddress((void**)&pc1t,  g_c1t);

    static cudaStream_t s2 = 0;
    static cudaEvent_t evF = 0, evJ = 0;
    if (!s2) {
        cudaStreamCreateWithFlags(&s2, cudaStreamNonBlocking);
        cudaEventCreateWithFlags(&evF, cudaEventDisableTiming);
        cudaEventCreateWithFlags(&evJ, cudaEventDisableTiming);
    }

    // fork: event-LSTM chain on s2 (independent until dp1)
    cudaEventRecord(evF, 0);
    cudaStreamWaitEvent(s2, evF, 0);
    k_packWhh<<<(Hh*H4 + 255)/256, 256, 0, s2>>>(lWhh);
    k_evgather<<<(Bb*Ee*Ll*EDd + 255)/256, 256, 0, s2>>>(events, Eemb);
    k_gemm<<<dim3(17, 32, 1), 256, 0, s2>>>(pxe, lWih, lb, pgiL,
        Bb*Ee*Ll, H4, EDd, EDd, H4, H4, 0,0,0, 1, 0,0, 0,0, 0,0, 0,0, 0,0);
    k_lstm3<<<(Bb*Ee)/2, 544, 0, s2>>>();
    cudaEventRecord(evJ, s2);

    // main stream
    k_build_X<<<(Nn*XCOLS + 255)/256, 256>>>(code_x, neigh, c_emb, n_emb);
    k_masks  <<<(BT*Nn + 255)/256, 256>>>(divided);
    k_wdctx  <<<1, 288>>>(Wd, bd, ctx);
    k_compact  <<<BT2, 1024>>>();
    k_compactU <<<BT,  1024>>>();
    k_compact1t<<<Tt,  1024>>>();
    k_packB<<<(33*KVG + 255)/256, 256>>>(Wk, bk, Wv, bv, gWih, gbih);

    k_spmm<<<Nn, 288>>>(adj);
    k_co_no<<<dim3(BT, Nn/8), dim3(32,8)>>>(code_x, neigh, c_emb, n_emb, Wg, bg);
    k_qin  <<<(BT*Nn*GSg + 255)/256, 256>>>(divided, u_emb);

    // packed k|v|gi projection, only m1|m23 rows
    k_gemm<<<dim3(18, 8, BT), 256>>>(pco, ppB, ppB + 32*KVG, pkvg,
        Nn, KVG, GSg, GSg, KVG, KVG,
        (long long)Nn*GSg, 0, (long long)Nn*KVG,
        1, 0,0, pidxU, Nn, 0,0, pidxU, Nn, pcntU, 0);

    // q projection, compact m23 rows, t>=1 batches
    k_gemm64<<<dim3(1, 16, BT2), 256>>>(pqin, Wq, bq, pq,
        Nn, ATa, GSg, GSg, ATa, ATa,
        (long long)Nn*GSg, 0, (long long)Nn*ATa,
        1, 1,0, pidx, Nn, 0,0, 0,0, pcnt, 0);

    // attention: fused score+softmax, then tanh(P @ V) scattered
    k_score_softmax<<<dim3(16, BT2), 256>>>();
    k_gemm<<<dim3(5, 8, BT2), 256>>>(pG, pkvg + OFF_V, 0, phm,
        Nn, Hh, Nn, Nn, KVG, Hh,
        (long long)Nn*Nn, (long long)Nn*KVG, (long long)Nn*Hh,
        2, 0,1, 0,0, pidx, Nn, pidx, Nn, pcnt, pcnt);

    // GRU: t=0 bias-only; t>=1 gh GEMM compacted to m1 rows
    k_gru_combine<<<(Bb*Nn*Hh + 255)/256, 256>>>(0, gbhh);
    for (int t = 1; t < Tt; t++) {
        k_gemm64<<<dim3(13, 64, 1), 256>>>(ph, gWhh, gbhh, pgh,
            Bb*Nn, H3, Hh, Hh, H3, H3, 0,0,0,
            1, 0,0, pidx1t + t*(Bb*Nn), 0, 0,0, pidx1t + t*(Bb*Nn), 0, pc1t + t, 0);
        k_gru_combine<<<(Bb*Nn*Hh + 255)/256, 256>>>(t, gbhh);
    }
    k_outlast1<<<dim3(Bb, 16), 288>>>();
    k_outlast2<<<Bb, 288>>>();

    // join LSTM chain, then dp attention + classifier
    cudaStreamWaitEvent(0, evJ, 0);
    k_dp1<<<dim3(Bb, Ee+1), 256>>>();
    k_dp2<<<Bb, 288>>>();
    k_gemm64<<<dim3(63, 1, 1), 256>>>(po1, Wc, bc, out,
        Bb, OUTo, Hh, Hh, OUTo, OUTo, 0,0,0, 3, 0,0, 0,0, 0,0, 0,0, 0,0);
}

// round 7
// speedup vs baseline: 2.5010x; 1.1349x over previous
#include <cuda_runtime.h>
#include <math.h>

// ---------------- problem constants ----------------
#define Bb   4
#define Tt   6
#define Nn   1024
#define CSc  48
#define GSg  32
#define Hh   270
#define ATa  32
#define DAd  64
#define Ee   32
#define Ll   32
#define EDd  400
#define OUTo 4000
#define BT   (Bb*Tt)        // 24
#define BT2  (Bb*(Tt-1))    // 20
#define H3   (3*Hh)         // 810
#define H4   (4*Hh)         // 1080
#define XCOLS (BT*CSc)      // 1152
#define KVG  1112           // packed cols: k(32) | v(270) | gi(810)
#define OFF_K 0
#define OFF_V 32
#define OFF_GI 302

// ---------------- device scratch ----------------
__device__ float g_X   [Nn*XCOLS];
__device__ float g_S   [Nn*XCOLS];
__device__ float g_co  [BT*Nn*GSg];
__device__ float g_no  [BT*Nn*GSg];
__device__ float g_qin [BT*Nn*GSg];
__device__ float g_q   [BT2*Nn*ATa];
__device__ float g_kvg [BT*Nn*KVG];
__device__ float g_packB[33*KVG];
__device__ float g_G   [BT2*Nn*Nn];
__device__ float g_hm23[BT2*Nn*Hh];
__device__ float g_h   [Bb*Nn*Hh];
__device__ float g_gh  [Bb*Nn*H3];
__device__ signed char g_m1 [BT*Nn];
__device__ signed char g_m23[BT*Nn];
__device__ int   g_idx [BT2*Nn];
__device__ int   g_cnt [BT2];
__device__ int   g_idxU[BT*Nn];
__device__ int   g_cntU[BT];
__device__ int   g_idx1t[Tt*Bb*Nn];
__device__ int   g_c1t [Tt];
__device__ float g_xe  [Bb*Ee*Ll*EDd];
__device__ float g_giL [Bb*Ee*Ll*H4];
__device__ float g_W4  [Hh*H4];          // repacked lstm Whh: [k][j*4+gate]
__device__ float g_stack[Bb*(Ee+1)*Hh];
__device__ float g_wdc [Hh+1];
__device__ float g_vu  [Bb*(Ee+1)];
__device__ float g_o1  [Bb*Hh];
__device__ float g_opart[Bb*16*2*Hh];

__device__ __forceinline__ float sigf(float x){ return 1.f/(1.f+expf(-x)); }

// ---------------- 128x64 tiled SGEMM with gather/scatter ----------------
#define TKk 16
__global__ __launch_bounds__(256) void k_gemm(
    const float* __restrict__ A, const float* __restrict__ B,
    const float* __restrict__ bias, float* __restrict__ C,
    int M, int N, int K,
    int lda, int ldb, int ldc,
    long long sA, long long sB, long long sC,
    int epi, int mapAz, int mapBz,
    const int* __restrict__ gAidx, int gAs,
    const int* __restrict__ gBidx, int gBs,
    const int* __restrict__ sCidx, int sCs,
    const int* __restrict__ cntM, const int* __restrict__ cntK)
{
    int z = blockIdx.z;
    if (cntM) M = cntM[z];
    if (cntK) K = cntK[z];
    int row0 = blockIdx.y * 128;
    if (row0 >= M) return;
    int col0 = blockIdx.x * 64;

    int za = mapAz ? (z + z/(Tt-1) + 1) : z;
    int zb = mapBz ? (z + z/(Tt-1) + 1) : z;
    const float* Ab = A + (long long)za * sA;
    const float* Bbp = B + (long long)zb * sB;
    float* Cb = C + (long long)z * sC;
    const int* gA = gAidx ? gAidx + (long long)z * gAs : (const int*)0;
    const int* gB = gBidx ? gBidx + (long long)z * gBs : (const int*)0;
    const int* sCr = sCidx ? sCidx + (long long)z * sCs : (const int*)0;

    __shared__ __align__(16) float As[2][TKk][132];
    __shared__ __align__(16) float Bs[2][TKk][64];

    int tid = threadIdx.x;
    int ka = tid & 15, ra = tid >> 4;
    int cb = tid & 63, kb = tid >> 6;
    int tx = tid & 15, ty = tid >> 4;

    float acc[8][4] = {};
    int nk = (K + TKk - 1) / TKk;

    {
        #pragma unroll
        for (int i = 0; i < 8; i++) {
            int r = ra + i*16;
            int gr = row0 + r, kk = ka;
            float v = 0.f;
            if (gr < M && kk < K) {
                int ar = gA ? gA[gr] : gr;
                v = Ab[(long long)ar*lda + kk];
            }
            As[0][ka][r] = v;
        }
        #pragma unroll
        for (int i = 0; i < 4; i++) {
            int kk = kb + i*4;
            int c = col0 + cb;
            float v = 0.f;
            if (kk < K && c < N) {
                int br = gB ? gB[kk] : kk;
                v = Bbp[(long long)br*ldb + c];
            }
            Bs[0][kb + i*4][cb] = v;
        }
    }
    __syncthreads();

    for (int kt = 0; kt < nk; kt++) {
        int buf = kt & 1;
        if (kt + 1 < nk) {
            int k0 = (kt + 1) * TKk;
            #pragma unroll
            for (int i = 0; i < 8; i++) {
                int r = ra + i*16;
                int gr = row0 + r, kk = k0 + ka;
                float v = 0.f;
                if (gr < M && kk < K) {
                    int ar = gA ? gA[gr] : gr;
                    v = Ab[(long long)ar*lda + kk];
                }
                As[buf^1][ka][r] = v;
            }
            #pragma unroll
            for (int i = 0; i < 4; i++) {
                int kk = k0 + kb + i*4;
                int c = col0 + cb;
                float v = 0.f;
                if (kk < K && c < N) {
                    int br = gB ? gB[kk] : kk;
                    v = Bbp[(long long)br*ldb + c];
                }
                Bs[buf^1][kb + i*4][cb] = v;
            }
        }
        #pragma unroll
        for (int kk = 0; kk < TKk; kk++) {
            float4 a0 = *(const float4*)&As[buf][kk][ty*8];
            float4 a1 = *(const float4*)&As[buf][kk][ty*8 + 4];
            float4 b0 = *(const float4*)&Bs[buf][kk][tx*4];
            float av[8] = {a0.x,a0.y,a0.z,a0.w,a1.x,a1.y,a1.z,a1.w};
            float bv[4] = {b0.x,b0.y,b0.z,b0.w};
            #pragma unroll
            for (int i = 0; i < 8; i++)
                #pragma unroll
                for (int j = 0; j < 4; j++)
                    acc[i][j] += av[i]*bv[j];
        }
        __syncthreads();
    }

    #pragma unroll
    for (int i = 0; i < 8; i++) {
        int r = row0 + ty*8 + i;
        if (r >= M) continue;
        long long crow = sCr ? (long long)sCr[r]*ldc : (long long)r*ldc;
        #pragma unroll
        for (int j = 0; j < 4; j++) {
            int c = col0 + tx*4 + j;
            if (c >= N) continue;
            float v = acc[i][j];
            if (epi == 1 || epi == 3) v += bias[c];
            if (epi == 2) v = tanhf(v);
            if (epi == 3) v = sigf(v);
            Cb[crow + c] = v;
        }
    }
}

// ---------------- 64x64 tiled SGEMM ----------------
__global__ __launch_bounds__(256) void k_gemm64(
    const float* __restrict__ A, const float* __restrict__ B,
    const float* __restrict__ bias, float* __restrict__ C,
    int M, int N, int K,
    int lda, int ldb, int ldc,
    long long sA, long long sB, long long sC,
    int epi, int mapAz, int mapBz,
    const int* __restrict__ gAidx, int gAs,
    const int* __restrict__ gBidx, int gBs,
    const int* __restrict__ sCidx, int sCs,
    const int* __restrict__ cntM, const int* __restrict__ cntK)
{
    int z = blockIdx.z;
    if (cntM) M = cntM[z];
    if (cntK) K = cntK[z];
    int row0 = blockIdx.y * 64;
    if (row0 >= M) return;
    int col0 = blockIdx.x * 64;

    int za = mapAz ? (z + z/(Tt-1) + 1) : z;
    int zb = mapBz ? (z + z/(Tt-1) + 1) : z;
    const float* Ab = A + (long long)za * sA;
    const float* Bbp = B + (long long)zb * sB;
    float* Cb = C + (long long)z * sC;
    const int* gA = gAidx ? gAidx + (long long)z * gAs : (const int*)0;
    const int* gB = gBidx ? gBidx + (long long)z * gBs : (const int*)0;
    const int* sCr = sCidx ? sCidx + (long long)z * sCs : (const int*)0;

    __shared__ __align__(16) float As[2][TKk][68];
    __shared__ __align__(16) float Bs[2][TKk][64];

    int tid = threadIdx.x;
    int ka = tid & 15, ra = tid >> 4;
    int cb = tid & 63, kb = tid >> 6;
    int tx = tid & 15, ty = tid >> 4;

    float acc[4][4] = {};
    int nk = (K + TKk - 1) / TKk;

    {
        #pragma unroll
        for (int i = 0; i < 4; i++) {
            int r = ra + i*16;
            int gr = row0 + r, kk = ka;
            float v = 0.f;
            if (gr < M && kk < K) {
                int ar = gA ? gA[gr] : gr;
                v = Ab[(long long)ar*lda + kk];
            }
            As[0][ka][r] = v;
        }
        #pragma unroll
        for (int i = 0; i < 4; i++) {
            int kk = kb + i*4;
            int c = col0 + cb;
            float v = 0.f;
            if (kk < K && c < N) {
                int br = gB ? gB[kk] : kk;
                v = Bbp[(long long)br*ldb + c];
            }
            Bs[0][kb + i*4][cb] = v;
        }
    }
    __syncthreads();

    for (int kt = 0; kt < nk; kt++) {
        int buf = kt & 1;
        if (kt + 1 < nk) {
            int k0 = (kt + 1) * TKk;
            #pragma unroll
            for (int i = 0; i < 4; i++) {
                int r = ra + i*16;
                int gr = row0 + r, kk = k0 + ka;
                float v = 0.f;
                if (gr < M && kk < K) {
                    int ar = gA ? gA[gr] : gr;
                    v = Ab[(long long)ar*lda + kk];
                }
                As[buf^1][ka][r] = v;
            }
            #pragma unroll
            for (int i = 0; i < 4; i++) {
                int kk = k0 + kb + i*4;
                int c = col0 + cb;
                float v = 0.f;
                if (kk < K && c < N) {
                    int br = gB ? gB[kk] : kk;
                    v = Bbp[(long long)br*ldb + c];
                }
                Bs[buf^1][kb + i*4][cb] = v;
            }
        }
        #pragma unroll
        for (int kk = 0; kk < TKk; kk++) {
            float4 a0 = *(const float4*)&As[buf][kk][ty*4];
            float4 b0 = *(const float4*)&Bs[buf][kk][tx*4];
            float av[4] = {a0.x,a0.y,a0.z,a0.w};
            float bv[4] = {b0.x,b0.y,b0.z,b0.w};
            #pragma unroll
            for (int i = 0; i < 4; i++)
                #pragma unroll
                for (int j = 0; j < 4; j++)
                    acc[i][j] += av[i]*bv[j];
        }
        __syncthreads();
    }

    #pragma unroll
    for (int i = 0; i < 4; i++) {
        int r = row0 + ty*4 + i;
        if (r >= M) continue;
        long long crow = sCr ? (long long)sCr[r]*ldc : (long long)r*ldc;
        #pragma unroll
        for (int j = 0; j < 4; j++) {
            int c = col0 + tx*4 + j;
            if (c >= N) continue;
            float v = acc[i][j];
            if (epi == 1 || epi == 3) v += bias[c];
            if (epi == 2) v = tanhf(v);
            if (epi == 3) v = sigf(v);
            Cb[crow + c] = v;
        }
    }
}

// ---------------- input build ----------------
__global__ void k_build_X(const int* __restrict__ code_x, const int* __restrict__ neigh,
                          const float* __restrict__ c_emb, const float* __restrict__ n_emb)
{
    int idx = blockIdx.x * blockDim.x + threadIdx.x;
    if (idx >= Nn * XCOLS) return;
    int n  = idx / XCOLS;
    int r  = idx % XCOLS;
    int bt = r / CSc;
    int c  = r % CSc;
    float cx = (float)code_x[bt*Nn + n];
    float nx = (float)neigh [bt*Nn + n];
    g_X[idx] = cx * c_emb[n*CSc + c] + nx * n_emb[n*CSc + c];
}

__global__ __launch_bounds__(288) void k_spmm(const float* __restrict__ adj)
{
    int m = blockIdx.x;
    int tid = threadIdx.x;
    __shared__ float arow[Nn];
    for (int i = tid; i < Nn; i += 288) arow[i] = adj[(long long)m*Nn + i];
    __syncthreads();
    float acc0 = 0.f, acc1 = 0.f, acc2 = 0.f, acc3 = 0.f;
    for (int n = 0; n < Nn; n++) {
        float a = arow[n];
        if (a != 0.f) {
            const float* xr = g_X + (long long)n * XCOLS;
            acc0 += a * xr[tid];
            acc1 += a * xr[tid + 288];
            acc2 += a * xr[tid + 576];
            acc3 += a * xr[tid + 864];
        }
    }
    float* sr = g_S + (long long)m * XCOLS;
    sr[tid] = acc0; sr[tid+288] = acc1; sr[tid+576] = acc2; sr[tid+864] = acc3;
}

__global__ void k_masks(const int* __restrict__ divided)
{
    int i = blockIdx.x * blockDim.x + threadIdx.x;
    if (i >= BT*Nn) return;
    g_m1 [i] = (divided[3*i]     > 0) ? 1 : 0;
    g_m23[i] = (divided[3*i + 1] > 0 || divided[3*i + 2] > 0) ? 1 : 0;
}

__global__ __launch_bounds__(1024) void k_compact()
{
    int z = blockIdx.x;
    int b = z / (Tt-1), t = 1 + z % (Tt-1);
    int bt = b*Tt + t;
    int n = threadIdx.x;
    __shared__ int warpCnt[32];
    int m = g_m23[bt*Nn + n];
    unsigned bal = __ballot_sync(0xffffffffu, m != 0);
    int lane = n & 31, w = n >> 5;
    int pre = __popc(bal & ((1u << lane) - 1u));
    if (lane == 0) warpCnt[w] = __popc(bal);
    __syncthreads();
    if (w == 0) {
        int v = warpCnt[lane];
        #pragma unroll
        for (int o = 1; o < 32; o <<= 1) {
            int u = __shfl_up_sync(0xffffffffu, v, o);
            if (lane >= o) v += u;
        }
        warpCnt[lane] = v;
    }
    __syncthreads();
    int base = (w == 0) ? 0 : warpCnt[w - 1];
    if (m) g_idx[z*Nn + base + pre] = n;
    if (n == 1023) g_cnt[z] = warpCnt[31];
}

__global__ __launch_bounds__(1024) void k_compactU()
{
    int bt = blockIdx.x;
    int n = threadIdx.x;
    __shared__ int warpCnt[32];
    int m = (g_m1[bt*Nn + n] | g_m23[bt*Nn + n]);
    unsigned bal = __ballot_sync(0xffffffffu, m != 0);
    int lane = n & 31, w = n >> 5;
    int pre = __popc(bal & ((1u << lane) - 1u));
    if (lane == 0) warpCnt[w] = __popc(bal);
    __syncthreads();
    if (w == 0) {
        int v = warpCnt[lane];
        #pragma unroll
        for (int o = 1; o < 32; o <<= 1) {
            int u = __shfl_up_sync(0xffffffffu, v, o);
            if (lane >= o) v += u;
        }
        warpCnt[lane] = v;
    }
    __syncthreads();
    int base = (w == 0) ? 0 : warpCnt[w - 1];
    if (m) g_idxU[bt*Nn + base + pre] = n;
    if (n == 1023) g_cntU[bt] = warpCnt[31];
}

__global__ __launch_bounds__(1024) void k_compact1t()
{
    int t = blockIdx.x;
    int n = threadIdx.x;
    int lane = n & 31, w = n >> 5;
    __shared__ int warpCnt[32];
    __shared__ int baseAcc;
    if (n == 0) baseAcc = 0;
    __syncthreads();
    for (int b = 0; b < Bb; b++) {
        int bt = b*Tt + t;
        int m = g_m1[bt*Nn + n];
        unsigned bal = __ballot_sync(0xffffffffu, m != 0);
        int pre = __popc(bal & ((1u << lane) - 1u));
        if (lane == 0) warpCnt[w] = __popc(bal);
        __syncthreads();
        if (w == 0) {
            int v = warpCnt[lane];
            #pragma unroll
            for (int o = 1; o < 32; o <<= 1) {
                int u = __shfl_up_sync(0xffffffffu, v, o);
                if (lane >= o) v += u;
            }
            warpCnt[lane] = v;
        }
        __syncthreads();
        int base = baseAcc + ((w == 0) ? 0 : warpCnt[w - 1]);
        if (m) g_idx1t[t*(Bb*Nn) + base + pre] = b*Nn + n;
        __syncthreads();
        if (n == 0) baseAcc += warpCnt[31];
        __syncthreads();
    }
    if (n == 0) g_c1t[t] = baseAcc;
}

__global__ void k_co_no(const int* __restrict__ code_x, const int* __restrict__ neigh,
                        const float* __restrict__ c_emb, const float* __restrict__ n_emb,
                        const float* __restrict__ Wg, const float* __restrict__ bg)
{
    int bt = blockIdx.x;
    int n  = blockIdx.y * 8 + threadIdx.y;
    int g  = threadIdx.x;
    __shared__ float Wgs[CSc][GSg];
    int tid = threadIdx.y * 32 + threadIdx.x;
    for (int i = tid; i < CSc*GSg; i += 256) Wgs[i / GSg][i % GSg] = Wg[i];
    __syncthreads();
    const float* Srow = g_S + (long long)n * XCOLS + bt * CSc;
    float a1 = 0.f, a2 = 0.f;
    #pragma unroll
    for (int c = 0; c < CSc; c++) {
        float s = Srow[c];
        float w = Wgs[c][g];
        a1 += (c_emb[n*CSc + c] + s) * w;
        a2 += (n_emb[n*CSc + c] + s) * w;
    }
    float cx = (float)code_x[bt*Nn + n];
    float nx = (float)neigh [bt*Nn + n];
    float co = cx * a1 + bg[g];
    float no = nx * a2 + bg[g];
    co = (co >= 0.f) ? co : 0.01f * co;
    no = (no >= 0.f) ? no : 0.01f * no;
    long long o = ((long long)bt*Nn + n) * GSg + g;
    g_co[o] = co;
    g_no[o] = no;
}

__global__ void k_qin(const int* __restrict__ divided, const float* __restrict__ u_emb)
{
    int idx = blockIdx.x * blockDim.x + threadIdx.x;
    if (idx >= BT*Nn*GSg) return;
    int g  = idx % GSg;
    int bn = idx / GSg;
    int n  = bn % Nn;
    int bt = bn / Nn;
    int t  = bt % Tt;
    float v;
    if (divided[bn*3 + 2] > 0)       v = u_emb[n*GSg + g];
    else if (t > 0)                  v = g_no[((long long)(bt-1)*Nn + n)*GSg + g];
    else                             v = 0.f;
    g_qin[idx] = v;
}

__global__ void k_packB(const float* __restrict__ Wk, const float* __restrict__ bk,
                        const float* __restrict__ Wv, const float* __restrict__ bv,
                        const float* __restrict__ Wih, const float* __restrict__ bih)
{
    int idx = blockIdx.x * blockDim.x + threadIdx.x;
    if (idx >= 33*KVG) return;
    int r = idx / KVG, c = idx % KVG;
    float v;
    if (r < 32) {
        if (c < OFF_V)       v = Wk [r*ATa + c];
        else if (c < OFF_GI) v = Wv [r*Hh  + (c - OFF_V)];
        else                 v = Wih[r*H3  + (c - OFF_GI)];
    } else {
        if (c < OFF_V)       v = bk [c];
        else if (c < OFF_GI) v = bv [c - OFF_V];
        else                 v = bih[c - OFF_GI];
    }
    g_packB[idx] = v;
}

// repack lstm Whh to [k][j*4+gate]
__global__ void k_packWhh(const float* __restrict__ Whh)
{
    int idx = blockIdx.x * blockDim.x + threadIdx.x;
    if (idx >= Hh*H4) return;
    int g = idx & 3;
    int rem = idx >> 2;
    int j = rem % Hh;
    int k2 = rem / Hh;
    g_W4[idx] = Whh[k2*H4 + g*Hh + j];
}

// ---------------- fused compacted score + softmax ----------------
__global__ __launch_bounds__(256) void k_score_softmax()
{
    int z = blockIdx.y;
    int cq = g_cnt[z];
    int qr0 = blockIdx.x * 64;
    if (qr0 >= cq) return;
    int b = z / (Tt-1), t = 1 + z % (Tt-1), bt = b*Tt + t;
    const int* idx = g_idx + z*Nn;
    const float* qp = g_q + (long long)z*Nn*ATa;
    const float* kb = g_kvg + (long long)bt*Nn*KVG;
    float* G = g_G + (long long)z * Nn * Nn;

    __shared__ float qs[64][33];
    __shared__ float ks[64][33];
    __shared__ float pmax[16][64];
    __shared__ float rowmax[64];

    int tid = threadIdx.x;
    int tx = tid & 15, ty = tid >> 4;

    for (int i = tid; i < 64*32; i += 256) {
        int r = i >> 5, a = i & 31;
        int gq = qr0 + r;
        qs[r][a] = (gq < cq) ? qp[(long long)gq*ATa + a] : 0.f;
    }

    float tmax[4] = {-1e30f, -1e30f, -1e30f, -1e30f};
    const float scale = 0.17677669529663687f;

    for (int j0 = 0; j0 < cq; j0 += 64) {
        __syncthreads();
        for (int i = tid; i < 64*32; i += 256) {
            int r = i >> 5, a = i & 31;
            int gk = j0 + r;
            ks[r][a] = (gk < cq) ? kb[(long long)idx[gk]*KVG + a] : 0.f;
        }
        __syncthreads();
        float acc[4][4] = {};
        #pragma unroll
        for (int a = 0; a < 32; a++) {
            float av[4], bv[4];
            #pragma unroll
            for (int i = 0; i < 4; i++) av[i] = qs[ty*4+i][a];
            #pragma unroll
            for (int j = 0; j < 4; j++) bv[j] = ks[tx*4+j][a];
            #pragma unroll
            for (int i = 0; i < 4; i++)
                #pragma unroll
                for (int j = 0; j < 4; j++) acc[i][j] += av[i]*bv[j];
        }
        #pragma unroll
        for (int i = 0; i < 4; i++) {
            int gr = qr0 + ty*4 + i;
            if (gr >= cq) continue;
            #pragma unroll
            for (int j = 0; j < 4; j++) {
                int gc = j0 + tx*4 + j;
                if (gc >= cq) continue;
                float v = acc[i][j] * scale;
                G[(long long)gr*Nn + gc] = v;
                tmax[i] = fmaxf(tmax[i], v);
            }
        }
    }
    #pragma unroll
    for (int i = 0; i < 4; i++) pmax[tx][ty*4 + i] = tmax[i];
    __syncthreads();
    if (tid < 64) {
        float m = -1e30f;
        #pragma unroll
        for (int x = 0; x < 16; x++) m = fmaxf(m, pmax[x][tid]);
        rowmax[tid] = m;
    }
    __syncthreads();

    int row = tid >> 2, l4 = tid & 3;
    int gr = qr0 + row;
    float s = 0.f;
    if (gr < cq) {
        float m = rowmax[row];
        for (int c = l4; c < cq; c += 4) {
            float e = expf(G[(long long)gr*Nn + c] - m);
            G[(long long)gr*Nn + c] = e;
            s += e;
        }
    }
    s += __shfl_xor_sync(0xffffffffu, s, 1);
    s += __shfl_xor_sync(0xffffffffu, s, 2);
    if (gr < cq) {
        float inv = 1.f / s;
        for (int c = l4; c < cq; c += 4)
            G[(long long)gr*Nn + c] *= inv;
    }
}

// ---------------- GRU combine ----------------
__global__ void k_gru_combine(int t, const float* __restrict__ gbhh)
{
    int idx = blockIdx.x * blockDim.x + threadIdx.x;
    if (idx >= Bb*Nn*Hh) return;
    int j  = idx % Hh;
    int bn = idx / Hh;
    int n  = bn % Nn;
    int b  = bn / Nn;
    int bt = b*Tt + t;
    int mi = bt*Nn + n;
    float hv = 0.f;
    if (t > 0 && g_m23[mi]) {
        hv = g_hm23[((long long)(b*(Tt-1) + (t-1))*Nn + n) * Hh + j];
    } else if (g_m1[mi]) {
        const float* gir = g_kvg + ((long long)bt*Nn + n)*KVG + OFF_GI;
        float g0, g1, g2;
        if (t == 0) { g0 = gbhh[j]; g1 = gbhh[Hh + j]; g2 = gbhh[2*Hh + j]; }
        else {
            const float* ghr = g_gh + (long long)bn * H3;
            g0 = ghr[j]; g1 = ghr[Hh + j]; g2 = ghr[2*Hh + j];
        }
        float r  = sigf(gir[j]        + g0);
        float zz = sigf(gir[Hh + j]   + g1);
        float nn = tanhf(gir[2*Hh + j] + r * g2);
        float hp = (t == 0) ? 0.f : g_h[idx];
        hv = (1.f - zz) * nn + zz * hp;
    }
    g_h[idx] = hv;
}

// parallel outlast
__global__ __launch_bounds__(288) void k_outlast1()
{
    int b = blockIdx.x, p = blockIdx.y, j = threadIdx.x;
    if (j >= Hh) return;
    float mx1 = -1e38f, mx23 = -1e38f;
    int mbase = (b*Tt + (Tt-1)) * Nn;
    int n0 = p * 64;
    for (int n = n0; n < n0 + 64; n++) {
        float hv = g_h[((long long)b*Nn + n)*Hh + j];
        if (g_m1 [mbase + n]) mx1  = fmaxf(mx1,  hv);
        if (g_m23[mbase + n]) mx23 = fmaxf(mx23, hv);
    }
    g_opart[((b*16 + p)*2    )*Hh + j] = mx1;
    g_opart[((b*16 + p)*2 + 1)*Hh + j] = mx23;
}

__global__ __launch_bounds__(288) void k_outlast2()
{
    int b = blockIdx.x, j = threadIdx.x;
    if (j >= Hh) return;
    float mx1 = -1e38f, mx23 = -1e38f;
    #pragma unroll
    for (int p = 0; p < 16; p++) {
        mx1  = fmaxf(mx1,  g_opart[((b*16 + p)*2    )*Hh + j]);
        mx23 = fmaxf(mx23, g_opart[((b*16 + p)*2 + 1)*Hh + j]);
    }
    float o = 0.f;
    if (mx1  > -1e37f) o += mx1;
    if (mx23 > -1e37f) o += mx23;
    g_stack[(long long)b*(Ee+1)*Hh + j] = o;
}

// ---------------- event LSTM ----------------
__global__ void k_evgather(const int* __restrict__ events, const float* __restrict__ Eemb)
{
    int idx = blockIdx.x * blockDim.x + threadIdx.x;
    if (idx >= Bb*Ee*Ll*EDd) return;
    int d   = idx % EDd;
    int rem = idx / EDd;
    int l   = rem % Ll;
    int be  = rem / Ll;
    int b   = be / Ee, e = be % Ee;
    int ev  = events[((b*Tt + (Tt-1))*Ee + e)*Ll + l];
    g_xe[idx] = Eemb[(long long)ev*EDd + d];
}

// column-parallel persistent LSTM: 2 rows per block, 64 blocks, 544 threads.
// Thread t<540 owns gate columns (2t, 2t+1): one coalesced LDG.64 of W per k,
// batched 10-deep for explicit MLP. Epilogue: thread (er,ej) keeps cs in reg.
#define LBATCH 10
__global__ __launch_bounds__(544) void k_lstm3()
{
    __shared__ __align__(8)  float2 h2[Hh];       // h of 2 rows, per k
    __shared__ __align__(16) float a_sh[2][H4];   // gate pre-activations
    int tid = threadIdx.x;
    int row0 = blockIdx.x * 2;

    int er = tid / Hh;            // epilogue row (valid if tid < 540)
    int ej = tid - er * Hh;
    float cs = 0.f;

    if (tid < Hh) h2[tid] = make_float2(0.f, 0.f);
    __syncthreads();

    const float2* W2 = (const float2*)g_W4 + tid;   // stride per k: H4/2 = 540

    for (int l = 0; l < Ll; l++) {
        if (tid < 2*Hh) {
            float a00 = 0.f, a01 = 0.f, a10 = 0.f, a11 = 0.f;
            #pragma unroll
            for (int k0 = 0; k0 < Hh; k0 += LBATCH) {
                float2 wv[LBATCH];
                float2 hv[LBATCH];
                #pragma unroll
                for (int u = 0; u < LBATCH; u++) wv[u] = __ldg(&W2[(k0 + u) * (H4/2)]);
                #pragma unroll
                for (int u = 0; u < LBATCH; u++) hv[u] = h2[k0 + u];
                #pragma unroll
                for (int u = 0; u < LBATCH; u++) {
                    a00 += hv[u].x * wv[u].x;
                    a01 += hv[u].x * wv[u].y;
                    a10 += hv[u].y * wv[u].x;
                    a11 += hv[u].y * wv[u].y;
                }
            }
            ((float2*)a_sh[0])[tid] = make_float2(a00, a01);
            ((float2*)a_sh[1])[tid] = make_float2(a10, a11);
        }
        __syncthreads();
        float hn = 0.f;
        if (tid < 2*Hh) {
            float4 ga = *(const float4*)&a_sh[er][ej*4];
            const float* gl = g_giL + ((long long)(row0 + er)*Ll + l) * H4;
            float gi_ = ga.x + gl[ej];
            float gf  = ga.y + gl[Hh   + ej];
            float gg  = ga.z + gl[2*Hh + ej];
            float go  = ga.w + gl[3*Hh + ej];
            cs = sigf(gf)*cs + sigf(gi_)*tanhf(gg);
            hn = sigf(go)*tanhf(cs);
        }
        __syncthreads();
        if (tid < 2*Hh) {
            float* hp = (float*)&h2[ej];
            hp[er] = hn;
        }
        __syncthreads();
    }

    if (tid < 2*Hh) {
        int be = row0 + er;
        int b = be / Ee, e = be % Ee;
        float* hp = (float*)&h2[ej];
        g_stack[((long long)b*(Ee+1) + 1 + e)*Hh + ej] = hp[er];
    }
}

// ---------------- final dp attention + head ----------------
__global__ void k_wdctx(const float* __restrict__ Wd, const float* __restrict__ bd,
                        const float* __restrict__ ctx)
{
    int j = threadIdx.x;
    if (j < Hh) {
        float s = 0.f;
        for (int d = 0; d < DAd; d++) s += Wd[j*DAd + d] * ctx[d];
        g_wdc[j] = s;
    } else if (j == Hh) {
        float s = 0.f;
        for (int d = 0; d < DAd; d++) s += bd[d] * ctx[d];
        g_wdc[Hh] = s;
    }
}

__global__ void k_dp1()
{
    int b = blockIdx.x, s = blockIdx.y;
    const float* x = g_stack + ((long long)b*(Ee+1) + s) * Hh;
    __shared__ float red[256];
    int tid = threadIdx.x;
    float acc = 0.f;
    for (int h = tid; h < Hh; h += 256) acc += x[h] * g_wdc[h];
    red[tid] = acc; __syncthreads();
    for (int st = 128; st > 0; st >>= 1) { if (tid < st) red[tid] += red[tid + st]; __syncthreads(); }
    if (tid == 0) g_vu[b*(Ee+1) + s] = red[0] + g_wdc[Hh];
}

__global__ void k_dp2()
{
    int b = blockIdx.x, j = threadIdx.x;
    __shared__ float sm[Ee+1];
    if (j == 0) {
        float mx = -1e38f;
        for (int s = 0; s < Ee+1; s++) mx = fmaxf(mx, g_vu[b*(Ee+1) + s]);
        float sum = 0.f;
        for (int s = 0; s < Ee+1; s++) { float e = expf(g_vu[b*(Ee+1) + s] - mx); sm[s] = e; sum += e; }
        float inv = 1.f / sum;
        for (int s = 0; s < Ee+1; s++) sm[s] *= inv;
    }
    __syncthreads();
    if (j < Hh) {
        float acc = 0.f;
        for (int s = 0; s < Ee+1; s++) acc += sm[s] * g_stack[((long long)b*(Ee+1) + s)*Hh + j];
        g_o1[b*Hh + j] = acc;
    }
}

// ---------------- host driver ----------------
extern "C" void kernel_launch(void* const* d_in, const int* in_sizes, int n_in,
                              void* d_out, int out_size)
{
    const int*   code_x = (const int*)  d_in[0];
    const int*   divided= (const int*)  d_in[1];
    const int*   neigh  = (const int*)  d_in[2];
    const int*   events = (const int*)  d_in[4];
    const float* c_emb  = (const float*)d_in[5];
    const float* n_emb  = (const float*)d_in[6];
    const float* u_emb  = (const float*)d_in[7];
    const float* adj    = (const float*)d_in[8];
    const float* Wg     = (const float*)d_in[9];
    const float* bg     = (const float*)d_in[10];
    const float* gWih   = (const float*)d_in[11];
    const float* gWhh   = (const float*)d_in[12];
    const float* gbih   = (const float*)d_in[13];
    const float* gbhh   = (const float*)d_in[14];
    const float* Wq     = (const float*)d_in[15];
    const float* bq     = (const float*)d_in[16];
    const float* Wk     = (const float*)d_in[17];
    const float* bk     = (const float*)d_in[18];
    const float* Wv     = (const float*)d_in[19];
    const float* bv     = (const float*)d_in[20];
    const float* Wd     = (const float*)d_in[21];
    const float* bd     = (const float*)d_in[22];
    const float* ctx    = (const float*)d_in[23];
    const float* Eemb   = (const float*)d_in[24];
    const float* lWih   = (const float*)d_in[25];
    const float* lWhh   = (const float*)d_in[26];
    const float* lb     = (const float*)d_in[27];
    const float* Wc     = (const float*)d_in[28];
    const float* bc     = (const float*)d_in[29];
    float* out = (float*)d_out;

    float *pco, *pqin, *pq, *pkvg, *ppB, *pG, *phm, *ph, *pgh, *pxe, *pgiL, *po1;
    int *pidx, *pcnt, *pidxU, *pcntU, *pidx1t, *pc1t;
    cudaGetSymbolAddress((void**)&pco,   g_co);
    cudaGetSymbolAddress((void**)&pqin,  g_qin);
    cudaGetSymbolAddress((void**)&pq,    g_q);
    cudaGetSymbolAddress((void**)&pkvg,  g_kvg);
    cudaGetSymbolAddress((void**)&ppB,   g_packB);
    cudaGetSymbolAddress((void**)&pG,    g_G);
    cudaGetSymbolAddress((void**)&phm,   g_hm23);
    cudaGetSymbolAddress((void**)&ph,    g_h);
    cudaGetSymbolAddress((void**)&pgh,   g_gh);
    cudaGetSymbolAddress((void**)&pxe,   g_xe);
    cudaGetSymbolAddress((void**)&pgiL,  g_giL);
    cudaGetSymbolAddress((void**)&po1,   g_o1);
    cudaGetSymbolAddress((void**)&pidx,  g_idx);
    cudaGetSymbolAddress((void**)&pcnt,  g_cnt);
    cudaGetSymbolAddress((void**)&pidxU, g_idxU);
    cudaGetSymbolAddress((void**)&pcntU, g_cntU);
    cudaGetSymbolAddress((void**)&pidx1t,g_idx1t);
    cudaGetSymbolAddress((void**)&pc1t,  g_c1t);

    static cudaStream_t s2 = 0;
    static cudaEvent_t evF = 0, evJ = 0;
    if (!s2) {
        cudaStreamCreateWithFlags(&s2, cudaStreamNonBlocking);
        cudaEventCreateWithFlags(&evF, cudaEventDisableTiming);
        cudaEventCreateWithFlags(&evJ, cudaEventDisableTiming);
    }

    // fork: event-LSTM chain on s2 (independent until dp1)
    cudaEventRecord(evF, 0);
    cudaStreamWaitEvent(s2, evF, 0);
    k_packWhh<<<(Hh*H4 + 255)/256, 256, 0, s2>>>(lWhh);
    k_evgather<<<(Bb*Ee*Ll*EDd + 255)/256, 256, 0, s2>>>(events, Eemb);
    k_gemm<<<dim3(17, 32, 1), 256, 0, s2>>>(pxe, lWih, lb, pgiL,
        Bb*Ee*Ll, H4, EDd, EDd, H4, H4, 0,0,0, 1, 0,0, 0,0, 0,0, 0,0, 0,0);
    k_lstm3<<<(Bb*Ee)/2, 544, 0, s2>>>();
    cudaEventRecord(evJ, s2);

    // main stream
    k_build_X<<<(Nn*XCOLS + 255)/256, 256>>>(code_x, neigh, c_emb, n_emb);
    k_masks  <<<(BT*Nn + 255)/256, 256>>>(divided);
    k_wdctx  <<<1, 288>>>(Wd, bd, ctx);
    k_compact  <<<BT2, 1024>>>();
    k_compactU <<<BT,  1024>>>();
    k_compact1t<<<Tt,  1024>>>();
    k_packB<<<(33*KVG + 255)/256, 256>>>(Wk, bk, Wv, bv, gWih, gbih);

    k_spmm<<<Nn, 288>>>(adj);
    k_co_no<<<dim3(BT, Nn/8), dim3(32,8)>>>(code_x, neigh, c_emb, n_emb, Wg, bg);
    k_qin  <<<(BT*Nn*GSg + 255)/256, 256>>>(divided, u_emb);

    // packed k|v|gi projection, only m1|m23 rows
    k_gemm<<<dim3(18, 8, BT), 256>>>(pco, ppB, ppB + 32*KVG, pkvg,
        Nn, KVG, GSg, GSg, KVG, KVG,
        (long long)Nn*GSg, 0, (long long)Nn*KVG,
        1, 0,0, pidxU, Nn, 0,0, pidxU, Nn, pcntU, 0);

    // q projection, compact m23 rows, t>=1 batches
    k_gemm64<<<dim3(1, 16, BT2), 256>>>(pqin, Wq, bq, pq,
        Nn, ATa, GSg, GSg, ATa, ATa,
        (long long)Nn*GSg, 0, (long long)Nn*ATa,
        1, 1,0, pidx, Nn, 0,0, 0,0, pcnt, 0);

    // attention: fused score+softmax, then tanh(P @ V) scattered
    k_score_softmax<<<dim3(16, BT2), 256>>>();
    k_gemm<<<dim3(5, 8, BT2), 256>>>(pG, pkvg + OFF_V, 0, phm,
        Nn, Hh, Nn, Nn, KVG, Hh,
        (long long)Nn*Nn, (long long)Nn*KVG, (long long)Nn*Hh,
        2, 0,1, 0,0, pidx, Nn, pidx, Nn, pcnt, pcnt);

    // GRU: t=0 bias-only; t>=1 gh GEMM compacted to m1 rows
    k_gru_combine<<<(Bb*Nn*Hh + 255)/256, 256>>>(0, gbhh);
    for (int t = 1; t < Tt; t++) {
        k_gemm64<<<dim3(13, 64, 1), 256>>>(ph, gWhh, gbhh, pgh,
            Bb*Nn, H3, Hh, Hh, H3, H3, 0,0,0,
            1, 0,0, pidx1t + t*(Bb*Nn), 0, 0,0, pidx1t + t*(Bb*Nn), 0, pc1t + t, 0);
        k_gru_combine<<<(Bb*Nn*Hh + 255)/256, 256>>>(t, gbhh);
    }
    k_outlast1<<<dim3(Bb, 16), 288>>>();
    k_outlast2<<<Bb, 288>>>();

    // join LSTM chain, then dp attention + classifier
    cudaStreamWaitEvent(0, evJ, 0);
    k_dp1<<<dim3(Bb, Ee+1), 256>>>();
    k_dp2<<<Bb, 288>>>();
    k_gemm64<<<dim3(63, 1, 1), 256>>>(po1, Wc, bc, out,
        Bb, OUTo, Hh, Hh, OUTo, OUTo, 0,0,0, 3, 0,0, 0,0, 0,0, 0,0, 0,0);
}